// round 3
// baseline (speedup 1.0000x reference)
#include <cuda_runtime.h>
#include <cuda_bf16.h>
#include <math.h>

#define BB 16
#define SD 512
#define DD 512
#define MT (BB*SD)      // 8192
#define NLAY 3
#define NDOM 8

// ---------------- scratch (device globals; no allocation) ----------------
__device__ float g_X[MT*DD];
__device__ float g_relX[MT*DD];
__device__ float g_fo[MT*DD];
__device__ float g_bo[MT*DD];
__device__ float g_Pf[MT*DD];
__device__ float g_Pb[MT*DD];
__device__ float g_delta[MT*DD];
__device__ float g_AxpX[MT*DD];
__device__ float g_FR[MT*DD];
__device__ float g_BR[MT*DD];
__device__ float g_outs[MT*NLAY*DD];
__device__ float g_pooled[BB*NDOM*DD];
__device__ float g_domout[BB*NDOM*DD];
__device__ float g_denom[MT];
__device__ float g_fadj[MT];
__device__ float g_badj[MT];
__device__ unsigned char g_dom8[MT*NDOM];
__device__ int g_domfmt;   // 0=uint8, 1=int32, 2=float32

__device__ __forceinline__ float sigf(float x) { return 1.f / (1.f + expf(-x)); }

// ---------------- domain dtype detection + normalization ----------------
// The `domain` input is a jax bool array; the harness ABI for bool is not
// documented. Detect encoding from content (deterministic for fixed inputs):
//   float32: words in {0x00000000, 0x3F800000}
//   int32:   words in {0, 1}
//   uint8:   packed 0/1 bytes -> many words with value > 1
__global__ void detect_dom_fmt(const unsigned int* __restrict__ w) {
    __shared__ int sf, sb;
    if (threadIdx.x == 0) { sf = 0; sb = 0; }
    __syncthreads();
    for (int i = threadIdx.x; i < 1024; i += 256) {
        unsigned int v = w[i];
        if (v == 0x3F800000u) atomicOr(&sf, 1);
        else if (v > 1u) atomicOr(&sb, 1);
    }
    __syncthreads();
    if (threadIdx.x == 0) g_domfmt = sf ? 2 : (sb ? 0 : 1);
}

__global__ void convert_dom(const void* __restrict__ dom, unsigned char* __restrict__ out) {
    int i = blockIdx.x * 256 + threadIdx.x;
    if (i >= MT * NDOM) return;
    int fmt = g_domfmt;
    unsigned char v;
    if (fmt == 0)      v = ((const unsigned char*)dom)[i] != 0;
    else if (fmt == 1) v = ((const int*)dom)[i] != 0;
    else               v = ((const float*)dom)[i] != 0.f;
    out[i] = v;
}

// ---------------- row stats: denom, frontadj, backadj ----------------
__global__ void rowstats_kernel(const float* __restrict__ adj,
                                const float* __restrict__ depmap,
                                float* __restrict__ denom,
                                float* __restrict__ fadj,
                                float* __restrict__ badj) {
    int warp = (blockIdx.x * blockDim.x + threadIdx.x) >> 5;
    int lane = threadIdx.x & 31;
    if (warp >= MT) return;
    int b = warp >> 9;
    int s = warp & 511;
    const float* arow = adj + (size_t)(b * SD + s) * SD;
    const float* drow = depmap + (size_t)(b * SD + s) * SD;
    const float* acol = adj + (size_t)b * SD * SD + s;
    float sa = 0.f, sf = 0.f, sb = 0.f;
    for (int j = lane; j < SD; j += 32) {
        float a = arow[j];
        float dp = drow[j];
        sa += a;
        sf += a * dp;
        sb += acol[(size_t)j * SD] * dp;
    }
#pragma unroll
    for (int off = 16; off > 0; off >>= 1) {
        sa += __shfl_down_sync(0xffffffffu, sa, off);
        sf += __shfl_down_sync(0xffffffffu, sf, off);
        sb += __shfl_down_sync(0xffffffffu, sb, off);
    }
    if (lane == 0) {
        denom[warp] = sa + 1.f;
        fadj[warp] = sf;
        badj[warp] = sb;
    }
}

// ---------------- copy (X init) ----------------
__global__ void copy_kernel(const float* __restrict__ src, float* __restrict__ dst, int n4) {
    int i = blockIdx.x * blockDim.x + threadIdx.x;
    if (i < n4) ((float4*)dst)[i] = ((const float4*)src)[i];
}

// ---------------- domain pooling: pooled[b,k,d] = max_s (dom? -1e4 : X) ----------------
__global__ void pool_kernel(const float* __restrict__ X,
                            const unsigned char* __restrict__ dom,
                            float* __restrict__ pooled) {
    int b = blockIdx.x;
    int d = blockIdx.y * 128 + threadIdx.x;
    float mv[NDOM];
#pragma unroll
    for (int k = 0; k < NDOM; k++) mv[k] = -3.402823466e38f;
    const float* Xb = X + (size_t)b * SD * DD;
    const unsigned long long* db = (const unsigned long long*)(dom + (size_t)b * SD * NDOM);
    for (int s = 0; s < SD; s++) {
        float x = Xb[(size_t)s * DD + d];
        unsigned long long m = db[s];
#pragma unroll
        for (int k = 0; k < NDOM; k++) {
            float v = ((m >> (8 * k)) & 0xffull) ? -10000.f : x;
            mv[k] = fmaxf(mv[k], v);
        }
    }
#pragma unroll
    for (int k = 0; k < NDOM; k++) pooled[((size_t)b * NDOM + k) * DD + d] = mv[k];
}

// ---------------- domain gate: sigmoid(pooled @ W_dg + b_dg) ----------------
__global__ void dgate_kernel(const float* __restrict__ pooled,
                             const float* __restrict__ Wdg,
                             const float* __restrict__ bdg,
                             float* __restrict__ out) {
    int bk = blockIdx.x;   // 0..127 (b*8+k)
    int d = blockIdx.y * 128 + threadIdx.x;
    __shared__ float sp[DD];
    for (int e = threadIdx.x; e < DD; e += 128) sp[e] = pooled[(size_t)bk * DD + e];
    __syncthreads();
    float acc = bdg[d];
#pragma unroll 8
    for (int e = 0; e < DD; e++) acc += sp[e] * Wdg[(size_t)e * DD + d];
    out[(size_t)bk * DD + d] = sigf(acc);
}

// ---------------- build front/back outputs ----------------
__global__ void buildfb_kernel(const float* __restrict__ X,
                               const float* __restrict__ relX,
                               const float* __restrict__ did,
                               const float* __restrict__ rid,
                               const float* __restrict__ domout,
                               float* __restrict__ fo,
                               float* __restrict__ bo) {
    int bs = blockIdx.x;          // 0..8191
    int b = bs >> 9;
    int d = threadIdx.x;          // 0..511
    __shared__ float sdi[NDOM], sri[NDOM];
    if (threadIdx.x < NDOM) sdi[threadIdx.x] = did[(size_t)bs * NDOM + threadIdx.x];
    else if (threadIdx.x < 2 * NDOM) sri[threadIdx.x - NDOM] = rid[(size_t)bs * NDOM + threadIdx.x - NDOM];
    __syncthreads();
    float dsum = 0.f, rsum = 0.f;
#pragma unroll
    for (int k = 0; k < NDOM; k++) { dsum += sdi[k]; rsum += sri[k]; }
    bool dmask = (dsum == 1.0f);
    bool rmask = (rsum == 1.0f);
    size_t idx = (size_t)bs * DD + d;
    float f = dmask ? 0.f : X[idx];
    float bv = rmask ? 0.f : relX[idx];
    const float* dob = domout + (size_t)b * NDOM * DD;
#pragma unroll
    for (int k = 0; k < NDOM; k++) {
        float dv = dob[(size_t)k * DD + d];
        f += sdi[k] * dv;
        bv += sri[k] * dv;
    }
    fo[idx] = f;
    bo[idx] = bv;
}

// ---------------- batched GEMM (per-batch 512x512x512), 64x64 tile ----------------
// C[b,i,d] = sum_j Aeff[b,i,j] * (B[b,j,d] * (BMUL? Bmul[b,j,d]:1))  (+ ADDC? Cadd : 0)
// TRANSA: Aeff[i,j] = A[j,i]
template<bool TRANSA, bool BMUL, bool ADDC>
__global__ void bgemm64(const float* __restrict__ A, const float* __restrict__ Bm,
                        const float* __restrict__ Bmul, const float* __restrict__ Cadd,
                        float* __restrict__ C) {
    __shared__ float As[16][68];
    __shared__ float Bs[16][68];
    int b = blockIdx.z;
    size_t base = (size_t)b * SD * DD;
    const float* Ab = A + base;
    const float* Bb = Bm + base;
    int i0 = blockIdx.y * 64, j0 = blockIdx.x * 64;
    int t = threadIdx.x;
    int tx = t & 15, ty = t >> 4;
    float acc[4][4];
#pragma unroll
    for (int r = 0; r < 4; r++)
#pragma unroll
        for (int c = 0; c < 4; c++) acc[r][c] = 0.f;

    for (int k0 = 0; k0 < SD; k0 += 16) {
        if (TRANSA) {
            int kr = t >> 4, ic = (t & 15) << 2;
            float4 av = *(const float4*)(Ab + (size_t)(k0 + kr) * SD + i0 + ic);
            *(float4*)&As[kr][ic] = av;
        } else {
            int lr = t >> 2, lc = (t & 3) << 2;
            float4 av = *(const float4*)(Ab + (size_t)(i0 + lr) * SD + k0 + lc);
            As[lc + 0][lr] = av.x; As[lc + 1][lr] = av.y;
            As[lc + 2][lr] = av.z; As[lc + 3][lr] = av.w;
        }
        {
            int kr = t >> 4, jc = (t & 15) << 2;
            float4 bv = *(const float4*)(Bb + (size_t)(k0 + kr) * DD + j0 + jc);
            if (BMUL) {
                float4 mv = *(const float4*)(Bmul + base + (size_t)(k0 + kr) * DD + j0 + jc);
                bv.x *= mv.x; bv.y *= mv.y; bv.z *= mv.z; bv.w *= mv.w;
            }
            *(float4*)&Bs[kr][jc] = bv;
        }
        __syncthreads();
#pragma unroll
        for (int kk = 0; kk < 16; kk++) {
            float4 a = *(const float4*)&As[kk][ty << 2];
            float4 bq = *(const float4*)&Bs[kk][tx << 2];
            float ar[4] = {a.x, a.y, a.z, a.w};
            float br[4] = {bq.x, bq.y, bq.z, bq.w};
#pragma unroll
            for (int r = 0; r < 4; r++)
#pragma unroll
                for (int c = 0; c < 4; c++) acc[r][c] = fmaf(ar[r], br[c], acc[r][c]);
        }
        __syncthreads();
    }
#pragma unroll
    for (int r = 0; r < 4; r++) {
        int row = i0 + (ty << 2) + r;
        size_t idx = base + (size_t)row * DD + j0 + (tx << 2);
        float4 v = make_float4(acc[r][0], acc[r][1], acc[r][2], acc[r][3]);
        if (ADDC) {
            float4 xa = *(const float4*)(Cadd + idx);
            v.x += xa.x; v.y += xa.y; v.z += xa.z; v.w += xa.w;
        }
        *(float4*)(C + idx) = v;
    }
}

// ---------------- weight GEMM [8192,K] x [K,512], 64x64 tile + fused epilogues ----
// EPI 0: C = acc + bias[n]                                    (FR/BR precompute)
// EPI 1: C = rowv[m] * sigmoid(acc + add1) * mulel             (gate products Pf/Pb)
// EPI 2: t=(acc + 2*bias[n] + add1 + add2)/rowv[m]; PReLU; -> C (=X) and C2 (=outs slot)
// EPI 3: C = acc + bias[n] + add1                              (final projection)
template<int EPI>
__global__ void wgemm64(const float* __restrict__ A, const float* __restrict__ W, int K,
                        float* __restrict__ C, const float* __restrict__ bias,
                        const float* __restrict__ add1, const float* __restrict__ add2,
                        const float* __restrict__ rowv, const float* __restrict__ mulel,
                        const float* __restrict__ pa, int l, float* __restrict__ C2) {
    __shared__ float As[16][68];
    __shared__ float Ws[16][68];
    int i0 = blockIdx.y * 64, j0 = blockIdx.x * 64;
    int t = threadIdx.x;
    int tx = t & 15, ty = t >> 4;
    float acc[4][4];
#pragma unroll
    for (int r = 0; r < 4; r++)
#pragma unroll
        for (int c = 0; c < 4; c++) acc[r][c] = 0.f;

    for (int k0 = 0; k0 < K; k0 += 16) {
        {
            int lr = t >> 2, lc = (t & 3) << 2;
            float4 av = *(const float4*)(A + (size_t)(i0 + lr) * K + k0 + lc);
            As[lc + 0][lr] = av.x; As[lc + 1][lr] = av.y;
            As[lc + 2][lr] = av.z; As[lc + 3][lr] = av.w;
        }
        {
            int kr = t >> 4, jc = (t & 15) << 2;
            float4 wv = *(const float4*)(W + (size_t)(k0 + kr) * DD + j0 + jc);
            *(float4*)&Ws[kr][jc] = wv;
        }
        __syncthreads();
#pragma unroll
        for (int kk = 0; kk < 16; kk++) {
            float4 a = *(const float4*)&As[kk][ty << 2];
            float4 w = *(const float4*)&Ws[kk][tx << 2];
            float ar[4] = {a.x, a.y, a.z, a.w};
            float wr[4] = {w.x, w.y, w.z, w.w};
#pragma unroll
            for (int r = 0; r < 4; r++)
#pragma unroll
                for (int c = 0; c < 4; c++) acc[r][c] = fmaf(ar[r], wr[c], acc[r][c]);
        }
        __syncthreads();
    }

    int n = j0 + (tx << 2);
#pragma unroll
    for (int r = 0; r < 4; r++) {
        int m = i0 + (ty << 2) + r;
        size_t idx = (size_t)m * DD + n;
        float v[4] = {acc[r][0], acc[r][1], acc[r][2], acc[r][3]};
        if (EPI == 0) {
#pragma unroll
            for (int c = 0; c < 4; c++) v[c] += bias[n + c];
        } else if (EPI == 1) {
            float rv = rowv[m];
            float4 a1 = *(const float4*)(add1 + idx);
            float4 me = *(const float4*)(mulel + idx);
            float a1a[4] = {a1.x, a1.y, a1.z, a1.w};
            float mea[4] = {me.x, me.y, me.z, me.w};
#pragma unroll
            for (int c = 0; c < 4; c++) v[c] = rv * sigf(v[c] + a1a[c]) * mea[c];
        } else if (EPI == 2) {
            float invd = 1.f / rowv[m];
            float al = pa[l];
            float4 a1 = *(const float4*)(add1 + idx);
            float4 a2 = *(const float4*)(add2 + idx);
            float a1a[4] = {a1.x, a1.y, a1.z, a1.w};
            float a2a[4] = {a2.x, a2.y, a2.z, a2.w};
#pragma unroll
            for (int c = 0; c < 4; c++) {
                float tt = (v[c] + 2.f * bias[n + c] + a1a[c] + a2a[c]) * invd;
                v[c] = tt >= 0.f ? tt : al * tt;
            }
            *(float4*)(C2 + (size_t)m * (NLAY * DD) + n) = make_float4(v[0], v[1], v[2], v[3]);
        } else if (EPI == 3) {
            float4 a1 = *(const float4*)(add1 + idx);
            float a1a[4] = {a1.x, a1.y, a1.z, a1.w};
#pragma unroll
            for (int c = 0; c < 4; c++) v[c] += bias[n + c] + a1a[c];
        }
        *(float4*)(C + idx) = make_float4(v[0], v[1], v[2], v[3]);
    }
}

// ---------------- host launcher ----------------
extern "C" void kernel_launch(void* const* d_in, const int* in_sizes, int n_in,
                              void* d_out, int out_size) {
    const float* adj       = (const float*)d_in[0];
    const void*  domain    = d_in[1];
    const float* domain_id = (const float*)d_in[2];
    const float* redom_id  = (const float*)d_in[3];
    const float* frontrel  = (const float*)d_in[4];
    const float* backrel   = (const float*)d_in[5];
    const float* depmap    = (const float*)d_in[6];
    const float* rel       = (const float*)d_in[7];
    const float* gcn       = (const float*)d_in[8];
    // d_in[9] = mask (unused)
    const float* W_layers  = (const float*)d_in[10];
    const float* b_layers  = (const float*)d_in[11];
    const float* prelu_a   = (const float*)d_in[12];
    const float* W_dg      = (const float*)d_in[13];
    const float* b_dg      = (const float*)d_in[14];
    const float* W_mg      = (const float*)d_in[15];
    const float* b_mg      = (const float*)d_in[16];
    const float* W_out     = (const float*)d_in[17];
    const float* b_out     = (const float*)d_in[18];

    float *X, *relX, *fo, *bo, *Pf, *Pb, *delta, *AxpX, *FR, *BR, *outs,
          *pooled, *domout, *denom, *fadj, *badj;
    unsigned char *dom8;
    cudaGetSymbolAddress((void**)&X, g_X);
    cudaGetSymbolAddress((void**)&relX, g_relX);
    cudaGetSymbolAddress((void**)&fo, g_fo);
    cudaGetSymbolAddress((void**)&bo, g_bo);
    cudaGetSymbolAddress((void**)&Pf, g_Pf);
    cudaGetSymbolAddress((void**)&Pb, g_Pb);
    cudaGetSymbolAddress((void**)&delta, g_delta);
    cudaGetSymbolAddress((void**)&AxpX, g_AxpX);
    cudaGetSymbolAddress((void**)&FR, g_FR);
    cudaGetSymbolAddress((void**)&BR, g_BR);
    cudaGetSymbolAddress((void**)&outs, g_outs);
    cudaGetSymbolAddress((void**)&pooled, g_pooled);
    cudaGetSymbolAddress((void**)&domout, g_domout);
    cudaGetSymbolAddress((void**)&denom, g_denom);
    cudaGetSymbolAddress((void**)&fadj, g_fadj);
    cudaGetSymbolAddress((void**)&badj, g_badj);
    cudaGetSymbolAddress((void**)&dom8, g_dom8);

    dim3 bgrid(8, 8, 16);     // batched 512x512 GEMMs
    dim3 wgrid(8, 128);       // [8192 x 512] weight GEMMs

    // normalize domain (bool) encoding to packed uint8
    detect_dom_fmt<<<1, 256>>>((const unsigned int*)domain);
    convert_dom<<<(MT * NDOM + 255) / 256, 256>>>(domain, dom8);

    // layer-invariant precomputes
    rowstats_kernel<<<1024, 256>>>(adj, depmap, denom, fadj, badj);
    copy_kernel<<<(MT * DD / 4 + 255) / 256, 256>>>(gcn, X, MT * DD / 4);
    // FR = frontrel @ W_mg[D:2D] + b_mg ; BR = backrel @ W_mg[D:2D] + b_mg
    wgemm64<0><<<wgrid, 256>>>(frontrel, W_mg + (size_t)DD * DD, DD, FR, b_mg,
                               nullptr, nullptr, nullptr, nullptr, nullptr, 0, nullptr);
    wgemm64<0><<<wgrid, 256>>>(backrel, W_mg + (size_t)DD * DD, DD, BR, b_mg,
                               nullptr, nullptr, nullptr, nullptr, nullptr, 0, nullptr);

    for (int l = 0; l < NLAY; l++) {
        pool_kernel<<<dim3(BB, DD / 128), 128>>>(X, dom8, pooled);
        dgate_kernel<<<dim3(BB * NDOM, DD / 128), 128>>>(pooled, W_dg, b_dg, domout);
        // relX = rel @ X
        bgemm64<false, false, false><<<bgrid, 256>>>(rel, X, nullptr, nullptr, relX);
        buildfb_kernel<<<MT, 512>>>(X, relX, domain_id, redom_id, domout, fo, bo);
        // Pf = frontadj * sigmoid(fo @ W_mg[:D] + FR) * fo ; Pb analogous
        wgemm64<1><<<wgrid, 256>>>(fo, W_mg, DD, Pf, nullptr, FR, nullptr, fadj, fo,
                                   nullptr, 0, nullptr);
        wgemm64<1><<<wgrid, 256>>>(bo, W_mg, DD, Pb, nullptr, BR, nullptr, badj, bo,
                                   nullptr, 0, nullptr);
        // delta = rel^T @ Pf
        bgemm64<true, false, false><<<bgrid, 256>>>(rel, Pf, nullptr, nullptr, delta);
        // AxpX = adj @ (X * rel) + X
        bgemm64<false, true, true><<<bgrid, 256>>>(adj, X, rel, X, AxpX);
        // X = PReLU((AxpX @ W_l + 2*b_l + delta + Pb)/denom); also store into outs[:, l*D:]
        wgemm64<2><<<wgrid, 256>>>(AxpX, W_layers + (size_t)l * DD * DD, DD, X,
                                   b_layers + (size_t)l * DD, delta, Pb, denom,
                                   nullptr, prelu_a, l, outs + (size_t)l * DD);
    }
    // final: out = outs @ W_out + b_out + gcn_inputs
    wgemm64<3><<<wgrid, 256>>>(outs, W_out, NLAY * DD, (float*)d_out, b_out, gcn,
                               nullptr, nullptr, nullptr, nullptr, 0, nullptr);
}

// round 5
// speedup vs baseline: 1.7238x; 1.7238x over previous
#include <cuda_runtime.h>
#include <cuda_bf16.h>
#include <math.h>
#include <stdint.h>

#define BB 16
#define SD 512
#define DD 512
#define MT (BB*SD)      // 8192
#define NLAY 3
#define NDOM 8

// ---------------- scratch (device globals; no allocation) ----------------
__device__ float g_X[MT*DD];
__device__ float g_relX[MT*DD];
__device__ float g_fo[MT*DD];
__device__ float g_bo[MT*DD];
__device__ float g_Pf[MT*DD];
__device__ float g_Pb[MT*DD];
__device__ float g_delta[MT*DD];
__device__ float g_AxpX[MT*DD];
__device__ float g_FR[MT*DD];
__device__ float g_BR[MT*DD];
__device__ float g_relT[MT*DD];
__device__ float g_outs[MT*NLAY*DD];
__device__ float g_pooled[BB*NDOM*DD];
__device__ float g_domout[BB*NDOM*DD];
__device__ float g_denom[MT];
__device__ float g_fadj[MT];
__device__ float g_badj[MT];
__device__ unsigned char g_dom8[MT*NDOM];
__device__ int g_domfmt;

__device__ __forceinline__ float sigf(float x) { return 1.f / (1.f + expf(-x)); }

// fp32 -> (bf16 hi, bf16 lo) split, packed pairwise (x low half, y high half)
__device__ __forceinline__ void split2(float x, float y, uint32_t& h, uint32_t& lo) {
    __nv_bfloat16 hx = __float2bfloat16(x), hy = __float2bfloat16(y);
    float rx = x - __bfloat162float(hx), ry = y - __bfloat162float(hy);
    __nv_bfloat16 lx = __float2bfloat16(rx), ly = __float2bfloat16(ry);
    h  = ((uint32_t)__bfloat16_as_ushort(hy) << 16) | (uint32_t)__bfloat16_as_ushort(hx);
    lo = ((uint32_t)__bfloat16_as_ushort(ly) << 16) | (uint32_t)__bfloat16_as_ushort(lx);
}

__device__ __forceinline__ uint32_t smem_u32(const void* p) {
    uint32_t a;
    asm("{ .reg .u64 t; cvta.to.shared.u64 t, %1; cvt.u32.u64 %0, t; }" : "=r"(a) : "l"(p));
    return a;
}

#define LDSM4(r0, r1, r2, r3, a) \
    asm volatile("ldmatrix.sync.aligned.m8n8.x4.shared.b16 {%0,%1,%2,%3}, [%4];" \
        : "=r"(r0), "=r"(r1), "=r"(r2), "=r"(r3) : "r"(a))
#define LDSM4T(r0, r1, r2, r3, a) \
    asm volatile("ldmatrix.sync.aligned.m8n8.x4.trans.shared.b16 {%0,%1,%2,%3}, [%4];" \
        : "=r"(r0), "=r"(r1), "=r"(r2), "=r"(r3) : "r"(a))
#define MMA(acc, a, b) \
    asm volatile("mma.sync.aligned.m16n8k16.row.col.f32.bf16.bf16.f32 " \
        "{%0,%1,%2,%3}, {%4,%5,%6,%7}, {%8,%9}, {%0,%1,%2,%3};" \
        : "+f"((acc)[0]), "+f"((acc)[1]), "+f"((acc)[2]), "+f"((acc)[3]) \
        : "r"((a)[0]), "r"((a)[1]), "r"((a)[2]), "r"((a)[3]), "r"((b)[0]), "r"((b)[1]))

// ================= HMMA bf16x3 GEMM =================
// C[128m x 128n tile] = A[MT x K] @ B[K x 512] with split-precision bf16 accumulation.
// BATCH: per-batch [512x512] blocks (A and B offset by batch*512*512, batch = m0>>9)
// BMUL: B multiplied elementwise by Bmul
// EPI: 0:+bias | 1: rowv*sig(acc+add1)*mulel | 2: prelu((acc+2b+add1+add2)/rowv)->C,C2
//      3:+bias+add1 | 4:none | 5:+Cadd
#define APITCH 80
#define BPITCH 272
#define A_ST (128*APITCH)           // 10240 per hi/lo
#define B_ST (32*BPITCH)            // 8704 per hi/lo
#define STG_SZ (2*A_ST + 2*B_ST)    // 37888
#define SMEM_TC (2*STG_SZ)          // 75776

template<int EPI, bool BATCH, bool BMUL>
__global__ void __launch_bounds__(256, 1) hgemm(
    const float* __restrict__ A, const float* __restrict__ B,
    const float* __restrict__ Bmul, float* __restrict__ C,
    const float* __restrict__ Cadd, const float* __restrict__ bias,
    const float* __restrict__ add1, const float* __restrict__ add2,
    const float* __restrict__ rowv, const float* __restrict__ mulel,
    const float* __restrict__ pa, int l, float* __restrict__ C2, int K)
{
    extern __shared__ __align__(128) char smp[];
    const uint32_t sb = smem_u32(smp);
    const int t = threadIdx.x;
    const int wid = t >> 5;
    const int lane = t & 31;
    const int m0 = blockIdx.y * 128;
    const int n0 = blockIdx.x * 128;
    const int KB = K >> 5;
    const int wm = (wid & 1) * 64;
    const int wn = (wid >> 1) * 32;

    const size_t batch_off = BATCH ? ((size_t)(m0 >> 9)) * 262144 : 0;

    // staging thread mapping
    const int a_tx = t & 7;           // k group: k = a_tx*4
    const int a_tm = t >> 3;          // m stride 32
    const int b_tn = t & 31;          // n group: n = b_tn*4
    const int b_tk = t >> 5;          // k stride 8

    float acc[4][4][4];
#pragma unroll
    for (int im = 0; im < 4; im++)
#pragma unroll
        for (int in = 0; in < 4; in++)
#pragma unroll
            for (int c = 0; c < 4; c++) acc[im][in][c] = 0.f;

    // ldmatrix lane addressing
    const int q = lane >> 3, r = lane & 7;
    const int arow = (q & 1) * 8 + r;        // + im*16 + wm
    const int acol = (q >> 1) * 8;           // + k16
    const int bkrow = (q & 1) * 8 + r;       // + k16
    const int bcol = wn + (q >> 1) * 8;      // + jn2*16

    // global load helper (into registers)
    float4 rA[4], rB[4], rBm[4];
    auto ldg = [&](int kb) {
        const int k0 = kb * 32;
#pragma unroll
        for (int i = 0; i < 4; i++) {
            int m = a_tm + i * 32;
            int mg = m0 + m;
            const float* p = BATCH
                ? A + batch_off + (size_t)(mg & 511) * 512 + k0 + a_tx * 4
                : A + (size_t)mg * K + k0 + a_tx * 4;
            rA[i] = *(const float4*)p;
        }
#pragma unroll
        for (int i = 0; i < 4; i++) {
            int k = b_tk + i * 8;
            const float* p = B + batch_off + (size_t)(k0 + k) * 512 + n0 + b_tn * 4;
            rB[i] = *(const float4*)p;
            if (BMUL) {
                const float* pq = Bmul + batch_off + (size_t)(k0 + k) * 512 + n0 + b_tn * 4;
                rBm[i] = *(const float4*)pq;
            }
        }
    };
    auto sts = [&](int s) {
        char* aH = smp + s * STG_SZ;
        char* aL = aH + A_ST;
        char* bH = aH + 2 * A_ST;
        char* bL = bH + B_ST;
#pragma unroll
        for (int i = 0; i < 4; i++) {
            int m = a_tm + i * 32;
            uint32_t h0, l0, h1, l1;
            split2(rA[i].x, rA[i].y, h0, l0);
            split2(rA[i].z, rA[i].w, h1, l1);
            *(uint2*)(aH + m * APITCH + a_tx * 8) = make_uint2(h0, h1);
            *(uint2*)(aL + m * APITCH + a_tx * 8) = make_uint2(l0, l1);
        }
#pragma unroll
        for (int i = 0; i < 4; i++) {
            int k = b_tk + i * 8;
            float4 v = rB[i];
            if (BMUL) {
                v.x *= rBm[i].x; v.y *= rBm[i].y; v.z *= rBm[i].z; v.w *= rBm[i].w;
            }
            uint32_t h0, l0, h1, l1;
            split2(v.x, v.y, h0, l0);
            split2(v.z, v.w, h1, l1);
            *(uint2*)(bH + k * BPITCH + b_tn * 8) = make_uint2(h0, h1);
            *(uint2*)(bL + k * BPITCH + b_tn * 8) = make_uint2(l0, l1);
        }
    };

    // prologue
    ldg(0);
    sts(0);
    __syncthreads();

    for (int kb = 0; kb < KB; kb++) {
        const int s = kb & 1;
        if (kb + 1 < KB) ldg(kb + 1);

        const uint32_t aH = sb + s * STG_SZ;
        const uint32_t aL = aH + A_ST;
        const uint32_t bH = aH + 2 * A_ST;
        const uint32_t bL = bH + B_ST;
#pragma unroll
        for (int ks = 0; ks < 2; ks++) {
            const int k16 = ks * 16;
            uint32_t ah[4][4], al[4][4], bh[4][2], bl[4][2];
#pragma unroll
            for (int im = 0; im < 4; im++) {
                uint32_t off = (uint32_t)(wm + im * 16 + arow) * APITCH + (k16 + acol) * 2;
                LDSM4(ah[im][0], ah[im][1], ah[im][2], ah[im][3], aH + off);
                LDSM4(al[im][0], al[im][1], al[im][2], al[im][3], aL + off);
            }
#pragma unroll
            for (int j2 = 0; j2 < 2; j2++) {
                uint32_t off = (uint32_t)(k16 + bkrow) * BPITCH + (bcol + j2 * 16) * 2;
                LDSM4T(bh[j2 * 2][0], bh[j2 * 2][1], bh[j2 * 2 + 1][0], bh[j2 * 2 + 1][1], bH + off);
                LDSM4T(bl[j2 * 2][0], bl[j2 * 2][1], bl[j2 * 2 + 1][0], bl[j2 * 2 + 1][1], bL + off);
            }
#pragma unroll
            for (int im = 0; im < 4; im++)
#pragma unroll
                for (int in = 0; in < 4; in++) {
                    MMA(acc[im][in], ah[im], bh[in]);
                    MMA(acc[im][in], ah[im], bl[in]);
                    MMA(acc[im][in], al[im], bh[in]);
                }
        }
        if (kb + 1 < KB) sts((kb + 1) & 1);
        __syncthreads();
    }

    // ---------------- epilogue ----------------
    const int lr = lane >> 2;          // 0..7
    const int lc = (lane & 3) * 2;     // 0,2,4,6
    float al_p = 0.f;
    if (EPI == 2) al_p = pa[l];

#pragma unroll
    for (int im = 0; im < 4; im++) {
        const int gm0 = m0 + wm + im * 16 + lr;
        const int gm1 = gm0 + 8;
        float rv0 = 1.f, rv1 = 1.f;
        if (EPI == 1) { rv0 = rowv[gm0]; rv1 = rowv[gm1]; }
        if (EPI == 2) { rv0 = 1.f / rowv[gm0]; rv1 = 1.f / rowv[gm1]; }
#pragma unroll
        for (int in = 0; in < 4; in++) {
            const int gc = n0 + wn + in * 8 + lc;
            float v[4] = {acc[im][in][0], acc[im][in][1], acc[im][in][2], acc[im][in][3]};
            const size_t i0 = (size_t)gm0 * 512 + gc;
            const size_t i1 = (size_t)gm1 * 512 + gc;
            if (EPI == 0) {
                v[0] += bias[gc]; v[1] += bias[gc + 1];
                v[2] += bias[gc]; v[3] += bias[gc + 1];
            } else if (EPI == 1) {
                float2 a0 = *(const float2*)(add1 + i0);
                float2 a1 = *(const float2*)(add1 + i1);
                float2 e0 = *(const float2*)(mulel + i0);
                float2 e1 = *(const float2*)(mulel + i1);
                v[0] = rv0 * sigf(v[0] + a0.x) * e0.x;
                v[1] = rv0 * sigf(v[1] + a0.y) * e0.y;
                v[2] = rv1 * sigf(v[2] + a1.x) * e1.x;
                v[3] = rv1 * sigf(v[3] + a1.y) * e1.y;
            } else if (EPI == 2) {
                float b0 = 2.f * bias[gc], b1 = 2.f * bias[gc + 1];
                float2 a0 = *(const float2*)(add1 + i0);
                float2 a1 = *(const float2*)(add1 + i1);
                float2 c0 = *(const float2*)(add2 + i0);
                float2 c1 = *(const float2*)(add2 + i1);
                float t0 = (v[0] + b0 + a0.x + c0.x) * rv0;
                float t1 = (v[1] + b1 + a0.y + c0.y) * rv0;
                float t2 = (v[2] + b0 + a1.x + c1.x) * rv1;
                float t3 = (v[3] + b1 + a1.y + c1.y) * rv1;
                v[0] = t0 >= 0.f ? t0 : al_p * t0;
                v[1] = t1 >= 0.f ? t1 : al_p * t1;
                v[2] = t2 >= 0.f ? t2 : al_p * t2;
                v[3] = t3 >= 0.f ? t3 : al_p * t3;
                *(float2*)(C2 + (size_t)gm0 * (NLAY * DD) + gc) = make_float2(v[0], v[1]);
                *(float2*)(C2 + (size_t)gm1 * (NLAY * DD) + gc) = make_float2(v[2], v[3]);
            } else if (EPI == 3) {
                float2 a0 = *(const float2*)(add1 + i0);
                float2 a1 = *(const float2*)(add1 + i1);
                v[0] += bias[gc] + a0.x;     v[1] += bias[gc + 1] + a0.y;
                v[2] += bias[gc] + a1.x;     v[3] += bias[gc + 1] + a1.y;
            } else if (EPI == 5) {
                float2 a0 = *(const float2*)(Cadd + i0);
                float2 a1 = *(const float2*)(Cadd + i1);
                v[0] += a0.x; v[1] += a0.y; v[2] += a1.x; v[3] += a1.y;
            }
            *(float2*)(C + i0) = make_float2(v[0], v[1]);
            *(float2*)(C + i1) = make_float2(v[2], v[3]);
        }
    }
}

// ================= small kernels =================
__global__ void detect_dom_fmt(const unsigned int* __restrict__ w) {
    __shared__ int sf, sbt;
    if (threadIdx.x == 0) { sf = 0; sbt = 0; }
    __syncthreads();
    for (int i = threadIdx.x; i < 1024; i += 256) {
        unsigned int v = w[i];
        if (v == 0x3F800000u) atomicOr(&sf, 1);
        else if (v > 1u) atomicOr(&sbt, 1);
    }
    __syncthreads();
    if (threadIdx.x == 0) g_domfmt = sf ? 2 : (sbt ? 0 : 1);
}

__global__ void convert_dom(const void* __restrict__ dom, unsigned char* __restrict__ out) {
    int i = blockIdx.x * 256 + threadIdx.x;
    if (i >= MT * NDOM) return;
    int fmt = g_domfmt;
    unsigned char v;
    if (fmt == 0)      v = ((const unsigned char*)dom)[i] != 0;
    else if (fmt == 1) v = ((const int*)dom)[i] != 0;
    else               v = ((const float*)dom)[i] != 0.f;
    out[i] = v;
}

__global__ void rowstats_kernel(const float* __restrict__ adj,
                                const float* __restrict__ depmap,
                                float* __restrict__ denom,
                                float* __restrict__ fadj,
                                float* __restrict__ badj) {
    int warp = (blockIdx.x * blockDim.x + threadIdx.x) >> 5;
    int lane = threadIdx.x & 31;
    if (warp >= MT) return;
    int b = warp >> 9;
    int s = warp & 511;
    const float* arow = adj + (size_t)(b * SD + s) * SD;
    const float* drow = depmap + (size_t)(b * SD + s) * SD;
    const float* acol = adj + (size_t)b * SD * SD + s;
    float sa = 0.f, sf = 0.f, sb = 0.f;
    for (int j = lane; j < SD; j += 32) {
        float a = arow[j];
        float dp = drow[j];
        sa += a;
        sf += a * dp;
        sb += acol[(size_t)j * SD] * dp;
    }
#pragma unroll
    for (int off = 16; off > 0; off >>= 1) {
        sa += __shfl_down_sync(0xffffffffu, sa, off);
        sf += __shfl_down_sync(0xffffffffu, sf, off);
        sb += __shfl_down_sync(0xffffffffu, sb, off);
    }
    if (lane == 0) {
        denom[warp] = sa + 1.f;
        fadj[warp] = sf;
        badj[warp] = sb;
    }
}

__global__ void copy_kernel(const float* __restrict__ src, float* __restrict__ dst, int n4) {
    int i = blockIdx.x * blockDim.x + threadIdx.x;
    if (i < n4) ((float4*)dst)[i] = ((const float4*)src)[i];
}

__global__ void transpose512(const float* __restrict__ in, float* __restrict__ out) {
    __shared__ float ts[32][33];
    int b = blockIdx.z;
    int x0 = blockIdx.x * 32, y0 = blockIdx.y * 32;
    const float* ib = in + (size_t)b * 262144;
    float* ob = out + (size_t)b * 262144;
    int tx = threadIdx.x, ty = threadIdx.y;
#pragma unroll
    for (int i = 0; i < 32; i += 8)
        ts[ty + i][tx] = ib[(size_t)(y0 + ty + i) * 512 + x0 + tx];
    __syncthreads();
#pragma unroll
    for (int i = 0; i < 32; i += 8)
        ob[(size_t)(x0 + ty + i) * 512 + y0 + tx] = ts[tx][ty + i];
}

__global__ void pool_kernel(const float* __restrict__ X,
                            const unsigned char* __restrict__ dom,
                            float* __restrict__ pooled) {
    int b = blockIdx.x;
    int d = blockIdx.y * 128 + threadIdx.x;
    float mv[NDOM];
#pragma unroll
    for (int k = 0; k < NDOM; k++) mv[k] = -3.402823466e38f;
    const float* Xb = X + (size_t)b * SD * DD;
    const unsigned long long* db = (const unsigned long long*)(dom + (size_t)b * SD * NDOM);
    for (int s = 0; s < SD; s++) {
        float x = Xb[(size_t)s * DD + d];
        unsigned long long mk = db[s];
#pragma unroll
        for (int k = 0; k < NDOM; k++) {
            float v = ((mk >> (8 * k)) & 0xffull) ? -10000.f : x;
            mv[k] = fmaxf(mv[k], v);
        }
    }
#pragma unroll
    for (int k = 0; k < NDOM; k++) pooled[((size_t)b * NDOM + k) * DD + d] = mv[k];
}

__global__ void dgate_kernel(const float* __restrict__ pooled,
                             const float* __restrict__ Wdg,
                             const float* __restrict__ bdg,
                             float* __restrict__ out) {
    int bk = blockIdx.x;
    int d = blockIdx.y * 128 + threadIdx.x;
    __shared__ float sp[DD];
    for (int e = threadIdx.x; e < DD; e += 128) sp[e] = pooled[(size_t)bk * DD + e];
    __syncthreads();
    float acc = bdg[d];
#pragma unroll 8
    for (int e = 0; e < DD; e++) acc += sp[e] * Wdg[(size_t)e * DD + d];
    out[(size_t)bk * DD + d] = sigf(acc);
}

__global__ void buildfb_kernel(const float* __restrict__ X,
                               const float* __restrict__ relX,
                               const float* __restrict__ did,
                               const float* __restrict__ rid,
                               const float* __restrict__ domout,
                               float* __restrict__ fo,
                               float* __restrict__ bo) {
    int bs = blockIdx.x;
    int b = bs >> 9;
    int d = threadIdx.x;
    __shared__ float sdi[NDOM], sri[NDOM];
    if (threadIdx.x < NDOM) sdi[threadIdx.x] = did[(size_t)bs * NDOM + threadIdx.x];
    else if (threadIdx.x < 2 * NDOM) sri[threadIdx.x - NDOM] = rid[(size_t)bs * NDOM + threadIdx.x - NDOM];
    __syncthreads();
    float dsum = 0.f, rsum = 0.f;
#pragma unroll
    for (int k = 0; k < NDOM; k++) { dsum += sdi[k]; rsum += sri[k]; }
    bool dmask = (dsum == 1.0f);
    bool rmask = (rsum == 1.0f);
    size_t idx = (size_t)bs * DD + d;
    float f = dmask ? 0.f : X[idx];
    float bv = rmask ? 0.f : relX[idx];
    const float* dob = domout + (size_t)b * NDOM * DD;
#pragma unroll
    for (int k = 0; k < NDOM; k++) {
        float dv = dob[(size_t)k * DD + d];
        f += sdi[k] * dv;
        bv += sri[k] * dv;
    }
    fo[idx] = f;
    bo[idx] = bv;
}

// ================= host launcher =================
extern "C" void kernel_launch(void* const* d_in, const int* in_sizes, int n_in,
                              void* d_out, int out_size) {
    const float* adj       = (const float*)d_in[0];
    const void*  domain    = d_in[1];
    const float* domain_id = (const float*)d_in[2];
    const float* redom_id  = (const float*)d_in[3];
    const float* frontrel  = (const float*)d_in[4];
    const float* backrel   = (const float*)d_in[5];
    const float* depmap    = (const float*)d_in[6];
    const float* rel       = (const float*)d_in[7];
    const float* gcn       = (const float*)d_in[8];
    const float* W_layers  = (const float*)d_in[10];
    const float* b_layers  = (const float*)d_in[11];
    const float* prelu_a   = (const float*)d_in[12];
    const float* W_dg      = (const float*)d_in[13];
    const float* b_dg      = (const float*)d_in[14];
    const float* W_mg      = (const float*)d_in[15];
    const float* b_mg      = (const float*)d_in[16];
    const float* W_out     = (const float*)d_in[17];
    const float* b_out     = (const float*)d_in[18];

    float *X, *relX, *fo, *bo, *Pf, *Pb, *delta, *AxpX, *FR, *BR, *relT, *outs,
          *pooled, *domout, *denom, *fadj, *badj;
    unsigned char *dom8;
    cudaGetSymbolAddress((void**)&X, g_X);
    cudaGetSymbolAddress((void**)&relX, g_relX);
    cudaGetSymbolAddress((void**)&fo, g_fo);
    cudaGetSymbolAddress((void**)&bo, g_bo);
    cudaGetSymbolAddress((void**)&Pf, g_Pf);
    cudaGetSymbolAddress((void**)&Pb, g_Pb);
    cudaGetSymbolAddress((void**)&delta, g_delta);
    cudaGetSymbolAddress((void**)&AxpX, g_AxpX);
    cudaGetSymbolAddress((void**)&FR, g_FR);
    cudaGetSymbolAddress((void**)&BR, g_BR);
    cudaGetSymbolAddress((void**)&relT, g_relT);
    cudaGetSymbolAddress((void**)&outs, g_outs);
    cudaGetSymbolAddress((void**)&pooled, g_pooled);
    cudaGetSymbolAddress((void**)&domout, g_domout);
    cudaGetSymbolAddress((void**)&denom, g_denom);
    cudaGetSymbolAddress((void**)&fadj, g_fadj);
    cudaGetSymbolAddress((void**)&badj, g_badj);
    cudaGetSymbolAddress((void**)&dom8, g_dom8);

    cudaFuncSetAttribute(hgemm<0, false, false>, cudaFuncAttributeMaxDynamicSharedMemorySize, SMEM_TC);
    cudaFuncSetAttribute(hgemm<1, false, false>, cudaFuncAttributeMaxDynamicSharedMemorySize, SMEM_TC);
    cudaFuncSetAttribute(hgemm<2, false, false>, cudaFuncAttributeMaxDynamicSharedMemorySize, SMEM_TC);
    cudaFuncSetAttribute(hgemm<3, false, false>, cudaFuncAttributeMaxDynamicSharedMemorySize, SMEM_TC);
    cudaFuncSetAttribute(hgemm<4, true,  false>, cudaFuncAttributeMaxDynamicSharedMemorySize, SMEM_TC);
    cudaFuncSetAttribute(hgemm<5, true,  true >, cudaFuncAttributeMaxDynamicSharedMemorySize, SMEM_TC);

    dim3 tg(4, 64);           // 128-wide N tiles x 128-tall M tiles
    const int TB = 256;

    detect_dom_fmt<<<1, 256>>>((const unsigned int*)domain);
    convert_dom<<<(MT * NDOM + 255) / 256, 256>>>(domain, dom8);
    rowstats_kernel<<<1024, 256>>>(adj, depmap, denom, fadj, badj);
    copy_kernel<<<(MT * DD / 4 + 255) / 256, 256>>>(gcn, X, MT * DD / 4);
    transpose512<<<dim3(16, 16, 16), dim3(32, 8)>>>(rel, relT);

    // FR = frontrel @ W_mg[D:2D] + b_mg ; BR = backrel @ W_mg[D:2D] + b_mg
    hgemm<0, false, false><<<tg, TB, SMEM_TC>>>(frontrel, W_mg + (size_t)DD * DD, nullptr, FR,
        nullptr, b_mg, nullptr, nullptr, nullptr, nullptr, nullptr, 0, nullptr, DD);
    hgemm<0, false, false><<<tg, TB, SMEM_TC>>>(backrel, W_mg + (size_t)DD * DD, nullptr, BR,
        nullptr, b_mg, nullptr, nullptr, nullptr, nullptr, nullptr, 0, nullptr, DD);

    for (int l = 0; l < NLAY; l++) {
        pool_kernel<<<dim3(BB, DD / 128), 128>>>(X, dom8, pooled);
        dgate_kernel<<<dim3(BB * NDOM, DD / 128), 128>>>(pooled, W_dg, b_dg, domout);
        // relX = rel @ X
        hgemm<4, true, false><<<tg, TB, SMEM_TC>>>(rel, X, nullptr, relX,
            nullptr, nullptr, nullptr, nullptr, nullptr, nullptr, nullptr, 0, nullptr, DD);
        buildfb_kernel<<<MT, 512>>>(X, relX, domain_id, redom_id, domout, fo, bo);
        // Pf = frontadj * sigmoid(fo @ W_mg[:D] + FR) * fo ; Pb analogous
        hgemm<1, false, false><<<tg, TB, SMEM_TC>>>(fo, W_mg, nullptr, Pf,
            nullptr, nullptr, FR, nullptr, fadj, fo, nullptr, 0, nullptr, DD);
        hgemm<1, false, false><<<tg, TB, SMEM_TC>>>(bo, W_mg, nullptr, Pb,
            nullptr, nullptr, BR, nullptr, badj, bo, nullptr, 0, nullptr, DD);
        // delta = rel^T @ Pf
        hgemm<4, true, false><<<tg, TB, SMEM_TC>>>(relT, Pf, nullptr, delta,
            nullptr, nullptr, nullptr, nullptr, nullptr, nullptr, nullptr, 0, nullptr, DD);
        // AxpX = adj @ (X * rel) + X
        hgemm<5, true, true><<<tg, TB, SMEM_TC>>>(adj, X, rel, AxpX,
            X, nullptr, nullptr, nullptr, nullptr, nullptr, nullptr, 0, nullptr, DD);
        // X = PReLU((AxpX @ W_l + 2*b_l + delta + Pb)/denom); also -> outs slot l
        hgemm<2, false, false><<<tg, TB, SMEM_TC>>>(AxpX, W_layers + (size_t)l * DD * DD, nullptr, X,
            nullptr, b_layers + (size_t)l * DD, delta, Pb, denom, nullptr, prelu_a, l,
            outs + (size_t)l * DD, DD);
    }
    // final: out = outs @ W_out + b_out + gcn_inputs
    hgemm<3, false, false><<<tg, TB, SMEM_TC>>>(outs, W_out, nullptr, (float*)d_out,
        nullptr, b_out, gcn, nullptr, nullptr, nullptr, nullptr, 0, nullptr, NLAY * DD);
}

// round 6
// speedup vs baseline: 1.9071x; 1.1063x over previous
#include <cuda_runtime.h>
#include <cuda_bf16.h>
#include <math.h>
#include <stdint.h>

#define BB 16
#define SD 512
#define DD 512
#define MT (BB*SD)      // 8192
#define NLAY 3
#define NDOM 8

typedef __nv_bfloat16 bf16;

// ---------------- scratch (device globals; no allocation) ----------------
__device__ float g_X[MT*DD];
__device__ float g_relX[MT*DD];
__device__ float g_fo[MT*DD];
__device__ float g_bo[MT*DD];
__device__ float g_Pb[MT*DD];
__device__ float g_delta[MT*DD];
__device__ float g_FR[MT*DD];
__device__ float g_BR[MT*DD];
__device__ float g_pooled[BB*NDOM*DD];
__device__ float g_domout[BB*NDOM*DD];
__device__ float g_denom[MT];
__device__ float g_fadj[MT];
__device__ float g_badj[MT];
__device__ unsigned char g_dom8[MT*NDOM];
__device__ int g_domfmt;

// bf16 hi/lo planes
__device__ bf16 g_adjh[MT*DD],  g_adjl[MT*DD];
__device__ bf16 g_relh[MT*DD],  g_rell[MT*DD];
__device__ bf16 g_relTh[MT*DD], g_relTl[MT*DD];
__device__ bf16 g_Xh[MT*DD],    g_Xl[MT*DD];
__device__ bf16 g_Xrh[MT*DD],   g_Xrl[MT*DD];
__device__ bf16 g_foh[MT*DD],   g_fol[MT*DD];
__device__ bf16 g_boh[MT*DD],   g_bol[MT*DD];
__device__ bf16 g_Pfh[MT*DD],   g_Pfl[MT*DD];
__device__ bf16 g_Axh[MT*DD],   g_Axl[MT*DD];
__device__ bf16 g_outsh[MT*NLAY*DD], g_outsl[MT*NLAY*DD];
__device__ bf16 g_frh[MT*DD],   g_frl[MT*DD];
__device__ bf16 g_brh[MT*DD],   g_brl[MT*DD];
__device__ bf16 g_wmgh[2*DD*DD], g_wmgl[2*DD*DD];
__device__ bf16 g_wlh[NLAY*DD*DD], g_wll[NLAY*DD*DD];
__device__ bf16 g_woh[NLAY*DD*DD], g_wol[NLAY*DD*DD];

__device__ __forceinline__ float sigf(float x) { return 1.f / (1.f + expf(-x)); }

// fp32 pair -> packed bf16x2 (hi plane word, lo plane word)
__device__ __forceinline__ void split2(float x, float y, uint32_t& h, uint32_t& lo) {
    bf16 hx = __float2bfloat16(x), hy = __float2bfloat16(y);
    float rx = x - __bfloat162float(hx), ry = y - __bfloat162float(hy);
    bf16 lx = __float2bfloat16(rx), ly = __float2bfloat16(ry);
    h  = ((uint32_t)__bfloat16_as_ushort(hy) << 16) | (uint32_t)__bfloat16_as_ushort(hx);
    lo = ((uint32_t)__bfloat16_as_ushort(ly) << 16) | (uint32_t)__bfloat16_as_ushort(lx);
}

__device__ __forceinline__ uint32_t smem_u32(const void* p) {
    uint32_t a;
    asm("{ .reg .u64 t; cvta.to.shared.u64 t, %1; cvt.u32.u64 %0, t; }" : "=r"(a) : "l"(p));
    return a;
}
__device__ __forceinline__ void cpa16(uint32_t dst, const void* src) {
    asm volatile("{ .reg .u64 g; cvta.to.global.u64 g, %1; cp.async.cg.shared.global [%0], [g], 16; }"
                 :: "r"(dst), "l"(src) : "memory");
}
#define CP_COMMIT() asm volatile("cp.async.commit_group;" ::: "memory")
#define CP_WAIT1()  asm volatile("cp.async.wait_group 1;" ::: "memory")
#define CP_WAIT0()  asm volatile("cp.async.wait_group 0;" ::: "memory")

#define LDSM4(r0, r1, r2, r3, a) \
    asm volatile("ldmatrix.sync.aligned.m8n8.x4.shared.b16 {%0,%1,%2,%3}, [%4];" \
        : "=r"(r0), "=r"(r1), "=r"(r2), "=r"(r3) : "r"(a))
#define LDSM4T(r0, r1, r2, r3, a) \
    asm volatile("ldmatrix.sync.aligned.m8n8.x4.trans.shared.b16 {%0,%1,%2,%3}, [%4];" \
        : "=r"(r0), "=r"(r1), "=r"(r2), "=r"(r3) : "r"(a))
#define MMA(acc, a, b) \
    asm volatile("mma.sync.aligned.m16n8k16.row.col.f32.bf16.bf16.f32 " \
        "{%0,%1,%2,%3}, {%4,%5,%6,%7}, {%8,%9}, {%0,%1,%2,%3};" \
        : "+f"((acc)[0]), "+f"((acc)[1]), "+f"((acc)[2]), "+f"((acc)[3]) \
        : "r"((a)[0]), "r"((a)[1]), "r"((a)[2]), "r"((a)[3]), "r"((b)[0]), "r"((b)[1]))

// ================= HMMA bf16x3 GEMM, pre-split operands, cp.async 3-stage =====
// CTA tile 256m x 128n, 8 warps (4m x 2n), warp tile 64x64.
// EPI: 0: C=acc+bias | 1: pair=split(rowv*sig(acc+add1)*mulel) | 2: prelu -> C,Xpair,outs-pair
//      3: C=acc+bias+add1 | 4: C=acc | 5: pair=split(acc+Cadd) | 6: C=rowv*sig(acc+add1)*mulel
#define APITCH 80
#define BPITCH 272
#define A_PL (256*APITCH)            // 20480
#define B_PL (32*BPITCH)             // 8704
#define STG (2*A_PL + 2*B_PL)        // 58368
#define SMEM_TC (3*STG)              // 175104

template<int EPI, bool BATCHB>
__global__ void __launch_bounds__(256, 1) hgemm(
    const bf16* __restrict__ Ah, const bf16* __restrict__ Al, int lda,
    const bf16* __restrict__ Bh, const bf16* __restrict__ Bl, int ldb, int K,
    float* __restrict__ C,
    bf16* __restrict__ Ch, bf16* __restrict__ Cl, int ldc2,
    bf16* __restrict__ C2h, bf16* __restrict__ C2l,
    const float* __restrict__ bias, const float* __restrict__ add1,
    const float* __restrict__ add2, const float* __restrict__ rowv,
    const float* __restrict__ mulel, const float* __restrict__ Cadd,
    const float* __restrict__ pa, int l)
{
    extern __shared__ __align__(128) char smp[];
    const uint32_t sb = smem_u32(smp);
    const int t = threadIdx.x;
    const int wid = t >> 5;
    const int lane = t & 31;
    const int m0 = blockIdx.y * 256;
    const int n0 = blockIdx.x * 128;
    const int KB = K >> 5;
    const int wm = (wid & 3) * 64;
    const int wn = (wid >> 2) * 64;
    const size_t boff = BATCHB ? (size_t)(m0 >> 9) * 512 * ldb : 0;

    float acc[4][8][4];
#pragma unroll
    for (int im = 0; im < 4; im++)
#pragma unroll
        for (int in = 0; in < 8; in++)
#pragma unroll
            for (int c = 0; c < 4; c++) acc[im][in][c] = 0.f;

    // ldmatrix lane addressing
    const int q = lane >> 3, r = lane & 7;
    const int arow = (q & 1) * 8 + r;
    const int acol = (q >> 1) * 8;
    const int bkrow = (q & 1) * 8 + r;
    const int bq8 = (q >> 1) * 8;

    auto stage_cp = [&](int st, int kb) {
        const int k0 = kb * 32;
        const uint32_t sa = sb + (uint32_t)st * STG;
        // A planes: 256 rows x 4 chunks = 1024 chunks/plane
#pragma unroll
        for (int i = 0; i < 4; i++) {
            int c = t + i * 256;
            int row = c >> 2, kc = c & 3;
            size_t go = (size_t)(m0 + row) * lda + k0 + kc * 8;
            uint32_t so = (uint32_t)row * APITCH + kc * 16;
            cpa16(sa + so, Ah + go);
            cpa16(sa + A_PL + so, Al + go);
        }
        // B planes: 32 rows x 16 chunks = 512 chunks/plane
#pragma unroll
        for (int i = 0; i < 2; i++) {
            int c = t + i * 256;
            int row = c >> 4, nc = c & 15;
            size_t go = boff + (size_t)(k0 + row) * ldb + n0 + nc * 8;
            uint32_t so = (uint32_t)row * BPITCH + nc * 16;
            cpa16(sa + 2 * A_PL + so, Bh + go);
            cpa16(sa + 2 * A_PL + B_PL + so, Bl + go);
        }
        CP_COMMIT();
    };

    auto compute = [&](int st) {
        const uint32_t aH = sb + (uint32_t)st * STG;
        const uint32_t aL = aH + A_PL;
        const uint32_t bHp = aH + 2 * A_PL;
        const uint32_t bLp = bHp + B_PL;
#pragma unroll
        for (int ks = 0; ks < 2; ks++) {
            const int k16 = ks * 16;
            uint32_t ah[4][4], al[4][4], bb[8][2];
#pragma unroll
            for (int im = 0; im < 4; im++) {
                uint32_t off = (uint32_t)(wm + im * 16 + arow) * APITCH + (k16 + acol) * 2;
                LDSM4(ah[im][0], ah[im][1], ah[im][2], ah[im][3], aH + off);
                LDSM4(al[im][0], al[im][1], al[im][2], al[im][3], aL + off);
            }
#pragma unroll
            for (int j2 = 0; j2 < 4; j2++) {
                uint32_t off = (uint32_t)(k16 + bkrow) * BPITCH + (wn + bq8 + j2 * 16) * 2;
                LDSM4T(bb[j2 * 2][0], bb[j2 * 2][1], bb[j2 * 2 + 1][0], bb[j2 * 2 + 1][1], bHp + off);
            }
#pragma unroll
            for (int im = 0; im < 4; im++)
#pragma unroll
                for (int in = 0; in < 8; in++) {
                    MMA(acc[im][in], ah[im], bb[in]);
                    MMA(acc[im][in], al[im], bb[in]);
                }
#pragma unroll
            for (int j2 = 0; j2 < 4; j2++) {
                uint32_t off = (uint32_t)(k16 + bkrow) * BPITCH + (wn + bq8 + j2 * 16) * 2;
                LDSM4T(bb[j2 * 2][0], bb[j2 * 2][1], bb[j2 * 2 + 1][0], bb[j2 * 2 + 1][1], bLp + off);
            }
#pragma unroll
            for (int im = 0; im < 4; im++)
#pragma unroll
                for (int in = 0; in < 8; in++)
                    MMA(acc[im][in], ah[im], bb[in]);
        }
    };

    stage_cp(0, 0);
    stage_cp(1, 1);
    for (int kb = 0; kb < KB; kb++) {
        if (kb + 2 < KB) { CP_WAIT1(); } else { CP_WAIT0(); }
        __syncthreads();
        if (kb + 2 < KB) stage_cp((kb + 2) % 3, kb + 2);
        compute(kb % 3);
    }

    // ---------------- epilogue ----------------
    const int lr = lane >> 2;
    const int lc = (lane & 3) * 2;
    float al_p = 0.f;
    if (EPI == 2) al_p = pa[l];

#pragma unroll
    for (int im = 0; im < 4; im++) {
        const int gm0 = m0 + wm + im * 16 + lr;
        const int gm1 = gm0 + 8;
        float rv0 = 1.f, rv1 = 1.f;
        if (EPI == 1 || EPI == 6) { rv0 = rowv[gm0]; rv1 = rowv[gm1]; }
        if (EPI == 2) { rv0 = 1.f / rowv[gm0]; rv1 = 1.f / rowv[gm1]; }
#pragma unroll
        for (int in = 0; in < 8; in++) {
            const int gc = n0 + wn + in * 8 + lc;
            float v[4] = {acc[im][in][0], acc[im][in][1], acc[im][in][2], acc[im][in][3]};
            const size_t i0 = (size_t)gm0 * 512 + gc;
            const size_t i1 = (size_t)gm1 * 512 + gc;
            if (EPI == 0) {
                v[0] += bias[gc]; v[1] += bias[gc + 1];
                v[2] += bias[gc]; v[3] += bias[gc + 1];
                *(float2*)(C + i0) = make_float2(v[0], v[1]);
                *(float2*)(C + i1) = make_float2(v[2], v[3]);
            } else if (EPI == 1 || EPI == 6) {
                float2 a0 = *(const float2*)(add1 + i0);
                float2 a1 = *(const float2*)(add1 + i1);
                float2 e0 = *(const float2*)(mulel + i0);
                float2 e1 = *(const float2*)(mulel + i1);
                v[0] = rv0 * sigf(v[0] + a0.x) * e0.x;
                v[1] = rv0 * sigf(v[1] + a0.y) * e0.y;
                v[2] = rv1 * sigf(v[2] + a1.x) * e1.x;
                v[3] = rv1 * sigf(v[3] + a1.y) * e1.y;
                if (EPI == 1) {
                    uint32_t h, lo;
                    split2(v[0], v[1], h, lo);
                    *(uint32_t*)(Ch + (size_t)gm0 * ldc2 + gc) = h;
                    *(uint32_t*)(Cl + (size_t)gm0 * ldc2 + gc) = lo;
                    split2(v[2], v[3], h, lo);
                    *(uint32_t*)(Ch + (size_t)gm1 * ldc2 + gc) = h;
                    *(uint32_t*)(Cl + (size_t)gm1 * ldc2 + gc) = lo;
                } else {
                    *(float2*)(C + i0) = make_float2(v[0], v[1]);
                    *(float2*)(C + i1) = make_float2(v[2], v[3]);
                }
            } else if (EPI == 2) {
                float b0 = 2.f * bias[gc], b1 = 2.f * bias[gc + 1];
                float2 a0 = *(const float2*)(add1 + i0);
                float2 a1 = *(const float2*)(add1 + i1);
                float2 c0 = *(const float2*)(add2 + i0);
                float2 c1 = *(const float2*)(add2 + i1);
                float t0 = (v[0] + b0 + a0.x + c0.x) * rv0;
                float t1 = (v[1] + b1 + a0.y + c0.y) * rv0;
                float t2 = (v[2] + b0 + a1.x + c1.x) * rv1;
                float t3 = (v[3] + b1 + a1.y + c1.y) * rv1;
                v[0] = t0 >= 0.f ? t0 : al_p * t0;
                v[1] = t1 >= 0.f ? t1 : al_p * t1;
                v[2] = t2 >= 0.f ? t2 : al_p * t2;
                v[3] = t3 >= 0.f ? t3 : al_p * t3;
                *(float2*)(C + i0) = make_float2(v[0], v[1]);
                *(float2*)(C + i1) = make_float2(v[2], v[3]);
                uint32_t h, lo;
                split2(v[0], v[1], h, lo);
                *(uint32_t*)(Ch + (size_t)gm0 * ldc2 + gc) = h;
                *(uint32_t*)(Cl + (size_t)gm0 * ldc2 + gc) = lo;
                *(uint32_t*)(C2h + (size_t)gm0 * (NLAY * DD) + gc) = h;
                *(uint32_t*)(C2l + (size_t)gm0 * (NLAY * DD) + gc) = lo;
                split2(v[2], v[3], h, lo);
                *(uint32_t*)(Ch + (size_t)gm1 * ldc2 + gc) = h;
                *(uint32_t*)(Cl + (size_t)gm1 * ldc2 + gc) = lo;
                *(uint32_t*)(C2h + (size_t)gm1 * (NLAY * DD) + gc) = h;
                *(uint32_t*)(C2l + (size_t)gm1 * (NLAY * DD) + gc) = lo;
            } else if (EPI == 3) {
                float2 a0 = *(const float2*)(add1 + i0);
                float2 a1 = *(const float2*)(add1 + i1);
                v[0] += bias[gc] + a0.x;     v[1] += bias[gc + 1] + a0.y;
                v[2] += bias[gc] + a1.x;     v[3] += bias[gc + 1] + a1.y;
                *(float2*)(C + i0) = make_float2(v[0], v[1]);
                *(float2*)(C + i1) = make_float2(v[2], v[3]);
            } else if (EPI == 4) {
                *(float2*)(C + i0) = make_float2(v[0], v[1]);
                *(float2*)(C + i1) = make_float2(v[2], v[3]);
            } else if (EPI == 5) {
                float2 a0 = *(const float2*)(Cadd + i0);
                float2 a1 = *(const float2*)(Cadd + i1);
                v[0] += a0.x; v[1] += a0.y; v[2] += a1.x; v[3] += a1.y;
                uint32_t h, lo;
                split2(v[0], v[1], h, lo);
                *(uint32_t*)(Ch + (size_t)gm0 * ldc2 + gc) = h;
                *(uint32_t*)(Cl + (size_t)gm0 * ldc2 + gc) = lo;
                split2(v[2], v[3], h, lo);
                *(uint32_t*)(Ch + (size_t)gm1 * ldc2 + gc) = h;
                *(uint32_t*)(Cl + (size_t)gm1 * ldc2 + gc) = lo;
            }
        }
    }
}

// ================= small kernels =================
__global__ void detect_dom_fmt(const unsigned int* __restrict__ w) {
    __shared__ int sf, sbt;
    if (threadIdx.x == 0) { sf = 0; sbt = 0; }
    __syncthreads();
    for (int i = threadIdx.x; i < 1024; i += 256) {
        unsigned int v = w[i];
        if (v == 0x3F800000u) atomicOr(&sf, 1);
        else if (v > 1u) atomicOr(&sbt, 1);
    }
    __syncthreads();
    if (threadIdx.x == 0) g_domfmt = sf ? 2 : (sbt ? 0 : 1);
}

__global__ void convert_dom(const void* __restrict__ dom, unsigned char* __restrict__ out) {
    int i = blockIdx.x * 256 + threadIdx.x;
    if (i >= MT * NDOM) return;
    int fmt = g_domfmt;
    unsigned char v;
    if (fmt == 0)      v = ((const unsigned char*)dom)[i] != 0;
    else if (fmt == 1) v = ((const int*)dom)[i] != 0;
    else               v = ((const float*)dom)[i] != 0.f;
    out[i] = v;
}

__global__ void rowstats_kernel(const float* __restrict__ adj,
                                const float* __restrict__ depmap,
                                float* __restrict__ denom,
                                float* __restrict__ fadj,
                                float* __restrict__ badj) {
    int warp = (blockIdx.x * blockDim.x + threadIdx.x) >> 5;
    int lane = threadIdx.x & 31;
    if (warp >= MT) return;
    int b = warp >> 9;
    int s = warp & 511;
    const float* arow = adj + (size_t)(b * SD + s) * SD;
    const float* drow = depmap + (size_t)(b * SD + s) * SD;
    const float* acol = adj + (size_t)b * SD * SD + s;
    float sa = 0.f, sf = 0.f, sb = 0.f;
    for (int j = lane; j < SD; j += 32) {
        float a = arow[j];
        float dp = drow[j];
        sa += a;
        sf += a * dp;
        sb += acol[(size_t)j * SD] * dp;
    }
#pragma unroll
    for (int off = 16; off > 0; off >>= 1) {
        sa += __shfl_down_sync(0xffffffffu, sa, off);
        sf += __shfl_down_sync(0xffffffffu, sf, off);
        sb += __shfl_down_sync(0xffffffffu, sb, off);
    }
    if (lane == 0) {
        denom[warp] = sa + 1.f;
        fadj[warp] = sf;
        badj[warp] = sb;
    }
}

// split fp32 array -> bf16 hi/lo planes (n2 = elements/2)
__global__ void split_kernel(const float* __restrict__ src, bf16* __restrict__ h,
                             bf16* __restrict__ lo, int n2) {
    int i = blockIdx.x * 256 + threadIdx.x;
    if (i >= n2) return;
    float2 v = ((const float2*)src)[i];
    uint32_t hw, lw;
    split2(v.x, v.y, hw, lw);
    ((uint32_t*)h)[i] = hw;
    ((uint32_t*)lo)[i] = lw;
}

// copy fp32 + split (for X0 = gcn)
__global__ void copy_split_kernel(const float* __restrict__ src, float* __restrict__ dst,
                                  bf16* __restrict__ h, bf16* __restrict__ lo, int n2) {
    int i = blockIdx.x * 256 + threadIdx.x;
    if (i >= n2) return;
    float2 v = ((const float2*)src)[i];
    ((float2*)dst)[i] = v;
    uint32_t hw, lw;
    split2(v.x, v.y, hw, lw);
    ((uint32_t*)h)[i] = hw;
    ((uint32_t*)lo)[i] = lw;
}

// elementwise product + split (Xrel = X * rel)
__global__ void mulsplit_kernel(const float* __restrict__ a, const float* __restrict__ b,
                                bf16* __restrict__ h, bf16* __restrict__ lo, int n2) {
    int i = blockIdx.x * 256 + threadIdx.x;
    if (i >= n2) return;
    float2 va = ((const float2*)a)[i];
    float2 vb = ((const float2*)b)[i];
    uint32_t hw, lw;
    split2(va.x * vb.x, va.y * vb.y, hw, lw);
    ((uint32_t*)h)[i] = hw;
    ((uint32_t*)lo)[i] = lw;
}

// per-batch transpose + split (relT pair)
__global__ void transpose_split(const float* __restrict__ in, bf16* __restrict__ h,
                                bf16* __restrict__ lo) {
    __shared__ float ts[32][33];
    int b = blockIdx.z;
    int x0 = blockIdx.x * 32, y0 = blockIdx.y * 32;
    const float* ib = in + (size_t)b * 262144;
    int tx = threadIdx.x, ty = threadIdx.y;
#pragma unroll
    for (int i = 0; i < 32; i += 8)
        ts[ty + i][tx] = ib[(size_t)(y0 + ty + i) * 512 + x0 + tx];
    __syncthreads();
#pragma unroll
    for (int i = 0; i < 32; i += 8) {
        float v = ts[tx][ty + i];
        bf16 hv = __float2bfloat16(v);
        size_t o = (size_t)b * 262144 + (size_t)(x0 + ty + i) * 512 + y0 + tx;
        h[o] = hv;
        lo[o] = __float2bfloat16(v - __bfloat162float(hv));
    }
}

__global__ void pool_kernel(const float* __restrict__ X,
                            const unsigned char* __restrict__ dom,
                            float* __restrict__ pooled) {
    int b = blockIdx.x;
    int d = blockIdx.y * 128 + threadIdx.x;
    float mv[NDOM];
#pragma unroll
    for (int k = 0; k < NDOM; k++) mv[k] = -3.402823466e38f;
    const float* Xb = X + (size_t)b * SD * DD;
    const unsigned long long* db = (const unsigned long long*)(dom + (size_t)b * SD * NDOM);
    for (int s = 0; s < SD; s++) {
        float x = Xb[(size_t)s * DD + d];
        unsigned long long mk = db[s];
#pragma unroll
        for (int k = 0; k < NDOM; k++) {
            float v = ((mk >> (8 * k)) & 0xffull) ? -10000.f : x;
            mv[k] = fmaxf(mv[k], v);
        }
    }
#pragma unroll
    for (int k = 0; k < NDOM; k++) pooled[((size_t)b * NDOM + k) * DD + d] = mv[k];
}

__global__ void dgate_kernel(const float* __restrict__ pooled,
                             const float* __restrict__ Wdg,
                             const float* __restrict__ bdg,
                             float* __restrict__ out) {
    int bk = blockIdx.x;
    int d = blockIdx.y * 128 + threadIdx.x;
    __shared__ float sp[DD];
    for (int e = threadIdx.x; e < DD; e += 128) sp[e] = pooled[(size_t)bk * DD + e];
    __syncthreads();
    float acc = bdg[d];
#pragma unroll 8
    for (int e = 0; e < DD; e++) acc += sp[e] * Wdg[(size_t)e * DD + d];
    out[(size_t)bk * DD + d] = sigf(acc);
}

__global__ void buildfb_kernel(const float* __restrict__ X,
                               const float* __restrict__ relX,
                               const float* __restrict__ did,
                               const float* __restrict__ rid,
                               const float* __restrict__ domout,
                               float* __restrict__ fo, float* __restrict__ bo,
                               bf16* __restrict__ foh, bf16* __restrict__ fol,
                               bf16* __restrict__ boh, bf16* __restrict__ bol) {
    int bs = blockIdx.x;
    int b = bs >> 9;
    int d = threadIdx.x;
    __shared__ float sdi[NDOM], sri[NDOM];
    if (threadIdx.x < NDOM) sdi[threadIdx.x] = did[(size_t)bs * NDOM + threadIdx.x];
    else if (threadIdx.x < 2 * NDOM) sri[threadIdx.x - NDOM] = rid[(size_t)bs * NDOM + threadIdx.x - NDOM];
    __syncthreads();
    float dsum = 0.f, rsum = 0.f;
#pragma unroll
    for (int k = 0; k < NDOM; k++) { dsum += sdi[k]; rsum += sri[k]; }
    bool dmask = (dsum == 1.0f);
    bool rmask = (rsum == 1.0f);
    size_t idx = (size_t)bs * DD + d;
    float f = dmask ? 0.f : X[idx];
    float bv = rmask ? 0.f : relX[idx];
    const float* dob = domout + (size_t)b * NDOM * DD;
#pragma unroll
    for (int k = 0; k < NDOM; k++) {
        float dv = dob[(size_t)k * DD + d];
        f += sdi[k] * dv;
        bv += sri[k] * dv;
    }
    fo[idx] = f;
    bo[idx] = bv;
    bf16 fh = __float2bfloat16(f);
    foh[idx] = fh;
    fol[idx] = __float2bfloat16(f - __bfloat162float(fh));
    bf16 bh = __float2bfloat16(bv);
    boh[idx] = bh;
    bol[idx] = __float2bfloat16(bv - __bfloat162float(bh));
}

// ================= host launcher =================
extern "C" void kernel_launch(void* const* d_in, const int* in_sizes, int n_in,
                              void* d_out, int out_size) {
    const float* adj       = (const float*)d_in[0];
    const void*  domain    = d_in[1];
    const float* domain_id = (const float*)d_in[2];
    const float* redom_id  = (const float*)d_in[3];
    const float* frontrel  = (const float*)d_in[4];
    const float* backrel   = (const float*)d_in[5];
    const float* depmap    = (const float*)d_in[6];
    const float* rel       = (const float*)d_in[7];
    const float* gcn       = (const float*)d_in[8];
    const float* W_layers  = (const float*)d_in[10];
    const float* b_layers  = (const float*)d_in[11];
    const float* prelu_a   = (const float*)d_in[12];
    const float* W_dg      = (const float*)d_in[13];
    const float* b_dg      = (const float*)d_in[14];
    const float* W_mg      = (const float*)d_in[15];
    const float* b_mg      = (const float*)d_in[16];
    const float* W_out     = (const float*)d_in[17];
    const float* b_out     = (const float*)d_in[18];

    float *X, *relX, *fo, *bo, *Pb, *delta, *FR, *BR, *pooled, *domout,
          *denom, *fadj, *badj;
    unsigned char *dom8;
    bf16 *adjh, *adjl, *relh, *rell, *relTh, *relTl, *Xh, *Xl, *Xrh, *Xrl,
         *foh, *fol, *boh, *bol, *Pfh, *Pfl, *Axh, *Axl, *outsh, *outsl,
         *frh, *frl, *brh, *brl, *wmgh, *wmgl, *wlh, *wll, *woh, *wol;
    cudaGetSymbolAddress((void**)&X, g_X);
    cudaGetSymbolAddress((void**)&relX, g_relX);
    cudaGetSymbolAddress((void**)&fo, g_fo);
    cudaGetSymbolAddress((void**)&bo, g_bo);
    cudaGetSymbolAddress((void**)&Pb, g_Pb);
    cudaGetSymbolAddress((void**)&delta, g_delta);
    cudaGetSymbolAddress((void**)&FR, g_FR);
    cudaGetSymbolAddress((void**)&BR, g_BR);
    cudaGetSymbolAddress((void**)&pooled, g_pooled);
    cudaGetSymbolAddress((void**)&domout, g_domout);
    cudaGetSymbolAddress((void**)&denom, g_denom);
    cudaGetSymbolAddress((void**)&fadj, g_fadj);
    cudaGetSymbolAddress((void**)&badj, g_badj);
    cudaGetSymbolAddress((void**)&dom8, g_dom8);
    cudaGetSymbolAddress((void**)&adjh, g_adjh);   cudaGetSymbolAddress((void**)&adjl, g_adjl);
    cudaGetSymbolAddress((void**)&relh, g_relh);   cudaGetSymbolAddress((void**)&rell, g_rell);
    cudaGetSymbolAddress((void**)&relTh, g_relTh); cudaGetSymbolAddress((void**)&relTl, g_relTl);
    cudaGetSymbolAddress((void**)&Xh, g_Xh);       cudaGetSymbolAddress((void**)&Xl, g_Xl);
    cudaGetSymbolAddress((void**)&Xrh, g_Xrh);     cudaGetSymbolAddress((void**)&Xrl, g_Xrl);
    cudaGetSymbolAddress((void**)&foh, g_foh);     cudaGetSymbolAddress((void**)&fol, g_fol);
    cudaGetSymbolAddress((void**)&boh, g_boh);     cudaGetSymbolAddress((void**)&bol, g_bol);
    cudaGetSymbolAddress((void**)&Pfh, g_Pfh);     cudaGetSymbolAddress((void**)&Pfl, g_Pfl);
    cudaGetSymbolAddress((void**)&Axh, g_Axh);     cudaGetSymbolAddress((void**)&Axl, g_Axl);
    cudaGetSymbolAddress((void**)&outsh, g_outsh); cudaGetSymbolAddress((void**)&outsl, g_outsl);
    cudaGetSymbolAddress((void**)&frh, g_frh);     cudaGetSymbolAddress((void**)&frl, g_frl);
    cudaGetSymbolAddress((void**)&brh, g_brh);     cudaGetSymbolAddress((void**)&brl, g_brl);
    cudaGetSymbolAddress((void**)&wmgh, g_wmgh);   cudaGetSymbolAddress((void**)&wmgl, g_wmgl);
    cudaGetSymbolAddress((void**)&wlh, g_wlh);     cudaGetSymbolAddress((void**)&wll, g_wll);
    cudaGetSymbolAddress((void**)&woh, g_woh);     cudaGetSymbolAddress((void**)&wol, g_wol);

    cudaFuncSetAttribute(hgemm<0, false>, cudaFuncAttributeMaxDynamicSharedMemorySize, SMEM_TC);
    cudaFuncSetAttribute(hgemm<1, false>, cudaFuncAttributeMaxDynamicSharedMemorySize, SMEM_TC);
    cudaFuncSetAttribute(hgemm<2, false>, cudaFuncAttributeMaxDynamicSharedMemorySize, SMEM_TC);
    cudaFuncSetAttribute(hgemm<3, false>, cudaFuncAttributeMaxDynamicSharedMemorySize, SMEM_TC);
    cudaFuncSetAttribute(hgemm<4, true >, cudaFuncAttributeMaxDynamicSharedMemorySize, SMEM_TC);
    cudaFuncSetAttribute(hgemm<5, true >, cudaFuncAttributeMaxDynamicSharedMemorySize, SMEM_TC);
    cudaFuncSetAttribute(hgemm<6, false>, cudaFuncAttributeMaxDynamicSharedMemorySize, SMEM_TC);

    const dim3 tg(DD / 128, MT / 256);    // (4, 32) = 128 CTAs
    const int TB = 256;
    const int N2 = MT * DD / 2;           // 2M float2s
    const int GB2 = (N2 + 255) / 256;

    // ---- invariant preprocessing ----
    detect_dom_fmt<<<1, 256>>>((const unsigned int*)domain);
    convert_dom<<<(MT * NDOM + 255) / 256, 256>>>(domain, dom8);
    rowstats_kernel<<<1024, 256>>>(adj, depmap, denom, fadj, badj);
    split_kernel<<<GB2, 256>>>(adj, adjh, adjl, N2);
    split_kernel<<<GB2, 256>>>(rel, relh, rell, N2);
    transpose_split<<<dim3(16, 16, 16), dim3(32, 8)>>>(rel, relTh, relTl);
    split_kernel<<<GB2, 256>>>(frontrel, frh, frl, N2);
    split_kernel<<<GB2, 256>>>(backrel, brh, brl, N2);
    split_kernel<<<(2 * DD * DD / 2 + 255) / 256, 256>>>(W_mg, wmgh, wmgl, 2 * DD * DD / 2);
    split_kernel<<<(NLAY * DD * DD / 2 + 255) / 256, 256>>>(W_layers, wlh, wll, NLAY * DD * DD / 2);
    split_kernel<<<(NLAY * DD * DD / 2 + 255) / 256, 256>>>(W_out, woh, wol, NLAY * DD * DD / 2);
    copy_split_kernel<<<GB2, 256>>>(gcn, X, Xh, Xl, N2);

    // FR = frontrel @ W_mg[D:2D] + b_mg ; BR analogous
    hgemm<0, false><<<tg, TB, SMEM_TC>>>(frh, frl, DD, wmgh + (size_t)DD * DD, wmgl + (size_t)DD * DD, DD, DD,
        FR, nullptr, nullptr, 0, nullptr, nullptr, b_mg, nullptr, nullptr, nullptr, nullptr, nullptr, nullptr, 0);
    hgemm<0, false><<<tg, TB, SMEM_TC>>>(brh, brl, DD, wmgh + (size_t)DD * DD, wmgl + (size_t)DD * DD, DD, DD,
        BR, nullptr, nullptr, 0, nullptr, nullptr, b_mg, nullptr, nullptr, nullptr, nullptr, nullptr, nullptr, 0);

    for (int l = 0; l < NLAY; l++) {
        pool_kernel<<<dim3(BB, DD / 128), 128>>>(X, dom8, pooled);
        dgate_kernel<<<dim3(BB * NDOM, DD / 128), 128>>>(pooled, W_dg, b_dg, domout);
        // relX = rel @ X     (batched)
        hgemm<4, true><<<tg, TB, SMEM_TC>>>(relh, rell, DD, Xh, Xl, DD, DD,
            relX, nullptr, nullptr, 0, nullptr, nullptr,
            nullptr, nullptr, nullptr, nullptr, nullptr, nullptr, nullptr, 0);
        buildfb_kernel<<<MT, 512>>>(X, relX, domain_id, redom_id, domout,
                                    fo, bo, foh, fol, boh, bol);
        // Pf (pair) = frontadj * sigmoid(fo @ W_mg[:D] + FR) * fo
        hgemm<1, false><<<tg, TB, SMEM_TC>>>(foh, fol, DD, wmgh, wmgl, DD, DD,
            nullptr, Pfh, Pfl, DD, nullptr, nullptr,
            nullptr, FR, nullptr, fadj, fo, nullptr, nullptr, 0);
        // Pb (fp32) = backadj * sigmoid(bo @ W_mg[:D] + BR) * bo
        hgemm<6, false><<<tg, TB, SMEM_TC>>>(boh, bol, DD, wmgh, wmgl, DD, DD,
            Pb, nullptr, nullptr, 0, nullptr, nullptr,
            nullptr, BR, nullptr, badj, bo, nullptr, nullptr, 0);
        // delta = rel^T @ Pf (batched)
        hgemm<4, true><<<tg, TB, SMEM_TC>>>(relTh, relTl, DD, Pfh, Pfl, DD, DD,
            delta, nullptr, nullptr, 0, nullptr, nullptr,
            nullptr, nullptr, nullptr, nullptr, nullptr, nullptr, nullptr, 0);
        // Xrel pair = X * rel
        mulsplit_kernel<<<GB2, 256>>>(X, rel, Xrh, Xrl, N2);
        // AxpX (pair) = adj @ Xrel + X (batched)
        hgemm<5, true><<<tg, TB, SMEM_TC>>>(adjh, adjl, DD, Xrh, Xrl, DD, DD,
            nullptr, Axh, Axl, DD, nullptr, nullptr,
            nullptr, nullptr, nullptr, nullptr, nullptr, X, nullptr, 0);
        // X = PReLU((AxpX @ W_l + 2b + delta + Pb)/denom) -> X fp32 + X pair + outs slot pair
        hgemm<2, false><<<tg, TB, SMEM_TC>>>(Axh, Axl, DD,
            wlh + (size_t)l * DD * DD, wll + (size_t)l * DD * DD, DD, DD,
            X, Xh, Xl, DD, outsh + (size_t)l * DD, outsl + (size_t)l * DD,
            b_layers + (size_t)l * DD, delta, Pb, denom, nullptr, nullptr, prelu_a, l);
    }
    // out = outs @ W_out + b_out + gcn
    hgemm<3, false><<<tg, TB, SMEM_TC>>>(outsh, outsl, NLAY * DD, woh, wol, DD, NLAY * DD,
        (float*)d_out, nullptr, nullptr, 0, nullptr, nullptr,
        b_out, gcn, nullptr, nullptr, nullptr, nullptr, nullptr, 0);
}

// round 7
// speedup vs baseline: 2.2772x; 1.1941x over previous
#include <cuda_runtime.h>
#include <cuda_fp16.h>
#include <math.h>
#include <stdint.h>

#define BB 16
#define SD 512
#define DD 512
#define MT (BB*SD)          // 8192
#define MTDD (MT*DD)        // 4194304
#define NLAY 3
#define NDOM 8

typedef __half fp16;

// ---------------- scratch (device globals; no allocation) ----------------
__device__ float g_X[MTDD];
__device__ float g_delta[MTDD];
__device__ float g_FRBR[2*MTDD];
__device__ float g_pooled[BB*NDOM*DD];
__device__ float g_domout[BB*NDOM*DD];
__device__ float g_denom[MT];
__device__ float g_fbadj[2*MT];
__device__ unsigned char g_dom8[MT*NDOM];
__device__ int g_domfmt;

// fp16 planes
__device__ fp16 g_adjh[MTDD],  g_adjl[MTDD];
__device__ fp16 g_relh[MTDD],  g_rell[MTDD];
__device__ fp16 g_relTh[MTDD], g_relTl[MTDD];
__device__ fp16 g_Xh16[MTDD];           // X single (B of relX)
__device__ fp16 g_Xr16[MTDD];           // X*rel single (B of AxpX)
__device__ fp16 g_foboh[2*MTDD], g_fobol[2*MTDD];   // fo at 0, bo at MTDD (A of gates)
__device__ fp16 g_P16[2*MTDD];          // Pf at 0 (B of delta), Pb at MTDD (add in EPI2)
__device__ fp16 g_Axh[MTDD],   g_Axl[MTDD];
__device__ fp16 g_outsh[MT*NLAY*DD], g_outsl[MT*NLAY*DD];
__device__ fp16 g_frbrh[2*MTDD], g_frbrl[2*MTDD];
__device__ fp16 g_wmg1[DD*DD];          // W_mg[:D] single
__device__ fp16 g_wmg2[DD*DD];          // W_mg[D:2D] single
__device__ fp16 g_wlh[NLAY*DD*DD], g_wll[NLAY*DD*DD];
__device__ fp16 g_woh[NLAY*DD*DD], g_wol[NLAY*DD*DD];

__device__ __forceinline__ float sigf(float x) { return 1.f / (1.f + expf(-x)); }

// fp32 pair -> packed fp16x2 hi word + lo word
__device__ __forceinline__ void split2h(float x, float y, uint32_t& h, uint32_t& lo) {
    fp16 hx = __float2half_rn(x), hy = __float2half_rn(y);
    float rx = x - __half2float(hx), ry = y - __half2float(hy);
    fp16 lx = __float2half_rn(rx), ly = __float2half_rn(ry);
    h  = ((uint32_t)__half_as_ushort(hy) << 16) | (uint32_t)__half_as_ushort(hx);
    lo = ((uint32_t)__half_as_ushort(ly) << 16) | (uint32_t)__half_as_ushort(lx);
}
__device__ __forceinline__ uint32_t pack2h(float x, float y) {
    return ((uint32_t)__half_as_ushort(__float2half_rn(y)) << 16) |
           (uint32_t)__half_as_ushort(__float2half_rn(x));
}

__device__ __forceinline__ uint32_t smem_u32(const void* p) {
    uint32_t a;
    asm("{ .reg .u64 t; cvta.to.shared.u64 t, %1; cvt.u32.u64 %0, t; }" : "=r"(a) : "l"(p));
    return a;
}
__device__ __forceinline__ void cpa16(uint32_t dst, const void* src) {
    asm volatile("{ .reg .u64 g; cvta.to.global.u64 g, %1; cp.async.cg.shared.global [%0], [g], 16; }"
                 :: "r"(dst), "l"(src) : "memory");
}
#define CP_COMMIT() asm volatile("cp.async.commit_group;" ::: "memory")
#define CP_WAIT1()  asm volatile("cp.async.wait_group 1;" ::: "memory")
#define CP_WAIT0()  asm volatile("cp.async.wait_group 0;" ::: "memory")

#define LDSM4(r0, r1, r2, r3, a) \
    asm volatile("ldmatrix.sync.aligned.m8n8.x4.shared.b16 {%0,%1,%2,%3}, [%4];" \
        : "=r"(r0), "=r"(r1), "=r"(r2), "=r"(r3) : "r"(a))
#define LDSM4T(r0, r1, r2, r3, a) \
    asm volatile("ldmatrix.sync.aligned.m8n8.x4.trans.shared.b16 {%0,%1,%2,%3}, [%4];" \
        : "=r"(r0), "=r"(r1), "=r"(r2), "=r"(r3) : "r"(a))
#define MMAH(acc, a, b) \
    asm volatile("mma.sync.aligned.m16n8k16.row.col.f32.f16.f16.f32 " \
        "{%0,%1,%2,%3}, {%4,%5,%6,%7}, {%8,%9}, {%0,%1,%2,%3};" \
        : "+f"((acc)[0]), "+f"((acc)[1]), "+f"((acc)[2]), "+f"((acc)[3]) \
        : "r"((a)[0]), "r"((a)[1]), "r"((a)[2]), "r"((a)[3]), "r"((b)[0]), "r"((b)[1]))

// one-hot row scan: returns hot index if sum==1 else -1
__device__ __forceinline__ int oh_idx(const float* __restrict__ p) {
    float s = 0.f; int k = -1;
#pragma unroll
    for (int i = 0; i < 8; i++) { float t = p[i]; s += t; if (t == 1.f) k = i; }
    return (s == 1.f) ? k : -1;
}

// ================= fp16 split GEMM =================
// CTA 256m x 128n, 8 warps (4m x 2n), warp tile 64x64.
// PASSES=2: C = Ah*Bh + Al*Bh   PASSES=3: + Ah*Bl
// EPI 0: C = acc + bias
// EPI 7: relX epilogue: fo/bo build (X, domout, did, rid) -> fobo fp16 pairs
// EPI 1: P16 = fp16(rowv * sig(acc + add1) * (mulh+mull))
// EPI 4: C = acc
// EPI 5: Ax pair = split(acc + Cadd)
// EPI 2: t = (acc + 2*bias + add1 + add16)/rowv; prelu -> C(X fp32), Xh16, Xr16(=t*relf), outs pair
// EPI 3: C = acc + bias + add1
#define APITCH 80
#define BPITCH 272
#define A_PL (256*APITCH)            // 20480
#define B_PL (32*BPITCH)             // 8704

template<int EPI, int PASSES, bool BATCHB>
__global__ void __launch_bounds__(256, 1) hgemm(
    const fp16* __restrict__ Ah, const fp16* __restrict__ Al, int lda,
    const fp16* __restrict__ Bh, const fp16* __restrict__ Bl, int ldb, int K,
    float* __restrict__ C,
    fp16* __restrict__ O16a, fp16* __restrict__ O16b,
    fp16* __restrict__ O16c, fp16* __restrict__ O16d,
    const float* __restrict__ Xf, const float* __restrict__ domout,
    const float* __restrict__ did, const float* __restrict__ rid,
    const float* __restrict__ bias, const float* __restrict__ add1,
    const fp16* __restrict__ add16, const float* __restrict__ rowv,
    const fp16* __restrict__ mulh, const fp16* __restrict__ mull,
    const float* __restrict__ Cadd, const float* __restrict__ relf,
    const float* __restrict__ pa, int l)
{
    constexpr int BPLANES = (PASSES == 3) ? 2 : 1;
    constexpr int STG = 2 * A_PL + BPLANES * B_PL;
    extern __shared__ __align__(128) char smp[];
    const uint32_t sb = smem_u32(smp);
    const int t = threadIdx.x;
    const int wid = t >> 5;
    const int lane = t & 31;
    const int m0 = blockIdx.y * 256;
    const int n0 = blockIdx.x * 128;
    const int KB = K >> 5;
    const int wm = (wid & 3) * 64;
    const int wn = (wid >> 2) * 64;
    const size_t boff = BATCHB ? (size_t)(m0 >> 9) * 512 * ldb : 0;

    float acc[4][8][4];
#pragma unroll
    for (int im = 0; im < 4; im++)
#pragma unroll
        for (int in = 0; in < 8; in++)
#pragma unroll
            for (int c = 0; c < 4; c++) acc[im][in][c] = 0.f;

    const int q = lane >> 3, r = lane & 7;
    const int arow = (q & 1) * 8 + r;
    const int acol = (q >> 1) * 8;
    const int bkrow = (q & 1) * 8 + r;
    const int bq8 = (q >> 1) * 8;

    auto stage_cp = [&](int st, int kb) {
        const int k0 = kb * 32;
        const uint32_t sa = sb + (uint32_t)st * STG;
#pragma unroll
        for (int i = 0; i < 4; i++) {
            int c = t + i * 256;
            int row = c >> 2, kc = c & 3;
            size_t go = (size_t)(m0 + row) * lda + k0 + kc * 8;
            uint32_t so = (uint32_t)row * APITCH + kc * 16;
            cpa16(sa + so, Ah + go);
            cpa16(sa + A_PL + so, Al + go);
        }
#pragma unroll
        for (int i = 0; i < 2; i++) {
            int c = t + i * 256;
            int row = c >> 4, nc = c & 15;
            size_t go = boff + (size_t)(k0 + row) * ldb + n0 + nc * 8;
            uint32_t so = (uint32_t)row * BPITCH + nc * 16;
            cpa16(sa + 2 * A_PL + so, Bh + go);
            if (PASSES == 3) cpa16(sa + 2 * A_PL + B_PL + so, Bl + go);
        }
        CP_COMMIT();
    };

    auto compute = [&](int st) {
        const uint32_t aH = sb + (uint32_t)st * STG;
        const uint32_t aL = aH + A_PL;
        const uint32_t bHp = aH + 2 * A_PL;
        const uint32_t bLp = bHp + B_PL;
#pragma unroll
        for (int ks = 0; ks < 2; ks++) {
            const int k16 = ks * 16;
            uint32_t ah[4][4], al[4][4], bb[8][2];
#pragma unroll
            for (int im = 0; im < 4; im++) {
                uint32_t off = (uint32_t)(wm + im * 16 + arow) * APITCH + (k16 + acol) * 2;
                LDSM4(ah[im][0], ah[im][1], ah[im][2], ah[im][3], aH + off);
                LDSM4(al[im][0], al[im][1], al[im][2], al[im][3], aL + off);
            }
#pragma unroll
            for (int j2 = 0; j2 < 4; j2++) {
                uint32_t off = (uint32_t)(k16 + bkrow) * BPITCH + (wn + bq8 + j2 * 16) * 2;
                LDSM4T(bb[j2 * 2][0], bb[j2 * 2][1], bb[j2 * 2 + 1][0], bb[j2 * 2 + 1][1], bHp + off);
            }
#pragma unroll
            for (int im = 0; im < 4; im++)
#pragma unroll
                for (int in = 0; in < 8; in++)
                    MMAH(acc[im][in], ah[im], bb[in]);
#pragma unroll
            for (int im = 0; im < 4; im++)
#pragma unroll
                for (int in = 0; in < 8; in++)
                    MMAH(acc[im][in], al[im], bb[in]);
            if (PASSES == 3) {
#pragma unroll
                for (int j2 = 0; j2 < 4; j2++) {
                    uint32_t off = (uint32_t)(k16 + bkrow) * BPITCH + (wn + bq8 + j2 * 16) * 2;
                    LDSM4T(bb[j2 * 2][0], bb[j2 * 2][1], bb[j2 * 2 + 1][0], bb[j2 * 2 + 1][1], bLp + off);
                }
#pragma unroll
                for (int im = 0; im < 4; im++)
#pragma unroll
                    for (int in = 0; in < 8; in++)
                        MMAH(acc[im][in], ah[im], bb[in]);
            }
        }
    };

    stage_cp(0, 0);
    stage_cp(1, 1);
    for (int kb = 0; kb < KB; kb++) {
        if (kb + 2 < KB) { CP_WAIT1(); } else { CP_WAIT0(); }
        __syncthreads();
        if (kb + 2 < KB) stage_cp((kb + 2) % 3, kb + 2);
        compute(kb % 3);
    }

    // ---------------- epilogue ----------------
    const int lr = lane >> 2;
    const int lc = (lane & 3) * 2;
    float al_p = 0.f;
    if (EPI == 2) al_p = pa[l];
    const int bofs = (EPI == 7) ? (m0 >> 9) * NDOM * 512 : 0;

#pragma unroll
    for (int im = 0; im < 4; im++) {
        const int gm0 = m0 + wm + im * 16 + lr;
        const int gm1 = gm0 + 8;
        float rv0 = 1.f, rv1 = 1.f;
        if (EPI == 1) { rv0 = rowv[gm0]; rv1 = rowv[gm1]; }
        if (EPI == 2) { rv0 = 1.f / rowv[gm0]; rv1 = 1.f / rowv[gm1]; }
        int dk0 = 0, dk1 = 0, rk0 = 0, rk1 = 0;
        if (EPI == 7) {
            dk0 = oh_idx(did + (size_t)gm0 * 8);
            dk1 = oh_idx(did + (size_t)gm1 * 8);
            rk0 = oh_idx(rid + (size_t)gm0 * 8);
            rk1 = oh_idx(rid + (size_t)gm1 * 8);
        }
#pragma unroll
        for (int in = 0; in < 8; in++) {
            const int gc = n0 + wn + in * 8 + lc;
            float v[4] = {acc[im][in][0], acc[im][in][1], acc[im][in][2], acc[im][in][3]};
            const size_t i0 = (size_t)gm0 * 512 + gc;
            const size_t i1 = (size_t)gm1 * 512 + gc;
            if (EPI == 0) {
                v[0] += bias[gc]; v[1] += bias[gc + 1];
                v[2] += bias[gc]; v[3] += bias[gc + 1];
                *(float2*)(C + i0) = make_float2(v[0], v[1]);
                *(float2*)(C + i1) = make_float2(v[2], v[3]);
            } else if (EPI == 7) {
                // fo
                float2 x0 = *(const float2*)(Xf + i0);
                float2 x1 = *(const float2*)(Xf + i1);
                float2 dd0 = (dk0 >= 0) ? *(const float2*)(domout + (size_t)(bofs + dk0 * 512) + gc) : make_float2(0.f, 0.f);
                float2 dd1 = (dk1 >= 0) ? *(const float2*)(domout + (size_t)(bofs + dk1 * 512) + gc) : make_float2(0.f, 0.f);
                float f00 = dk0 >= 0 ? dd0.x : x0.x, f01 = dk0 >= 0 ? dd0.y : x0.y;
                float f10 = dk1 >= 0 ? dd1.x : x1.x, f11 = dk1 >= 0 ? dd1.y : x1.y;
                uint32_t h, lo;
                split2h(f00, f01, h, lo);
                *(uint32_t*)(O16a + i0) = h; *(uint32_t*)(O16b + i0) = lo;
                split2h(f10, f11, h, lo);
                *(uint32_t*)(O16a + i1) = h; *(uint32_t*)(O16b + i1) = lo;
                // bo (uses acc = relX)
                float2 rr0 = (rk0 >= 0) ? *(const float2*)(domout + (size_t)(bofs + rk0 * 512) + gc) : make_float2(0.f, 0.f);
                float2 rr1 = (rk1 >= 0) ? *(const float2*)(domout + (size_t)(bofs + rk1 * 512) + gc) : make_float2(0.f, 0.f);
                float b00 = rk0 >= 0 ? rr0.x : v[0], b01 = rk0 >= 0 ? rr0.y : v[1];
                float b10 = rk1 >= 0 ? rr1.x : v[2], b11 = rk1 >= 0 ? rr1.y : v[3];
                split2h(b00, b01, h, lo);
                *(uint32_t*)(O16c + i0) = h; *(uint32_t*)(O16d + i0) = lo;
                split2h(b10, b11, h, lo);
                *(uint32_t*)(O16c + i1) = h; *(uint32_t*)(O16d + i1) = lo;
            } else if (EPI == 1) {
                float2 a0 = *(const float2*)(add1 + i0);
                float2 a1 = *(const float2*)(add1 + i1);
                uint32_t mh0 = *(const uint32_t*)(mulh + i0), ml0 = *(const uint32_t*)(mull + i0);
                uint32_t mh1 = *(const uint32_t*)(mulh + i1), ml1 = *(const uint32_t*)(mull + i1);
                float m00 = __half2float(__ushort_as_half(mh0 & 0xffff)) + __half2float(__ushort_as_half(ml0 & 0xffff));
                float m01 = __half2float(__ushort_as_half(mh0 >> 16)) + __half2float(__ushort_as_half(ml0 >> 16));
                float m10 = __half2float(__ushort_as_half(mh1 & 0xffff)) + __half2float(__ushort_as_half(ml1 & 0xffff));
                float m11 = __half2float(__ushort_as_half(mh1 >> 16)) + __half2float(__ushort_as_half(ml1 >> 16));
                v[0] = rv0 * sigf(v[0] + a0.x) * m00;
                v[1] = rv0 * sigf(v[1] + a0.y) * m01;
                v[2] = rv1 * sigf(v[2] + a1.x) * m10;
                v[3] = rv1 * sigf(v[3] + a1.y) * m11;
                *(uint32_t*)(O16a + i0) = pack2h(v[0], v[1]);
                *(uint32_t*)(O16a + i1) = pack2h(v[2], v[3]);
            } else if (EPI == 4) {
                *(float2*)(C + i0) = make_float2(v[0], v[1]);
                *(float2*)(C + i1) = make_float2(v[2], v[3]);
            } else if (EPI == 5) {
                float2 a0 = *(const float2*)(Cadd + i0);
                float2 a1 = *(const float2*)(Cadd + i1);
                v[0] += a0.x; v[1] += a0.y; v[2] += a1.x; v[3] += a1.y;
                uint32_t h, lo;
                split2h(v[0], v[1], h, lo);
                *(uint32_t*)(O16a + i0) = h; *(uint32_t*)(O16b + i0) = lo;
                split2h(v[2], v[3], h, lo);
                *(uint32_t*)(O16a + i1) = h; *(uint32_t*)(O16b + i1) = lo;
            } else if (EPI == 2) {
                float b0 = 2.f * bias[gc], b1 = 2.f * bias[gc + 1];
                float2 a0 = *(const float2*)(add1 + i0);
                float2 a1 = *(const float2*)(add1 + i1);
                uint32_t p0 = *(const uint32_t*)(add16 + i0);
                uint32_t p1 = *(const uint32_t*)(add16 + i1);
                float t0 = (v[0] + b0 + a0.x + __half2float(__ushort_as_half(p0 & 0xffff))) * rv0;
                float t1 = (v[1] + b1 + a0.y + __half2float(__ushort_as_half(p0 >> 16))) * rv0;
                float t2 = (v[2] + b0 + a1.x + __half2float(__ushort_as_half(p1 & 0xffff))) * rv1;
                float t3 = (v[3] + b1 + a1.y + __half2float(__ushort_as_half(p1 >> 16))) * rv1;
                v[0] = t0 >= 0.f ? t0 : al_p * t0;
                v[1] = t1 >= 0.f ? t1 : al_p * t1;
                v[2] = t2 >= 0.f ? t2 : al_p * t2;
                v[3] = t3 >= 0.f ? t3 : al_p * t3;
                *(float2*)(C + i0) = make_float2(v[0], v[1]);
                *(float2*)(C + i1) = make_float2(v[2], v[3]);
                *(uint32_t*)(O16a + i0) = pack2h(v[0], v[1]);
                *(uint32_t*)(O16a + i1) = pack2h(v[2], v[3]);
                float2 re0 = *(const float2*)(relf + i0);
                float2 re1 = *(const float2*)(relf + i1);
                *(uint32_t*)(O16b + i0) = pack2h(v[0] * re0.x, v[1] * re0.y);
                *(uint32_t*)(O16b + i1) = pack2h(v[2] * re1.x, v[3] * re1.y);
                uint32_t h, lo;
                split2h(v[0], v[1], h, lo);
                *(uint32_t*)(O16c + (size_t)gm0 * (NLAY * DD) + gc) = h;
                *(uint32_t*)(O16d + (size_t)gm0 * (NLAY * DD) + gc) = lo;
                split2h(v[2], v[3], h, lo);
                *(uint32_t*)(O16c + (size_t)gm1 * (NLAY * DD) + gc) = h;
                *(uint32_t*)(O16d + (size_t)gm1 * (NLAY * DD) + gc) = lo;
            } else if (EPI == 3) {
                float2 a0 = *(const float2*)(add1 + i0);
                float2 a1 = *(const float2*)(add1 + i1);
                v[0] += bias[gc] + a0.x;     v[1] += bias[gc + 1] + a0.y;
                v[2] += bias[gc] + a1.x;     v[3] += bias[gc + 1] + a1.y;
                *(float2*)(C + i0) = make_float2(v[0], v[1]);
                *(float2*)(C + i1) = make_float2(v[2], v[3]);
            }
        }
    }
}

// ================= small kernels =================
__global__ void detect_dom_fmt(const unsigned int* __restrict__ w) {
    __shared__ int sf, sbt;
    if (threadIdx.x == 0) { sf = 0; sbt = 0; }
    __syncthreads();
    for (int i = threadIdx.x; i < 1024; i += 256) {
        unsigned int v = w[i];
        if (v == 0x3F800000u) atomicOr(&sf, 1);
        else if (v > 1u) atomicOr(&sbt, 1);
    }
    __syncthreads();
    if (threadIdx.x == 0) g_domfmt = sf ? 2 : (sbt ? 0 : 1);
}

__global__ void convert_dom(const void* __restrict__ dom, unsigned char* __restrict__ out) {
    int i = blockIdx.x * 256 + threadIdx.x;
    if (i >= MT * NDOM) return;
    int fmt = g_domfmt;
    unsigned char v;
    if (fmt == 0)      v = ((const unsigned char*)dom)[i] != 0;
    else if (fmt == 1) v = ((const int*)dom)[i] != 0;
    else               v = ((const float*)dom)[i] != 0.f;
    out[i] = v;
}

__global__ void rowstats_kernel(const float* __restrict__ adj,
                                const float* __restrict__ depmap,
                                float* __restrict__ denom,
                                float* __restrict__ fbadj) {
    int warp = (blockIdx.x * blockDim.x + threadIdx.x) >> 5;
    int lane = threadIdx.x & 31;
    if (warp >= MT) return;
    int b = warp >> 9;
    int s = warp & 511;
    const float* arow = adj + (size_t)(b * SD + s) * SD;
    const float* drow = depmap + (size_t)(b * SD + s) * SD;
    const float* acol = adj + (size_t)b * SD * SD + s;
    float sa = 0.f, sf = 0.f, sb = 0.f;
    for (int j = lane; j < SD; j += 32) {
        float a = arow[j];
        float dp = drow[j];
        sa += a;
        sf += a * dp;
        sb += acol[(size_t)j * SD] * dp;
    }
#pragma unroll
    for (int off = 16; off > 0; off >>= 1) {
        sa += __shfl_down_sync(0xffffffffu, sa, off);
        sf += __shfl_down_sync(0xffffffffu, sf, off);
        sb += __shfl_down_sync(0xffffffffu, sb, off);
    }
    if (lane == 0) {
        denom[warp] = sa + 1.f;
        fbadj[warp] = sf;
        fbadj[MT + warp] = sb;
    }
}

__global__ void split_pair16(const float* __restrict__ src, fp16* __restrict__ h,
                             fp16* __restrict__ lo, int n2) {
    int i = blockIdx.x * 256 + threadIdx.x;
    if (i >= n2) return;
    float2 v = ((const float2*)src)[i];
    uint32_t hw, lw;
    split2h(v.x, v.y, hw, lw);
    ((uint32_t*)h)[i] = hw;
    ((uint32_t*)lo)[i] = lw;
}

__global__ void split_single16(const float* __restrict__ src, fp16* __restrict__ h, int n2) {
    int i = blockIdx.x * 256 + threadIdx.x;
    if (i >= n2) return;
    float2 v = ((const float2*)src)[i];
    ((uint32_t*)h)[i] = pack2h(v.x, v.y);
}

// X0 = gcn (fp32 copy + fp16) ; Xr0 = gcn*rel (fp16)
__global__ void copy_split0(const float* __restrict__ gcn, const float* __restrict__ rel,
                            float* __restrict__ X, fp16* __restrict__ Xh,
                            fp16* __restrict__ Xr, int n2) {
    int i = blockIdx.x * 256 + threadIdx.x;
    if (i >= n2) return;
    float2 v = ((const float2*)gcn)[i];
    float2 rv = ((const float2*)rel)[i];
    ((float2*)X)[i] = v;
    ((uint32_t*)Xh)[i] = pack2h(v.x, v.y);
    ((uint32_t*)Xr)[i] = pack2h(v.x * rv.x, v.y * rv.y);
}

__global__ void transpose_split16(const float* __restrict__ in, fp16* __restrict__ h,
                                  fp16* __restrict__ lo) {
    __shared__ float ts[32][33];
    int b = blockIdx.z;
    int x0 = blockIdx.x * 32, y0 = blockIdx.y * 32;
    const float* ib = in + (size_t)b * 262144;
    int tx = threadIdx.x, ty = threadIdx.y;
#pragma unroll
    for (int i = 0; i < 32; i += 8)
        ts[ty + i][tx] = ib[(size_t)(y0 + ty + i) * 512 + x0 + tx];
    __syncthreads();
#pragma unroll
    for (int i = 0; i < 32; i += 8) {
        float v = ts[tx][ty + i];
        fp16 hv = __float2half_rn(v);
        size_t o = (size_t)b * 262144 + (size_t)(x0 + ty + i) * 512 + y0 + tx;
        h[o] = hv;
        lo[o] = __float2half_rn(v - __half2float(hv));
    }
}

__global__ void pool_kernel(const float* __restrict__ X,
                            const unsigned char* __restrict__ dom,
                            float* __restrict__ pooled) {
    int b = blockIdx.x;
    int d = blockIdx.y * 128 + threadIdx.x;
    float mv[NDOM];
#pragma unroll
    for (int k = 0; k < NDOM; k++) mv[k] = -3.402823466e38f;
    const float* Xb = X + (size_t)b * SD * DD;
    const unsigned long long* db = (const unsigned long long*)(dom + (size_t)b * SD * NDOM);
    for (int s = 0; s < SD; s++) {
        float x = Xb[(size_t)s * DD + d];
        unsigned long long mk = db[s];
#pragma unroll
        for (int k = 0; k < NDOM; k++) {
            float v = ((mk >> (8 * k)) & 0xffull) ? -10000.f : x;
            mv[k] = fmaxf(mv[k], v);
        }
    }
#pragma unroll
    for (int k = 0; k < NDOM; k++) pooled[((size_t)b * NDOM + k) * DD + d] = mv[k];
}

__global__ void dgate_kernel(const float* __restrict__ pooled,
                             const float* __restrict__ Wdg,
                             const float* __restrict__ bdg,
                             float* __restrict__ out) {
    int bk = blockIdx.x;
    int d = blockIdx.y * 128 + threadIdx.x;
    __shared__ float sp[DD];
    for (int e = threadIdx.x; e < DD; e += 128) sp[e] = pooled[(size_t)bk * DD + e];
    __syncthreads();
    float acc = bdg[d];
#pragma unroll 8
    for (int e = 0; e < DD; e++) acc += sp[e] * Wdg[(size_t)e * DD + d];
    out[(size_t)bk * DD + d] = sigf(acc);
}

// ================= host launcher =================
#define SM2 (3 * (2 * A_PL + B_PL))
#define SM3 (3 * (2 * A_PL + 2 * B_PL))

extern "C" void kernel_launch(void* const* d_in, const int* in_sizes, int n_in,
                              void* d_out, int out_size) {
    const float* adj       = (const float*)d_in[0];
    const void*  domain    = d_in[1];
    const float* domain_id = (const float*)d_in[2];
    const float* redom_id  = (const float*)d_in[3];
    const float* frontrel  = (const float*)d_in[4];
    const float* backrel   = (const float*)d_in[5];
    const float* depmap    = (const float*)d_in[6];
    const float* rel       = (const float*)d_in[7];
    const float* gcn       = (const float*)d_in[8];
    const float* W_layers  = (const float*)d_in[10];
    const float* b_layers  = (const float*)d_in[11];
    const float* prelu_a   = (const float*)d_in[12];
    const float* W_dg      = (const float*)d_in[13];
    const float* b_dg      = (const float*)d_in[14];
    const float* W_mg      = (const float*)d_in[15];
    const float* b_mg      = (const float*)d_in[16];
    const float* W_out     = (const float*)d_in[17];
    const float* b_out     = (const float*)d_in[18];

    float *X, *delta, *FRBR, *pooled, *domout, *denom, *fbadj;
    unsigned char *dom8;
    fp16 *adjh, *adjl, *relh, *rell, *relTh, *relTl, *Xh16, *Xr16,
         *foboh, *fobol, *P16, *Axh, *Axl, *outsh, *outsl,
         *frbrh, *frbrl, *wmg1, *wmg2, *wlh, *wll, *woh, *wol;
    cudaGetSymbolAddress((void**)&X, g_X);
    cudaGetSymbolAddress((void**)&delta, g_delta);
    cudaGetSymbolAddress((void**)&FRBR, g_FRBR);
    cudaGetSymbolAddress((void**)&pooled, g_pooled);
    cudaGetSymbolAddress((void**)&domout, g_domout);
    cudaGetSymbolAddress((void**)&denom, g_denom);
    cudaGetSymbolAddress((void**)&fbadj, g_fbadj);
    cudaGetSymbolAddress((void**)&dom8, g_dom8);
    cudaGetSymbolAddress((void**)&adjh, g_adjh);   cudaGetSymbolAddress((void**)&adjl, g_adjl);
    cudaGetSymbolAddress((void**)&relh, g_relh);   cudaGetSymbolAddress((void**)&rell, g_rell);
    cudaGetSymbolAddress((void**)&relTh, g_relTh); cudaGetSymbolAddress((void**)&relTl, g_relTl);
    cudaGetSymbolAddress((void**)&Xh16, g_Xh16);   cudaGetSymbolAddress((void**)&Xr16, g_Xr16);
    cudaGetSymbolAddress((void**)&foboh, g_foboh); cudaGetSymbolAddress((void**)&fobol, g_fobol);
    cudaGetSymbolAddress((void**)&P16, g_P16);
    cudaGetSymbolAddress((void**)&Axh, g_Axh);     cudaGetSymbolAddress((void**)&Axl, g_Axl);
    cudaGetSymbolAddress((void**)&outsh, g_outsh); cudaGetSymbolAddress((void**)&outsl, g_outsl);
    cudaGetSymbolAddress((void**)&frbrh, g_frbrh); cudaGetSymbolAddress((void**)&frbrl, g_frbrl);
    cudaGetSymbolAddress((void**)&wmg1, g_wmg1);   cudaGetSymbolAddress((void**)&wmg2, g_wmg2);
    cudaGetSymbolAddress((void**)&wlh, g_wlh);     cudaGetSymbolAddress((void**)&wll, g_wll);
    cudaGetSymbolAddress((void**)&woh, g_woh);     cudaGetSymbolAddress((void**)&wol, g_wol);

    cudaFuncSetAttribute(hgemm<0, 2, false>, cudaFuncAttributeMaxDynamicSharedMemorySize, SM2);
    cudaFuncSetAttribute(hgemm<7, 2, true >, cudaFuncAttributeMaxDynamicSharedMemorySize, SM2);
    cudaFuncSetAttribute(hgemm<1, 2, false>, cudaFuncAttributeMaxDynamicSharedMemorySize, SM2);
    cudaFuncSetAttribute(hgemm<4, 2, true >, cudaFuncAttributeMaxDynamicSharedMemorySize, SM2);
    cudaFuncSetAttribute(hgemm<5, 2, true >, cudaFuncAttributeMaxDynamicSharedMemorySize, SM2);
    cudaFuncSetAttribute(hgemm<2, 3, false>, cudaFuncAttributeMaxDynamicSharedMemorySize, SM3);
    cudaFuncSetAttribute(hgemm<3, 3, false>, cudaFuncAttributeMaxDynamicSharedMemorySize, SM3);

    const dim3 tg32(4, 32);
    const dim3 tg64(4, 64);
    const int TB = 256;
    const int N2 = MTDD / 2;
    const int GB2 = (N2 + 255) / 256;
    const int W2 = (DD * DD / 2 + 255) / 256;
    const int W32 = (NLAY * DD * DD / 2 + 255) / 256;

    // launches 1-3 (deps of the profiled hgemm)
    split_pair16<<<GB2, 256>>>(frontrel, frbrh, frbrl, N2);
    split_pair16<<<GB2, 256>>>(backrel, frbrh + MTDD, frbrl + MTDD, N2);
    split_single16<<<W2, 256>>>(W_mg + (size_t)DD * DD, wmg2, DD * DD / 2);
    // launch 4: PROFILED — merged FR/BR GEMM
    hgemm<0, 2, false><<<tg64, TB, SM2>>>(frbrh, frbrl, DD, wmg2, nullptr, DD, DD,
        FRBR, nullptr, nullptr, nullptr, nullptr, nullptr, nullptr, nullptr, nullptr,
        b_mg, nullptr, nullptr, nullptr, nullptr, nullptr, nullptr, nullptr, nullptr, 0);

    // remaining invariant prep
    detect_dom_fmt<<<1, 256>>>((const unsigned int*)domain);
    convert_dom<<<(MT * NDOM + 255) / 256, 256>>>(domain, dom8);
    rowstats_kernel<<<1024, 256>>>(adj, depmap, denom, fbadj);
    split_pair16<<<GB2, 256>>>(adj, adjh, adjl, N2);
    split_pair16<<<GB2, 256>>>(rel, relh, rell, N2);
    transpose_split16<<<dim3(16, 16, 16), dim3(32, 8)>>>(rel, relTh, relTl);
    split_single16<<<W2, 256>>>(W_mg, wmg1, DD * DD / 2);
    split_pair16<<<W32, 256>>>(W_layers, wlh, wll, NLAY * DD * DD / 2);
    split_pair16<<<W32, 256>>>(W_out, woh, wol, NLAY * DD * DD / 2);
    copy_split0<<<GB2, 256>>>(gcn, rel, X, Xh16, Xr16, N2);

    for (int l = 0; l < NLAY; l++) {
        pool_kernel<<<dim3(BB, DD / 128), 128>>>(X, dom8, pooled);
        dgate_kernel<<<dim3(BB * NDOM, DD / 128), 128>>>(pooled, W_dg, b_dg, domout);
        // relX GEMM + fused fo/bo build
        hgemm<7, 2, true><<<tg32, TB, SM2>>>(relh, rell, DD, Xh16, nullptr, DD, DD,
            nullptr, foboh, fobol, foboh + MTDD, fobol + MTDD,
            X, domout, domain_id, redom_id,
            nullptr, nullptr, nullptr, nullptr, nullptr, nullptr, nullptr, nullptr, nullptr, 0);
        // merged gates: P16[0:MTDD)=Pf, [MTDD:)=Pb
        hgemm<1, 2, false><<<tg64, TB, SM2>>>(foboh, fobol, DD, wmg1, nullptr, DD, DD,
            nullptr, P16, nullptr, nullptr, nullptr, nullptr, nullptr, nullptr, nullptr,
            nullptr, FRBR, nullptr, fbadj, foboh, fobol, nullptr, nullptr, nullptr, 0);
        // delta = relT @ Pf
        hgemm<4, 2, true><<<tg32, TB, SM2>>>(relTh, relTl, DD, P16, nullptr, DD, DD,
            delta, nullptr, nullptr, nullptr, nullptr, nullptr, nullptr, nullptr, nullptr,
            nullptr, nullptr, nullptr, nullptr, nullptr, nullptr, nullptr, nullptr, nullptr, 0);
        // AxpX = adj @ Xr + X  -> pair
        hgemm<5, 2, true><<<tg32, TB, SM2>>>(adjh, adjl, DD, Xr16, nullptr, DD, DD,
            nullptr, Axh, Axl, nullptr, nullptr, nullptr, nullptr, nullptr, nullptr,
            nullptr, nullptr, nullptr, nullptr, nullptr, nullptr, X, nullptr, nullptr, 0);
        // layer update (3-pass weights)
        hgemm<2, 3, false><<<tg32, TB, SM3>>>(Axh, Axl, DD,
            wlh + (size_t)l * DD * DD, wll + (size_t)l * DD * DD, DD, DD,
            X, Xh16, Xr16, outsh + (size_t)l * DD, outsl + (size_t)l * DD,
            nullptr, nullptr, nullptr, nullptr,
            b_layers + (size_t)l * DD, delta, P16 + MTDD, denom,
            nullptr, nullptr, nullptr, rel, prelu_a, l);
    }
    // final projection (3-pass weights)
    hgemm<3, 3, false><<<tg32, TB, SM3>>>(outsh, outsl, NLAY * DD, woh, wol, DD, NLAY * DD,
        (float*)d_out, nullptr, nullptr, nullptr, nullptr, nullptr, nullptr, nullptr, nullptr,
        b_out, gcn, nullptr, nullptr, nullptr, nullptr, nullptr, nullptr, nullptr, 0);
}

// round 8
// speedup vs baseline: 2.3346x; 1.0252x over previous
#include <cuda_runtime.h>
#include <cuda_fp16.h>
#include <math.h>
#include <stdint.h>

#define BB 16
#define SD 512
#define DD 512
#define MT (BB*SD)          // 8192
#define MTDD (MT*DD)        // 4194304
#define NLAY 3
#define NDOM 8

typedef __half fp16;

// ---------------- scratch (device globals; no allocation) ----------------
__device__ float g_X[MTDD];
__device__ float g_delta[MTDD];
__device__ float g_FRBR[2*MTDD];
__device__ float g_pooled[BB*NDOM*DD];
__device__ float g_domout[BB*NDOM*DD];
__device__ float g_denom[MT];
__device__ float g_fbadj[2*MT];
__device__ unsigned char g_dom8[MT*NDOM];
__device__ int g_domfmt;

// fp16 planes
__device__ fp16 g_adjh[MTDD],  g_adjl[MTDD];
__device__ fp16 g_relh[MTDD],  g_rell[MTDD];
__device__ fp16 g_relTh[MTDD], g_relTl[MTDD];
__device__ fp16 g_Xh16[MTDD];
__device__ fp16 g_Xr16[MTDD];
__device__ fp16 g_foboh[2*MTDD], g_fobol[2*MTDD];
__device__ fp16 g_P16[2*MTDD];
__device__ fp16 g_Axh[MTDD],   g_Axl[MTDD];
__device__ fp16 g_outsh[MT*NLAY*DD], g_outsl[MT*NLAY*DD];
__device__ fp16 g_frbrh[2*MTDD], g_frbrl[2*MTDD];
__device__ fp16 g_wmg1[DD*DD];
__device__ fp16 g_wmg2[DD*DD];
__device__ fp16 g_wlh[NLAY*DD*DD], g_wll[NLAY*DD*DD];
__device__ fp16 g_woh[NLAY*DD*DD], g_wol[NLAY*DD*DD];

__device__ __forceinline__ float sigf(float x) { return 1.f / (1.f + expf(-x)); }

__device__ __forceinline__ void split2h(float x, float y, uint32_t& h, uint32_t& lo) {
    fp16 hx = __float2half_rn(x), hy = __float2half_rn(y);
    float rx = x - __half2float(hx), ry = y - __half2float(hy);
    fp16 lx = __float2half_rn(rx), ly = __float2half_rn(ry);
    h  = ((uint32_t)__half_as_ushort(hy) << 16) | (uint32_t)__half_as_ushort(hx);
    lo = ((uint32_t)__half_as_ushort(ly) << 16) | (uint32_t)__half_as_ushort(lx);
}
__device__ __forceinline__ uint32_t pack2h(float x, float y) {
    return ((uint32_t)__half_as_ushort(__float2half_rn(y)) << 16) |
           (uint32_t)__half_as_ushort(__float2half_rn(x));
}

__device__ __forceinline__ uint32_t smem_u32(const void* p) {
    uint32_t a;
    asm("{ .reg .u64 t; cvta.to.shared.u64 t, %1; cvt.u32.u64 %0, t; }" : "=r"(a) : "l"(p));
    return a;
}
__device__ __forceinline__ void cpa16(uint32_t dst, const void* src) {
    asm volatile("{ .reg .u64 g; cvta.to.global.u64 g, %1; cp.async.cg.shared.global [%0], [g], 16; }"
                 :: "r"(dst), "l"(src) : "memory");
}
#define CP_COMMIT() asm volatile("cp.async.commit_group;" ::: "memory")
#define CP_WAIT1()  asm volatile("cp.async.wait_group 1;" ::: "memory")
#define CP_WAIT0()  asm volatile("cp.async.wait_group 0;" ::: "memory")

#define LDSM4(r0, r1, r2, r3, a) \
    asm volatile("ldmatrix.sync.aligned.m8n8.x4.shared.b16 {%0,%1,%2,%3}, [%4];" \
        : "=r"(r0), "=r"(r1), "=r"(r2), "=r"(r3) : "r"(a))
#define LDSM4T(r0, r1, r2, r3, a) \
    asm volatile("ldmatrix.sync.aligned.m8n8.x4.trans.shared.b16 {%0,%1,%2,%3}, [%4];" \
        : "=r"(r0), "=r"(r1), "=r"(r2), "=r"(r3) : "r"(a))
#define MMAH(acc, a, b) \
    asm volatile("mma.sync.aligned.m16n8k16.row.col.f32.f16.f16.f32 " \
        "{%0,%1,%2,%3}, {%4,%5,%6,%7}, {%8,%9}, {%0,%1,%2,%3};" \
        : "+f"((acc)[0]), "+f"((acc)[1]), "+f"((acc)[2]), "+f"((acc)[3]) \
        : "r"((a)[0]), "r"((a)[1]), "r"((a)[2]), "r"((a)[3]), "r"((b)[0]), "r"((b)[1]))

__device__ __forceinline__ int oh_idx(const float* __restrict__ p) {
    float s = 0.f; int k = -1;
#pragma unroll
    for (int i = 0; i < 8; i++) { float t = p[i]; s += t; if (t == 1.f) k = i; }
    return (s == 1.f) ? k : -1;
}

// ================= fp16 split GEMM, 128x128 CTA, 2 CTAs/SM =================
// 8 warps (2m x 4n), warp tile 64x32.
// PASSES=2: C = Ah*Bh + Al*Bh   PASSES=3: + Ah*Bl
// EPI: see launcher comments.
#define APITCH 80
#define BPITCH 272
#define A_PL (128*APITCH)            // 10240
#define B_PL (32*BPITCH)             // 8704

template<int EPI, int PASSES, bool BATCHB>
__global__ void __launch_bounds__(256, 2) hgemm(
    const fp16* __restrict__ Ah, const fp16* __restrict__ Al, int lda,
    const fp16* __restrict__ Bh, const fp16* __restrict__ Bl, int ldb, int K,
    float* __restrict__ C,
    fp16* __restrict__ O16a, fp16* __restrict__ O16b,
    fp16* __restrict__ O16c, fp16* __restrict__ O16d,
    const float* __restrict__ Xf, const float* __restrict__ domout,
    const float* __restrict__ did, const float* __restrict__ rid,
    const float* __restrict__ bias, const float* __restrict__ add1,
    const fp16* __restrict__ add16, const float* __restrict__ rowv,
    const fp16* __restrict__ mulh, const fp16* __restrict__ mull,
    const float* __restrict__ Cadd, const float* __restrict__ relf,
    const float* __restrict__ pa, int l)
{
    constexpr int BPLANES = (PASSES == 3) ? 2 : 1;
    constexpr int STG = 2 * A_PL + BPLANES * B_PL;
    extern __shared__ __align__(128) char smp[];
    const uint32_t sb = smem_u32(smp);
    const int t = threadIdx.x;
    const int wid = t >> 5;
    const int lane = t & 31;
    const int m0 = blockIdx.y * 128;
    const int n0 = blockIdx.x * 128;
    const int KB = K >> 5;
    const int wm = (wid & 1) * 64;
    const int wn = (wid >> 1) * 32;
    const size_t boff = BATCHB ? (size_t)(m0 >> 9) * 512 * ldb : 0;

    float acc[4][4][4];
#pragma unroll
    for (int im = 0; im < 4; im++)
#pragma unroll
        for (int in = 0; in < 4; in++)
#pragma unroll
            for (int c = 0; c < 4; c++) acc[im][in][c] = 0.f;

    const int q = lane >> 3, r = lane & 7;
    const int arow = (q & 1) * 8 + r;
    const int acol = (q >> 1) * 8;
    const int bkrow = (q & 1) * 8 + r;
    const int bq8 = (q >> 1) * 8;

    auto stage_cp = [&](int st, int kb) {
        const int k0 = kb * 32;
        const uint32_t sa = sb + (uint32_t)st * STG;
        // A planes: 128 rows x 4 chunks = 512 chunks/plane, 2 iters
#pragma unroll
        for (int i = 0; i < 2; i++) {
            int c = t + i * 256;
            int row = c >> 2, kc = c & 3;
            size_t go = (size_t)(m0 + row) * lda + k0 + kc * 8;
            uint32_t so = (uint32_t)row * APITCH + kc * 16;
            cpa16(sa + so, Ah + go);
            cpa16(sa + A_PL + so, Al + go);
        }
        // B planes: 32 rows x 16 chunks = 512 chunks/plane, 2 iters
#pragma unroll
        for (int i = 0; i < 2; i++) {
            int c = t + i * 256;
            int row = c >> 4, nc = c & 15;
            size_t go = boff + (size_t)(k0 + row) * ldb + n0 + nc * 8;
            uint32_t so = (uint32_t)row * BPITCH + nc * 16;
            cpa16(sa + 2 * A_PL + so, Bh + go);
            if (PASSES == 3) cpa16(sa + 2 * A_PL + B_PL + so, Bl + go);
        }
        CP_COMMIT();
    };

    auto compute = [&](int st) {
        const uint32_t aH = sb + (uint32_t)st * STG;
        const uint32_t aL = aH + A_PL;
        const uint32_t bHp = aH + 2 * A_PL;
        const uint32_t bLp = bHp + B_PL;
#pragma unroll
        for (int ks = 0; ks < 2; ks++) {
            const int k16 = ks * 16;
            uint32_t ah[4][4], al[4][4], bb[4][2];
#pragma unroll
            for (int im = 0; im < 4; im++) {
                uint32_t off = (uint32_t)(wm + im * 16 + arow) * APITCH + (k16 + acol) * 2;
                LDSM4(ah[im][0], ah[im][1], ah[im][2], ah[im][3], aH + off);
                LDSM4(al[im][0], al[im][1], al[im][2], al[im][3], aL + off);
            }
#pragma unroll
            for (int j2 = 0; j2 < 2; j2++) {
                uint32_t off = (uint32_t)(k16 + bkrow) * BPITCH + (wn + bq8 + j2 * 16) * 2;
                LDSM4T(bb[j2 * 2][0], bb[j2 * 2][1], bb[j2 * 2 + 1][0], bb[j2 * 2 + 1][1], bHp + off);
            }
#pragma unroll
            for (int im = 0; im < 4; im++)
#pragma unroll
                for (int in = 0; in < 4; in++)
                    MMAH(acc[im][in], ah[im], bb[in]);
#pragma unroll
            for (int im = 0; im < 4; im++)
#pragma unroll
                for (int in = 0; in < 4; in++)
                    MMAH(acc[im][in], al[im], bb[in]);
            if (PASSES == 3) {
#pragma unroll
                for (int j2 = 0; j2 < 2; j2++) {
                    uint32_t off = (uint32_t)(k16 + bkrow) * BPITCH + (wn + bq8 + j2 * 16) * 2;
                    LDSM4T(bb[j2 * 2][0], bb[j2 * 2][1], bb[j2 * 2 + 1][0], bb[j2 * 2 + 1][1], bLp + off);
                }
#pragma unroll
                for (int im = 0; im < 4; im++)
#pragma unroll
                    for (int in = 0; in < 4; in++)
                        MMAH(acc[im][in], ah[im], bb[in]);
            }
        }
    };

    stage_cp(0, 0);
    stage_cp(1, 1);
    for (int kb = 0; kb < KB; kb++) {
        if (kb + 2 < KB) { CP_WAIT1(); } else { CP_WAIT0(); }
        __syncthreads();
        if (kb + 2 < KB) stage_cp((kb + 2) % 3, kb + 2);
        compute(kb % 3);
    }

    // ---------------- epilogue ----------------
    const int lr = lane >> 2;
    const int lc = (lane & 3) * 2;
    float al_p = 0.f;
    if (EPI == 2) al_p = pa[l];
    const int bofs = (EPI == 7) ? (m0 >> 9) * NDOM * 512 : 0;

#pragma unroll
    for (int im = 0; im < 4; im++) {
        const int gm0 = m0 + wm + im * 16 + lr;
        const int gm1 = gm0 + 8;
        float rv0 = 1.f, rv1 = 1.f;
        if (EPI == 1) { rv0 = rowv[gm0]; rv1 = rowv[gm1]; }
        if (EPI == 2) { rv0 = 1.f / rowv[gm0]; rv1 = 1.f / rowv[gm1]; }
        int dk0 = 0, dk1 = 0, rk0 = 0, rk1 = 0;
        if (EPI == 7) {
            dk0 = oh_idx(did + (size_t)gm0 * 8);
            dk1 = oh_idx(did + (size_t)gm1 * 8);
            rk0 = oh_idx(rid + (size_t)gm0 * 8);
            rk1 = oh_idx(rid + (size_t)gm1 * 8);
        }
#pragma unroll
        for (int in = 0; in < 4; in++) {
            const int gc = n0 + wn + in * 8 + lc;
            float v[4] = {acc[im][in][0], acc[im][in][1], acc[im][in][2], acc[im][in][3]};
            const size_t i0 = (size_t)gm0 * 512 + gc;
            const size_t i1 = (size_t)gm1 * 512 + gc;
            if (EPI == 0) {
                v[0] += bias[gc]; v[1] += bias[gc + 1];
                v[2] += bias[gc]; v[3] += bias[gc + 1];
                *(float2*)(C + i0) = make_float2(v[0], v[1]);
                *(float2*)(C + i1) = make_float2(v[2], v[3]);
            } else if (EPI == 7) {
                float2 x0 = *(const float2*)(Xf + i0);
                float2 x1 = *(const float2*)(Xf + i1);
                float2 dd0 = (dk0 >= 0) ? *(const float2*)(domout + (size_t)(bofs + dk0 * 512) + gc) : make_float2(0.f, 0.f);
                float2 dd1 = (dk1 >= 0) ? *(const float2*)(domout + (size_t)(bofs + dk1 * 512) + gc) : make_float2(0.f, 0.f);
                float f00 = dk0 >= 0 ? dd0.x : x0.x, f01 = dk0 >= 0 ? dd0.y : x0.y;
                float f10 = dk1 >= 0 ? dd1.x : x1.x, f11 = dk1 >= 0 ? dd1.y : x1.y;
                uint32_t h, lo;
                split2h(f00, f01, h, lo);
                *(uint32_t*)(O16a + i0) = h; *(uint32_t*)(O16b + i0) = lo;
                split2h(f10, f11, h, lo);
                *(uint32_t*)(O16a + i1) = h; *(uint32_t*)(O16b + i1) = lo;
                float2 rr0 = (rk0 >= 0) ? *(const float2*)(domout + (size_t)(bofs + rk0 * 512) + gc) : make_float2(0.f, 0.f);
                float2 rr1 = (rk1 >= 0) ? *(const float2*)(domout + (size_t)(bofs + rk1 * 512) + gc) : make_float2(0.f, 0.f);
                float b00 = rk0 >= 0 ? rr0.x : v[0], b01 = rk0 >= 0 ? rr0.y : v[1];
                float b10 = rk1 >= 0 ? rr1.x : v[2], b11 = rk1 >= 0 ? rr1.y : v[3];
                split2h(b00, b01, h, lo);
                *(uint32_t*)(O16c + i0) = h; *(uint32_t*)(O16d + i0) = lo;
                split2h(b10, b11, h, lo);
                *(uint32_t*)(O16c + i1) = h; *(uint32_t*)(O16d + i1) = lo;
            } else if (EPI == 1) {
                float2 a0 = *(const float2*)(add1 + i0);
                float2 a1 = *(const float2*)(add1 + i1);
                uint32_t mh0 = *(const uint32_t*)(mulh + i0), ml0 = *(const uint32_t*)(mull + i0);
                uint32_t mh1 = *(const uint32_t*)(mulh + i1), ml1 = *(const uint32_t*)(mull + i1);
                float m00 = __half2float(__ushort_as_half(mh0 & 0xffff)) + __half2float(__ushort_as_half(ml0 & 0xffff));
                float m01 = __half2float(__ushort_as_half(mh0 >> 16)) + __half2float(__ushort_as_half(ml0 >> 16));
                float m10 = __half2float(__ushort_as_half(mh1 & 0xffff)) + __half2float(__ushort_as_half(ml1 & 0xffff));
                float m11 = __half2float(__ushort_as_half(mh1 >> 16)) + __half2float(__ushort_as_half(ml1 >> 16));
                v[0] = rv0 * sigf(v[0] + a0.x) * m00;
                v[1] = rv0 * sigf(v[1] + a0.y) * m01;
                v[2] = rv1 * sigf(v[2] + a1.x) * m10;
                v[3] = rv1 * sigf(v[3] + a1.y) * m11;
                *(uint32_t*)(O16a + i0) = pack2h(v[0], v[1]);
                *(uint32_t*)(O16a + i1) = pack2h(v[2], v[3]);
            } else if (EPI == 4) {
                *(float2*)(C + i0) = make_float2(v[0], v[1]);
                *(float2*)(C + i1) = make_float2(v[2], v[3]);
            } else if (EPI == 5) {
                float2 a0 = *(const float2*)(Cadd + i0);
                float2 a1 = *(const float2*)(Cadd + i1);
                v[0] += a0.x; v[1] += a0.y; v[2] += a1.x; v[3] += a1.y;
                uint32_t h, lo;
                split2h(v[0], v[1], h, lo);
                *(uint32_t*)(O16a + i0) = h; *(uint32_t*)(O16b + i0) = lo;
                split2h(v[2], v[3], h, lo);
                *(uint32_t*)(O16a + i1) = h; *(uint32_t*)(O16b + i1) = lo;
            } else if (EPI == 2) {
                float b0 = 2.f * bias[gc], b1 = 2.f * bias[gc + 1];
                float2 a0 = *(const float2*)(add1 + i0);
                float2 a1 = *(const float2*)(add1 + i1);
                uint32_t p0 = *(const uint32_t*)(add16 + i0);
                uint32_t p1 = *(const uint32_t*)(add16 + i1);
                float t0 = (v[0] + b0 + a0.x + __half2float(__ushort_as_half(p0 & 0xffff))) * rv0;
                float t1 = (v[1] + b1 + a0.y + __half2float(__ushort_as_half(p0 >> 16))) * rv0;
                float t2 = (v[2] + b0 + a1.x + __half2float(__ushort_as_half(p1 & 0xffff))) * rv1;
                float t3 = (v[3] + b1 + a1.y + __half2float(__ushort_as_half(p1 >> 16))) * rv1;
                v[0] = t0 >= 0.f ? t0 : al_p * t0;
                v[1] = t1 >= 0.f ? t1 : al_p * t1;
                v[2] = t2 >= 0.f ? t2 : al_p * t2;
                v[3] = t3 >= 0.f ? t3 : al_p * t3;
                *(float2*)(C + i0) = make_float2(v[0], v[1]);
                *(float2*)(C + i1) = make_float2(v[2], v[3]);
                *(uint32_t*)(O16a + i0) = pack2h(v[0], v[1]);
                *(uint32_t*)(O16a + i1) = pack2h(v[2], v[3]);
                float2 re0 = *(const float2*)(relf + i0);
                float2 re1 = *(const float2*)(relf + i1);
                *(uint32_t*)(O16b + i0) = pack2h(v[0] * re0.x, v[1] * re0.y);
                *(uint32_t*)(O16b + i1) = pack2h(v[2] * re1.x, v[3] * re1.y);
                uint32_t h, lo;
                split2h(v[0], v[1], h, lo);
                *(uint32_t*)(O16c + (size_t)gm0 * (NLAY * DD) + gc) = h;
                *(uint32_t*)(O16d + (size_t)gm0 * (NLAY * DD) + gc) = lo;
                split2h(v[2], v[3], h, lo);
                *(uint32_t*)(O16c + (size_t)gm1 * (NLAY * DD) + gc) = h;
                *(uint32_t*)(O16d + (size_t)gm1 * (NLAY * DD) + gc) = lo;
            } else if (EPI == 3) {
                float2 a0 = *(const float2*)(add1 + i0);
                float2 a1 = *(const float2*)(add1 + i1);
                v[0] += bias[gc] + a0.x;     v[1] += bias[gc + 1] + a0.y;
                v[2] += bias[gc] + a1.x;     v[3] += bias[gc + 1] + a1.y;
                *(float2*)(C + i0) = make_float2(v[0], v[1]);
                *(float2*)(C + i1) = make_float2(v[2], v[3]);
            }
        }
    }
}

// ================= small kernels =================
__global__ void detect_dom_fmt(const unsigned int* __restrict__ w) {
    __shared__ int sf, sbt;
    if (threadIdx.x == 0) { sf = 0; sbt = 0; }
    __syncthreads();
    for (int i = threadIdx.x; i < 1024; i += 256) {
        unsigned int v = w[i];
        if (v == 0x3F800000u) atomicOr(&sf, 1);
        else if (v > 1u) atomicOr(&sbt, 1);
    }
    __syncthreads();
    if (threadIdx.x == 0) g_domfmt = sf ? 2 : (sbt ? 0 : 1);
}

__global__ void convert_dom(const void* __restrict__ dom, unsigned char* __restrict__ out) {
    int i = blockIdx.x * 256 + threadIdx.x;
    if (i >= MT * NDOM) return;
    int fmt = g_domfmt;
    unsigned char v;
    if (fmt == 0)      v = ((const unsigned char*)dom)[i] != 0;
    else if (fmt == 1) v = ((const int*)dom)[i] != 0;
    else               v = ((const float*)dom)[i] != 0.f;
    out[i] = v;
}

__global__ void rowstats_kernel(const float* __restrict__ adj,
                                const float* __restrict__ depmap,
                                float* __restrict__ denom,
                                float* __restrict__ fbadj) {
    int warp = (blockIdx.x * blockDim.x + threadIdx.x) >> 5;
    int lane = threadIdx.x & 31;
    if (warp >= MT) return;
    int b = warp >> 9;
    int s = warp & 511;
    const float* arow = adj + (size_t)(b * SD + s) * SD;
    const float* drow = depmap + (size_t)(b * SD + s) * SD;
    const float* acol = adj + (size_t)b * SD * SD + s;
    float sa = 0.f, sf = 0.f, sb = 0.f;
    for (int j = lane; j < SD; j += 32) {
        float a = arow[j];
        float dp = drow[j];
        sa += a;
        sf += a * dp;
        sb += acol[(size_t)j * SD] * dp;
    }
#pragma unroll
    for (int off = 16; off > 0; off >>= 1) {
        sa += __shfl_down_sync(0xffffffffu, sa, off);
        sf += __shfl_down_sync(0xffffffffu, sf, off);
        sb += __shfl_down_sync(0xffffffffu, sb, off);
    }
    if (lane == 0) {
        denom[warp] = sa + 1.f;
        fbadj[warp] = sf;
        fbadj[MT + warp] = sb;
    }
}

__global__ void split_pair16(const float* __restrict__ src, fp16* __restrict__ h,
                             fp16* __restrict__ lo, int n2) {
    int i = blockIdx.x * 256 + threadIdx.x;
    if (i >= n2) return;
    float2 v = ((const float2*)src)[i];
    uint32_t hw, lw;
    split2h(v.x, v.y, hw, lw);
    ((uint32_t*)h)[i] = hw;
    ((uint32_t*)lo)[i] = lw;
}

__global__ void split_single16(const float* __restrict__ src, fp16* __restrict__ h, int n2) {
    int i = blockIdx.x * 256 + threadIdx.x;
    if (i >= n2) return;
    float2 v = ((const float2*)src)[i];
    ((uint32_t*)h)[i] = pack2h(v.x, v.y);
}

__global__ void copy_split0(const float* __restrict__ gcn, const float* __restrict__ rel,
                            float* __restrict__ X, fp16* __restrict__ Xh,
                            fp16* __restrict__ Xr, int n2) {
    int i = blockIdx.x * 256 + threadIdx.x;
    if (i >= n2) return;
    float2 v = ((const float2*)gcn)[i];
    float2 rv = ((const float2*)rel)[i];
    ((float2*)X)[i] = v;
    ((uint32_t*)Xh)[i] = pack2h(v.x, v.y);
    ((uint32_t*)Xr)[i] = pack2h(v.x * rv.x, v.y * rv.y);
}

__global__ void transpose_split16(const float* __restrict__ in, fp16* __restrict__ h,
                                  fp16* __restrict__ lo) {
    __shared__ float ts[32][33];
    int b = blockIdx.z;
    int x0 = blockIdx.x * 32, y0 = blockIdx.y * 32;
    const float* ib = in + (size_t)b * 262144;
    int tx = threadIdx.x, ty = threadIdx.y;
#pragma unroll
    for (int i = 0; i < 32; i += 8)
        ts[ty + i][tx] = ib[(size_t)(y0 + ty + i) * 512 + x0 + tx];
    __syncthreads();
#pragma unroll
    for (int i = 0; i < 32; i += 8) {
        float v = ts[tx][ty + i];
        fp16 hv = __float2half_rn(v);
        size_t o = (size_t)b * 262144 + (size_t)(x0 + ty + i) * 512 + y0 + tx;
        h[o] = hv;
        lo[o] = __float2half_rn(v - __half2float(hv));
    }
}

__global__ void pool_kernel(const float* __restrict__ X,
                            const unsigned char* __restrict__ dom,
                            float* __restrict__ pooled) {
    int b = blockIdx.x;
    int d = blockIdx.y * 128 + threadIdx.x;
    float mv[NDOM];
#pragma unroll
    for (int k = 0; k < NDOM; k++) mv[k] = -3.402823466e38f;
    const float* Xb = X + (size_t)b * SD * DD;
    const unsigned long long* db = (const unsigned long long*)(dom + (size_t)b * SD * NDOM);
    for (int s = 0; s < SD; s++) {
        float x = Xb[(size_t)s * DD + d];
        unsigned long long mk = db[s];
#pragma unroll
        for (int k = 0; k < NDOM; k++) {
            float v = ((mk >> (8 * k)) & 0xffull) ? -10000.f : x;
            mv[k] = fmaxf(mv[k], v);
        }
    }
#pragma unroll
    for (int k = 0; k < NDOM; k++) pooled[((size_t)b * NDOM + k) * DD + d] = mv[k];
}

__global__ void dgate_kernel(const float* __restrict__ pooled,
                             const float* __restrict__ Wdg,
                             const float* __restrict__ bdg,
                             float* __restrict__ out) {
    int bk = blockIdx.x;
    int d = blockIdx.y * 128 + threadIdx.x;
    __shared__ float sp[DD];
    for (int e = threadIdx.x; e < DD; e += 128) sp[e] = pooled[(size_t)bk * DD + e];
    __syncthreads();
    float acc = bdg[d];
#pragma unroll 8
    for (int e = 0; e < DD; e++) acc += sp[e] * Wdg[(size_t)e * DD + d];
    out[(size_t)bk * DD + d] = sigf(acc);
}

// ================= host launcher =================
#define SM2 (3 * (2 * A_PL + B_PL))      // 87552
#define SM3 (3 * (2 * A_PL + 2 * B_PL))  // 113664

extern "C" void kernel_launch(void* const* d_in, const int* in_sizes, int n_in,
                              void* d_out, int out_size) {
    const float* adj       = (const float*)d_in[0];
    const void*  domain    = d_in[1];
    const float* domain_id = (const float*)d_in[2];
    const float* redom_id  = (const float*)d_in[3];
    const float* frontrel  = (const float*)d_in[4];
    const float* backrel   = (const float*)d_in[5];
    const float* depmap    = (const float*)d_in[6];
    const float* rel       = (const float*)d_in[7];
    const float* gcn       = (const float*)d_in[8];
    const float* W_layers  = (const float*)d_in[10];
    const float* b_layers  = (const float*)d_in[11];
    const float* prelu_a   = (const float*)d_in[12];
    const float* W_dg      = (const float*)d_in[13];
    const float* b_dg      = (const float*)d_in[14];
    const float* W_mg      = (const float*)d_in[15];
    const float* b_mg      = (const float*)d_in[16];
    const float* W_out     = (const float*)d_in[17];
    const float* b_out     = (const float*)d_in[18];

    float *X, *delta, *FRBR, *pooled, *domout, *denom, *fbadj;
    unsigned char *dom8;
    fp16 *adjh, *adjl, *relh, *rell, *relTh, *relTl, *Xh16, *Xr16,
         *foboh, *fobol, *P16, *Axh, *Axl, *outsh, *outsl,
         *frbrh, *frbrl, *wmg1, *wmg2, *wlh, *wll, *woh, *wol;
    cudaGetSymbolAddress((void**)&X, g_X);
    cudaGetSymbolAddress((void**)&delta, g_delta);
    cudaGetSymbolAddress((void**)&FRBR, g_FRBR);
    cudaGetSymbolAddress((void**)&pooled, g_pooled);
    cudaGetSymbolAddress((void**)&domout, g_domout);
    cudaGetSymbolAddress((void**)&denom, g_denom);
    cudaGetSymbolAddress((void**)&fbadj, g_fbadj);
    cudaGetSymbolAddress((void**)&dom8, g_dom8);
    cudaGetSymbolAddress((void**)&adjh, g_adjh);   cudaGetSymbolAddress((void**)&adjl, g_adjl);
    cudaGetSymbolAddress((void**)&relh, g_relh);   cudaGetSymbolAddress((void**)&rell, g_rell);
    cudaGetSymbolAddress((void**)&relTh, g_relTh); cudaGetSymbolAddress((void**)&relTl, g_relTl);
    cudaGetSymbolAddress((void**)&Xh16, g_Xh16);   cudaGetSymbolAddress((void**)&Xr16, g_Xr16);
    cudaGetSymbolAddress((void**)&foboh, g_foboh); cudaGetSymbolAddress((void**)&fobol, g_fobol);
    cudaGetSymbolAddress((void**)&P16, g_P16);
    cudaGetSymbolAddress((void**)&Axh, g_Axh);     cudaGetSymbolAddress((void**)&Axl, g_Axl);
    cudaGetSymbolAddress((void**)&outsh, g_outsh); cudaGetSymbolAddress((void**)&outsl, g_outsl);
    cudaGetSymbolAddress((void**)&frbrh, g_frbrh); cudaGetSymbolAddress((void**)&frbrl, g_frbrl);
    cudaGetSymbolAddress((void**)&wmg1, g_wmg1);   cudaGetSymbolAddress((void**)&wmg2, g_wmg2);
    cudaGetSymbolAddress((void**)&wlh, g_wlh);     cudaGetSymbolAddress((void**)&wll, g_wll);
    cudaGetSymbolAddress((void**)&woh, g_woh);     cudaGetSymbolAddress((void**)&wol, g_wol);

    cudaFuncSetAttribute(hgemm<0, 2, false>, cudaFuncAttributeMaxDynamicSharedMemorySize, SM2);
    cudaFuncSetAttribute(hgemm<7, 2, true >, cudaFuncAttributeMaxDynamicSharedMemorySize, SM2);
    cudaFuncSetAttribute(hgemm<1, 2, false>, cudaFuncAttributeMaxDynamicSharedMemorySize, SM2);
    cudaFuncSetAttribute(hgemm<4, 2, true >, cudaFuncAttributeMaxDynamicSharedMemorySize, SM2);
    cudaFuncSetAttribute(hgemm<5, 2, true >, cudaFuncAttributeMaxDynamicSharedMemorySize, SM2);
    cudaFuncSetAttribute(hgemm<2, 3, false>, cudaFuncAttributeMaxDynamicSharedMemorySize, SM3);
    cudaFuncSetAttribute(hgemm<3, 3, false>, cudaFuncAttributeMaxDynamicSharedMemorySize, SM3);

    const dim3 tgA(4, 64);     // M=8192:  256 CTAs
    const dim3 tgB(4, 128);    // M=16384: 512 CTAs
    const int TB = 256;
    const int N2 = MTDD / 2;
    const int GB2 = (N2 + 255) / 256;
    const int W2 = (DD * DD / 2 + 255) / 256;
    const int W32 = (NLAY * DD * DD / 2 + 255) / 256;

    // launches 1-3 (deps of the profiled hgemm)
    split_pair16<<<GB2, 256>>>(frontrel, frbrh, frbrl, N2);
    split_pair16<<<GB2, 256>>>(backrel, frbrh + MTDD, frbrl + MTDD, N2);
    split_single16<<<W2, 256>>>(W_mg + (size_t)DD * DD, wmg2, DD * DD / 2);
    // launch 4: PROFILED — merged FR/BR GEMM
    hgemm<0, 2, false><<<tgB, TB, SM2>>>(frbrh, frbrl, DD, wmg2, nullptr, DD, DD,
        FRBR, nullptr, nullptr, nullptr, nullptr, nullptr, nullptr, nullptr, nullptr,
        b_mg, nullptr, nullptr, nullptr, nullptr, nullptr, nullptr, nullptr, nullptr, 0);

    detect_dom_fmt<<<1, 256>>>((const unsigned int*)domain);
    convert_dom<<<(MT * NDOM + 255) / 256, 256>>>(domain, dom8);
    rowstats_kernel<<<1024, 256>>>(adj, depmap, denom, fbadj);
    split_pair16<<<GB2, 256>>>(adj, adjh, adjl, N2);
    split_pair16<<<GB2, 256>>>(rel, relh, rell, N2);
    transpose_split16<<<dim3(16, 16, 16), dim3(32, 8)>>>(rel, relTh, relTl);
    split_single16<<<W2, 256>>>(W_mg, wmg1, DD * DD / 2);
    split_pair16<<<W32, 256>>>(W_layers, wlh, wll, NLAY * DD * DD / 2);
    split_pair16<<<W32, 256>>>(W_out, woh, wol, NLAY * DD * DD / 2);
    copy_split0<<<GB2, 256>>>(gcn, rel, X, Xh16, Xr16, N2);

    for (int l = 0; l < NLAY; l++) {
        pool_kernel<<<dim3(BB, DD / 128), 128>>>(X, dom8, pooled);
        dgate_kernel<<<dim3(BB * NDOM, DD / 128), 128>>>(pooled, W_dg, b_dg, domout);
        // relX GEMM + fused fo/bo build
        hgemm<7, 2, true><<<tgA, TB, SM2>>>(relh, rell, DD, Xh16, nullptr, DD, DD,
            nullptr, foboh, fobol, foboh + MTDD, fobol + MTDD,
            X, domout, domain_id, redom_id,
            nullptr, nullptr, nullptr, nullptr, nullptr, nullptr, nullptr, nullptr, nullptr, 0);
        // merged gates: P16[0:MTDD)=Pf, [MTDD:)=Pb
        hgemm<1, 2, false><<<tgB, TB, SM2>>>(foboh, fobol, DD, wmg1, nullptr, DD, DD,
            nullptr, P16, nullptr, nullptr, nullptr, nullptr, nullptr, nullptr, nullptr,
            nullptr, FRBR, nullptr, fbadj, foboh, fobol, nullptr, nullptr, nullptr, 0);
        // delta = relT @ Pf
        hgemm<4, 2, true><<<tgA, TB, SM2>>>(relTh, relTl, DD, P16, nullptr, DD, DD,
            delta, nullptr, nullptr, nullptr, nullptr, nullptr, nullptr, nullptr, nullptr,
            nullptr, nullptr, nullptr, nullptr, nullptr, nullptr, nullptr, nullptr, nullptr, 0);
        // AxpX = adj @ Xr + X  -> pair
        hgemm<5, 2, true><<<tgA, TB, SM2>>>(adjh, adjl, DD, Xr16, nullptr, DD, DD,
            nullptr, Axh, Axl, nullptr, nullptr, nullptr, nullptr, nullptr, nullptr,
            nullptr, nullptr, nullptr, nullptr, nullptr, nullptr, X, nullptr, nullptr, 0);
        // layer update (3-pass weights)
        hgemm<2, 3, false><<<tgA, TB, SM3>>>(Axh, Axl, DD,
            wlh + (size_t)l * DD * DD, wll + (size_t)l * DD * DD, DD, DD,
            X, Xh16, Xr16, outsh + (size_t)l * DD, outsl + (size_t)l * DD,
            nullptr, nullptr, nullptr, nullptr,
            b_layers + (size_t)l * DD, delta, P16 + MTDD, denom,
            nullptr, nullptr, nullptr, rel, prelu_a, l);
    }
    // final projection (3-pass weights)
    hgemm<3, 3, false><<<tgA, TB, SM3>>>(outsh, outsl, NLAY * DD, woh, wol, DD, NLAY * DD,
        (float*)d_out, nullptr, nullptr, nullptr, nullptr, nullptr, nullptr, nullptr, nullptr,
        b_out, gcn, nullptr, nullptr, nullptr, nullptr, nullptr, nullptr, nullptr, 0);
}

// round 9
// speedup vs baseline: 2.7476x; 1.1769x over previous
#include <cuda_runtime.h>
#include <cuda_fp16.h>
#include <math.h>
#include <stdint.h>

#define BB 16
#define SD 512
#define DD 512
#define MT (BB*SD)          // 8192
#define MTDD (MT*DD)        // 4194304
#define NLAY 3
#define NDOM 8

typedef __half fp16;

// ---------------- scratch (device globals; no allocation) ----------------
__device__ float g_X[MTDD];
__device__ float g_delta[MTDD];
__device__ float g_FRBR[2*MTDD];
__device__ float g_pooled[BB*NDOM*DD];
__device__ float g_domout[BB*NDOM*DD];
__device__ float g_denom[MT];
__device__ float g_fbadj[2*MT];
__device__ unsigned char g_dom8[MT*NDOM];
__device__ int g_domfmt;

// fp16 planes (data matrices: hi only; weights on the output path: hi+lo)
__device__ fp16 g_adjh[MTDD];
__device__ fp16 g_relh[MTDD];
__device__ fp16 g_relTh[MTDD];
__device__ fp16 g_Xh16[MTDD];
__device__ fp16 g_Xr16[MTDD];
__device__ fp16 g_foboh[2*MTDD];
__device__ fp16 g_P16[2*MTDD];
__device__ fp16 g_Axh[MTDD],   g_Axl[MTDD];
__device__ fp16 g_outsh[MT*NLAY*DD], g_outsl[MT*NLAY*DD];
__device__ fp16 g_frbrh[2*MTDD];
__device__ fp16 g_wmg1[DD*DD];
__device__ fp16 g_wmg2[DD*DD];
__device__ fp16 g_wlh[NLAY*DD*DD], g_wll[NLAY*DD*DD];
__device__ fp16 g_woh[NLAY*DD*DD], g_wol[NLAY*DD*DD];

__device__ __forceinline__ float sigf(float x) { return 1.f / (1.f + expf(-x)); }

__device__ __forceinline__ void split2h(float x, float y, uint32_t& h, uint32_t& lo) {
    fp16 hx = __float2half_rn(x), hy = __float2half_rn(y);
    float rx = x - __half2float(hx), ry = y - __half2float(hy);
    fp16 lx = __float2half_rn(rx), ly = __float2half_rn(ry);
    h  = ((uint32_t)__half_as_ushort(hy) << 16) | (uint32_t)__half_as_ushort(hx);
    lo = ((uint32_t)__half_as_ushort(ly) << 16) | (uint32_t)__half_as_ushort(lx);
}
__device__ __forceinline__ uint32_t pack2h(float x, float y) {
    return ((uint32_t)__half_as_ushort(__float2half_rn(y)) << 16) |
           (uint32_t)__half_as_ushort(__float2half_rn(x));
}

__device__ __forceinline__ uint32_t smem_u32(const void* p) {
    uint32_t a;
    asm("{ .reg .u64 t; cvta.to.shared.u64 t, %1; cvt.u32.u64 %0, t; }" : "=r"(a) : "l"(p));
    return a;
}
__device__ __forceinline__ void cpa16(uint32_t dst, const void* src) {
    asm volatile("{ .reg .u64 g; cvta.to.global.u64 g, %1; cp.async.cg.shared.global [%0], [g], 16; }"
                 :: "r"(dst), "l"(src) : "memory");
}
#define CP_COMMIT() asm volatile("cp.async.commit_group;" ::: "memory")
#define CP_WAIT1()  asm volatile("cp.async.wait_group 1;" ::: "memory")
#define CP_WAIT0()  asm volatile("cp.async.wait_group 0;" ::: "memory")

#define LDSM4(r0, r1, r2, r3, a) \
    asm volatile("ldmatrix.sync.aligned.m8n8.x4.shared.b16 {%0,%1,%2,%3}, [%4];" \
        : "=r"(r0), "=r"(r1), "=r"(r2), "=r"(r3) : "r"(a))
#define LDSM4T(r0, r1, r2, r3, a) \
    asm volatile("ldmatrix.sync.aligned.m8n8.x4.trans.shared.b16 {%0,%1,%2,%3}, [%4];" \
        : "=r"(r0), "=r"(r1), "=r"(r2), "=r"(r3) : "r"(a))
#define MMAH(acc, a, b) \
    asm volatile("mma.sync.aligned.m16n8k16.row.col.f32.f16.f16.f32 " \
        "{%0,%1,%2,%3}, {%4,%5,%6,%7}, {%8,%9}, {%0,%1,%2,%3};" \
        : "+f"((acc)[0]), "+f"((acc)[1]), "+f"((acc)[2]), "+f"((acc)[3]) \
        : "r"((a)[0]), "r"((a)[1]), "r"((a)[2]), "r"((a)[3]), "r"((b)[0]), "r"((b)[1]))

__device__ __forceinline__ int oh_idx(const float* __restrict__ p) {
    float s = 0.f; int k = -1;
#pragma unroll
    for (int i = 0; i < 8; i++) { float t = p[i]; s += t; if (t == 1.f) k = i; }
    return (s == 1.f) ? k : -1;
}

// ================= fp16 GEMM, 128x128 CTA =================
// 8 warps (2m x 4n), warp tile 64x32.
// PASSES=1: C = Ah*Bh (data GEMMs)
// PASSES=3: C = Ah*Bh + Al*Bh + Ah*Bl (weight-path GEMMs)
#define APITCH 80
#define BPITCH 272
#define A_PL (128*APITCH)            // 10240
#define B_PL (32*BPITCH)             // 8704

template<int EPI, int PASSES, bool BATCHB>
__global__ void __launch_bounds__(256, 2) hgemm(
    const fp16* __restrict__ Ah, const fp16* __restrict__ Al, int lda,
    const fp16* __restrict__ Bh, const fp16* __restrict__ Bl, int ldb, int K,
    float* __restrict__ C,
    fp16* __restrict__ O16a, fp16* __restrict__ O16b,
    fp16* __restrict__ O16c, fp16* __restrict__ O16d,
    const float* __restrict__ Xf, const float* __restrict__ domout,
    const float* __restrict__ did, const float* __restrict__ rid,
    const float* __restrict__ bias, const float* __restrict__ add1,
    const fp16* __restrict__ add16, const float* __restrict__ rowv,
    const fp16* __restrict__ mulh,
    const float* __restrict__ Cadd, const float* __restrict__ relf,
    const float* __restrict__ pa, int l)
{
    constexpr int APLANES = (PASSES == 3) ? 2 : 1;
    constexpr int BPLANES = (PASSES == 3) ? 2 : 1;
    constexpr int STG = APLANES * A_PL + BPLANES * B_PL;
    extern __shared__ __align__(128) char smp[];
    const uint32_t sb = smem_u32(smp);
    const int t = threadIdx.x;
    const int wid = t >> 5;
    const int lane = t & 31;
    const int m0 = blockIdx.y * 128;
    const int n0 = blockIdx.x * 128;
    const int KB = K >> 5;
    const int wm = (wid & 1) * 64;
    const int wn = (wid >> 1) * 32;
    const size_t boff = BATCHB ? (size_t)(m0 >> 9) * 512 * ldb : 0;

    float acc[4][4][4];
#pragma unroll
    for (int im = 0; im < 4; im++)
#pragma unroll
        for (int in = 0; in < 4; in++)
#pragma unroll
            for (int c = 0; c < 4; c++) acc[im][in][c] = 0.f;

    const int q = lane >> 3, r = lane & 7;
    const int arow = (q & 1) * 8 + r;
    const int acol = (q >> 1) * 8;
    const int bkrow = (q & 1) * 8 + r;
    const int bq8 = (q >> 1) * 8;

    auto stage_cp = [&](int st, int kb) {
        const int k0 = kb * 32;
        const uint32_t sa = sb + (uint32_t)st * STG;
#pragma unroll
        for (int i = 0; i < 2; i++) {
            int c = t + i * 256;
            int row = c >> 2, kc = c & 3;
            size_t go = (size_t)(m0 + row) * lda + k0 + kc * 8;
            uint32_t so = (uint32_t)row * APITCH + kc * 16;
            cpa16(sa + so, Ah + go);
            if (PASSES == 3) cpa16(sa + A_PL + so, Al + go);
        }
#pragma unroll
        for (int i = 0; i < 2; i++) {
            int c = t + i * 256;
            int row = c >> 4, nc = c & 15;
            size_t go = boff + (size_t)(k0 + row) * ldb + n0 + nc * 8;
            uint32_t so = (uint32_t)row * BPITCH + nc * 16;
            cpa16(sa + APLANES * A_PL + so, Bh + go);
            if (PASSES == 3) cpa16(sa + APLANES * A_PL + B_PL + so, Bl + go);
        }
        CP_COMMIT();
    };

    auto compute = [&](int st) {
        const uint32_t aH = sb + (uint32_t)st * STG;
        const uint32_t aL = aH + A_PL;
        const uint32_t bHp = aH + APLANES * A_PL;
        const uint32_t bLp = bHp + B_PL;
#pragma unroll
        for (int ks = 0; ks < 2; ks++) {
            const int k16 = ks * 16;
            uint32_t ah[4][4], bb[4][2];
#pragma unroll
            for (int im = 0; im < 4; im++) {
                uint32_t off = (uint32_t)(wm + im * 16 + arow) * APITCH + (k16 + acol) * 2;
                LDSM4(ah[im][0], ah[im][1], ah[im][2], ah[im][3], aH + off);
            }
#pragma unroll
            for (int j2 = 0; j2 < 2; j2++) {
                uint32_t off = (uint32_t)(k16 + bkrow) * BPITCH + (wn + bq8 + j2 * 16) * 2;
                LDSM4T(bb[j2 * 2][0], bb[j2 * 2][1], bb[j2 * 2 + 1][0], bb[j2 * 2 + 1][1], bHp + off);
            }
#pragma unroll
            for (int im = 0; im < 4; im++)
#pragma unroll
                for (int in = 0; in < 4; in++)
                    MMAH(acc[im][in], ah[im], bb[in]);
            if (PASSES == 3) {
                uint32_t al[4][4];
#pragma unroll
                for (int im = 0; im < 4; im++) {
                    uint32_t off = (uint32_t)(wm + im * 16 + arow) * APITCH + (k16 + acol) * 2;
                    LDSM4(al[im][0], al[im][1], al[im][2], al[im][3], aL + off);
                }
#pragma unroll
                for (int im = 0; im < 4; im++)
#pragma unroll
                    for (int in = 0; in < 4; in++)
                        MMAH(acc[im][in], al[im], bb[in]);
#pragma unroll
                for (int j2 = 0; j2 < 2; j2++) {
                    uint32_t off = (uint32_t)(k16 + bkrow) * BPITCH + (wn + bq8 + j2 * 16) * 2;
                    LDSM4T(bb[j2 * 2][0], bb[j2 * 2][1], bb[j2 * 2 + 1][0], bb[j2 * 2 + 1][1], bLp + off);
                }
#pragma unroll
                for (int im = 0; im < 4; im++)
#pragma unroll
                    for (int in = 0; in < 4; in++)
                        MMAH(acc[im][in], ah[im], bb[in]);
            }
        }
    };

    stage_cp(0, 0);
    stage_cp(1, 1);
    for (int kb = 0; kb < KB; kb++) {
        if (kb + 2 < KB) { CP_WAIT1(); } else { CP_WAIT0(); }
        __syncthreads();
        if (kb + 2 < KB) stage_cp((kb + 2) % 3, kb + 2);
        compute(kb % 3);
    }

    // ---------------- epilogue ----------------
    const int lr = lane >> 2;
    const int lc = (lane & 3) * 2;
    float al_p = 0.f;
    if (EPI == 2) al_p = pa[l];
    const int bofs = (EPI == 7) ? (m0 >> 9) * NDOM * 512 : 0;

#pragma unroll
    for (int im = 0; im < 4; im++) {
        const int gm0 = m0 + wm + im * 16 + lr;
        const int gm1 = gm0 + 8;
        float rv0 = 1.f, rv1 = 1.f;
        if (EPI == 1) { rv0 = rowv[gm0]; rv1 = rowv[gm1]; }
        if (EPI == 2) { rv0 = 1.f / rowv[gm0]; rv1 = 1.f / rowv[gm1]; }
        int dk0 = 0, dk1 = 0, rk0 = 0, rk1 = 0;
        if (EPI == 7) {
            dk0 = oh_idx(did + (size_t)gm0 * 8);
            dk1 = oh_idx(did + (size_t)gm1 * 8);
            rk0 = oh_idx(rid + (size_t)gm0 * 8);
            rk1 = oh_idx(rid + (size_t)gm1 * 8);
        }
#pragma unroll
        for (int in = 0; in < 4; in++) {
            const int gc = n0 + wn + in * 8 + lc;
            float v[4] = {acc[im][in][0], acc[im][in][1], acc[im][in][2], acc[im][in][3]};
            const size_t i0 = (size_t)gm0 * 512 + gc;
            const size_t i1 = (size_t)gm1 * 512 + gc;
            if (EPI == 0) {
                v[0] += bias[gc]; v[1] += bias[gc + 1];
                v[2] += bias[gc]; v[3] += bias[gc + 1];
                *(float2*)(C + i0) = make_float2(v[0], v[1]);
                *(float2*)(C + i1) = make_float2(v[2], v[3]);
            } else if (EPI == 7) {
                // fo (hi only)
                float2 x0 = *(const float2*)(Xf + i0);
                float2 x1 = *(const float2*)(Xf + i1);
                float2 dd0 = (dk0 >= 0) ? *(const float2*)(domout + (size_t)(bofs + dk0 * 512) + gc) : make_float2(0.f, 0.f);
                float2 dd1 = (dk1 >= 0) ? *(const float2*)(domout + (size_t)(bofs + dk1 * 512) + gc) : make_float2(0.f, 0.f);
                float f00 = dk0 >= 0 ? dd0.x : x0.x, f01 = dk0 >= 0 ? dd0.y : x0.y;
                float f10 = dk1 >= 0 ? dd1.x : x1.x, f11 = dk1 >= 0 ? dd1.y : x1.y;
                *(uint32_t*)(O16a + i0) = pack2h(f00, f01);
                *(uint32_t*)(O16a + i1) = pack2h(f10, f11);
                // bo (acc = relX)
                float2 rr0 = (rk0 >= 0) ? *(const float2*)(domout + (size_t)(bofs + rk0 * 512) + gc) : make_float2(0.f, 0.f);
                float2 rr1 = (rk1 >= 0) ? *(const float2*)(domout + (size_t)(bofs + rk1 * 512) + gc) : make_float2(0.f, 0.f);
                float b00 = rk0 >= 0 ? rr0.x : v[0], b01 = rk0 >= 0 ? rr0.y : v[1];
                float b10 = rk1 >= 0 ? rr1.x : v[2], b11 = rk1 >= 0 ? rr1.y : v[3];
                *(uint32_t*)(O16c + i0) = pack2h(b00, b01);
                *(uint32_t*)(O16c + i1) = pack2h(b10, b11);
            } else if (EPI == 1) {
                float2 a0 = *(const float2*)(add1 + i0);
                float2 a1 = *(const float2*)(add1 + i1);
                uint32_t mh0 = *(const uint32_t*)(mulh + i0);
                uint32_t mh1 = *(const uint32_t*)(mulh + i1);
                float m00 = __half2float(__ushort_as_half(mh0 & 0xffff));
                float m01 = __half2float(__ushort_as_half(mh0 >> 16));
                float m10 = __half2float(__ushort_as_half(mh1 & 0xffff));
                float m11 = __half2float(__ushort_as_half(mh1 >> 16));
                v[0] = rv0 * sigf(v[0] + a0.x) * m00;
                v[1] = rv0 * sigf(v[1] + a0.y) * m01;
                v[2] = rv1 * sigf(v[2] + a1.x) * m10;
                v[3] = rv1 * sigf(v[3] + a1.y) * m11;
                *(uint32_t*)(O16a + i0) = pack2h(v[0], v[1]);
                *(uint32_t*)(O16a + i1) = pack2h(v[2], v[3]);
            } else if (EPI == 4) {
                *(float2*)(C + i0) = make_float2(v[0], v[1]);
                *(float2*)(C + i1) = make_float2(v[2], v[3]);
            } else if (EPI == 5) {
                float2 a0 = *(const float2*)(Cadd + i0);
                float2 a1 = *(const float2*)(Cadd + i1);
                v[0] += a0.x; v[1] += a0.y; v[2] += a1.x; v[3] += a1.y;
                uint32_t h, lo;
                split2h(v[0], v[1], h, lo);
                *(uint32_t*)(O16a + i0) = h; *(uint32_t*)(O16b + i0) = lo;
                split2h(v[2], v[3], h, lo);
                *(uint32_t*)(O16a + i1) = h; *(uint32_t*)(O16b + i1) = lo;
            } else if (EPI == 2) {
                float b0 = 2.f * bias[gc], b1 = 2.f * bias[gc + 1];
                float2 a0 = *(const float2*)(add1 + i0);
                float2 a1 = *(const float2*)(add1 + i1);
                uint32_t p0 = *(const uint32_t*)(add16 + i0);
                uint32_t p1 = *(const uint32_t*)(add16 + i1);
                float t0 = (v[0] + b0 + a0.x + __half2float(__ushort_as_half(p0 & 0xffff))) * rv0;
                float t1 = (v[1] + b1 + a0.y + __half2float(__ushort_as_half(p0 >> 16))) * rv0;
                float t2 = (v[2] + b0 + a1.x + __half2float(__ushort_as_half(p1 & 0xffff))) * rv1;
                float t3 = (v[3] + b1 + a1.y + __half2float(__ushort_as_half(p1 >> 16))) * rv1;
                v[0] = t0 >= 0.f ? t0 : al_p * t0;
                v[1] = t1 >= 0.f ? t1 : al_p * t1;
                v[2] = t2 >= 0.f ? t2 : al_p * t2;
                v[3] = t3 >= 0.f ? t3 : al_p * t3;
                *(float2*)(C + i0) = make_float2(v[0], v[1]);
                *(float2*)(C + i1) = make_float2(v[2], v[3]);
                *(uint32_t*)(O16a + i0) = pack2h(v[0], v[1]);
                *(uint32_t*)(O16a + i1) = pack2h(v[2], v[3]);
                float2 re0 = *(const float2*)(relf + i0);
                float2 re1 = *(const float2*)(relf + i1);
                *(uint32_t*)(O16b + i0) = pack2h(v[0] * re0.x, v[1] * re0.y);
                *(uint32_t*)(O16b + i1) = pack2h(v[2] * re1.x, v[3] * re1.y);
                uint32_t h, lo;
                split2h(v[0], v[1], h, lo);
                *(uint32_t*)(O16c + (size_t)gm0 * (NLAY * DD) + gc) = h;
                *(uint32_t*)(O16d + (size_t)gm0 * (NLAY * DD) + gc) = lo;
                split2h(v[2], v[3], h, lo);
                *(uint32_t*)(O16c + (size_t)gm1 * (NLAY * DD) + gc) = h;
                *(uint32_t*)(O16d + (size_t)gm1 * (NLAY * DD) + gc) = lo;
            } else if (EPI == 3) {
                float2 a0 = *(const float2*)(add1 + i0);
                float2 a1 = *(const float2*)(add1 + i1);
                v[0] += bias[gc] + a0.x;     v[1] += bias[gc + 1] + a0.y;
                v[2] += bias[gc] + a1.x;     v[3] += bias[gc + 1] + a1.y;
                *(float2*)(C + i0) = make_float2(v[0], v[1]);
                *(float2*)(C + i1) = make_float2(v[2], v[3]);
            }
        }
    }
}

// ================= small kernels =================
__global__ void detect_dom_fmt(const unsigned int* __restrict__ w) {
    __shared__ int sf, sbt;
    if (threadIdx.x == 0) { sf = 0; sbt = 0; }
    __syncthreads();
    for (int i = threadIdx.x; i < 1024; i += 256) {
        unsigned int v = w[i];
        if (v == 0x3F800000u) atomicOr(&sf, 1);
        else if (v > 1u) atomicOr(&sbt, 1);
    }
    __syncthreads();
    if (threadIdx.x == 0) g_domfmt = sf ? 2 : (sbt ? 0 : 1);
}

__global__ void convert_dom(const void* __restrict__ dom, unsigned char* __restrict__ out) {
    int i = blockIdx.x * 256 + threadIdx.x;
    if (i >= MT * NDOM) return;
    int fmt = g_domfmt;
    unsigned char v;
    if (fmt == 0)      v = ((const unsigned char*)dom)[i] != 0;
    else if (fmt == 1) v = ((const int*)dom)[i] != 0;
    else               v = ((const float*)dom)[i] != 0.f;
    out[i] = v;
}

__global__ void rowstats_kernel(const float* __restrict__ adj,
                                const float* __restrict__ depmap,
                                float* __restrict__ denom,
                                float* __restrict__ fbadj) {
    int warp = (blockIdx.x * blockDim.x + threadIdx.x) >> 5;
    int lane = threadIdx.x & 31;
    if (warp >= MT) return;
    int b = warp >> 9;
    int s = warp & 511;
    const float* arow = adj + (size_t)(b * SD + s) * SD;
    const float* drow = depmap + (size_t)(b * SD + s) * SD;
    const float* acol = adj + (size_t)b * SD * SD + s;
    float sa = 0.f, sf = 0.f, sb = 0.f;
    for (int j = lane; j < SD; j += 32) {
        float a = arow[j];
        float dp = drow[j];
        sa += a;
        sf += a * dp;
        sb += acol[(size_t)j * SD] * dp;
    }
#pragma unroll
    for (int off = 16; off > 0; off >>= 1) {
        sa += __shfl_down_sync(0xffffffffu, sa, off);
        sf += __shfl_down_sync(0xffffffffu, sf, off);
        sb += __shfl_down_sync(0xffffffffu, sb, off);
    }
    if (lane == 0) {
        denom[warp] = sa + 1.f;
        fbadj[warp] = sf;
        fbadj[MT + warp] = sb;
    }
}

__global__ void split_pair16(const float* __restrict__ src, fp16* __restrict__ h,
                             fp16* __restrict__ lo, int n2) {
    int i = blockIdx.x * 256 + threadIdx.x;
    if (i >= n2) return;
    float2 v = ((const float2*)src)[i];
    uint32_t hw, lw;
    split2h(v.x, v.y, hw, lw);
    ((uint32_t*)h)[i] = hw;
    ((uint32_t*)lo)[i] = lw;
}

__global__ void split_single16(const float* __restrict__ src, fp16* __restrict__ h, int n2) {
    int i = blockIdx.x * 256 + threadIdx.x;
    if (i >= n2) return;
    float2 v = ((const float2*)src)[i];
    ((uint32_t*)h)[i] = pack2h(v.x, v.y);
}

__global__ void copy_split0(const float* __restrict__ gcn, const float* __restrict__ rel,
                            float* __restrict__ X, fp16* __restrict__ Xh,
                            fp16* __restrict__ Xr, int n2) {
    int i = blockIdx.x * 256 + threadIdx.x;
    if (i >= n2) return;
    float2 v = ((const float2*)gcn)[i];
    float2 rv = ((const float2*)rel)[i];
    ((float2*)X)[i] = v;
    ((uint32_t*)Xh)[i] = pack2h(v.x, v.y);
    ((uint32_t*)Xr)[i] = pack2h(v.x * rv.x, v.y * rv.y);
}

__global__ void transpose_single16(const float* __restrict__ in, fp16* __restrict__ h) {
    __shared__ float ts[32][33];
    int b = blockIdx.z;
    int x0 = blockIdx.x * 32, y0 = blockIdx.y * 32;
    const float* ib = in + (size_t)b * 262144;
    int tx = threadIdx.x, ty = threadIdx.y;
#pragma unroll
    for (int i = 0; i < 32; i += 8)
        ts[ty + i][tx] = ib[(size_t)(y0 + ty + i) * 512 + x0 + tx];
    __syncthreads();
#pragma unroll
    for (int i = 0; i < 32; i += 8) {
        float v = ts[tx][ty + i];
        size_t o = (size_t)b * 262144 + (size_t)(x0 + ty + i) * 512 + y0 + tx;
        h[o] = __float2half_rn(v);
    }
}

__global__ void pool_kernel(const float* __restrict__ X,
                            const unsigned char* __restrict__ dom,
                            float* __restrict__ pooled) {
    int b = blockIdx.x;
    int d = blockIdx.y * 128 + threadIdx.x;
    float mv[NDOM];
#pragma unroll
    for (int k = 0; k < NDOM; k++) mv[k] = -3.402823466e38f;
    const float* Xb = X + (size_t)b * SD * DD;
    const unsigned long long* db = (const unsigned long long*)(dom + (size_t)b * SD * NDOM);
    for (int s = 0; s < SD; s++) {
        float x = Xb[(size_t)s * DD + d];
        unsigned long long mk = db[s];
#pragma unroll
        for (int k = 0; k < NDOM; k++) {
            float v = ((mk >> (8 * k)) & 0xffull) ? -10000.f : x;
            mv[k] = fmaxf(mv[k], v);
        }
    }
#pragma unroll
    for (int k = 0; k < NDOM; k++) pooled[((size_t)b * NDOM + k) * DD + d] = mv[k];
}

__global__ void dgate_kernel(const float* __restrict__ pooled,
                             const float* __restrict__ Wdg,
                             const float* __restrict__ bdg,
                             float* __restrict__ out) {
    int bk = blockIdx.x;
    int d = blockIdx.y * 128 + threadIdx.x;
    __shared__ float sp[DD];
    for (int e = threadIdx.x; e < DD; e += 128) sp[e] = pooled[(size_t)bk * DD + e];
    __syncthreads();
    float acc = bdg[d];
#pragma unroll 8
    for (int e = 0; e < DD; e++) acc += sp[e] * Wdg[(size_t)e * DD + d];
    out[(size_t)bk * DD + d] = sigf(acc);
}

// ================= host launcher =================
#define SM1 (3 * (A_PL + B_PL))          // 56832
#define SM3 (3 * (2 * A_PL + 2 * B_PL))  // 113664

extern "C" void kernel_launch(void* const* d_in, const int* in_sizes, int n_in,
                              void* d_out, int out_size) {
    const float* adj       = (const float*)d_in[0];
    const void*  domain    = d_in[1];
    const float* domain_id = (const float*)d_in[2];
    const float* redom_id  = (const float*)d_in[3];
    const float* frontrel  = (const float*)d_in[4];
    const float* backrel   = (const float*)d_in[5];
    const float* depmap    = (const float*)d_in[6];
    const float* rel       = (const float*)d_in[7];
    const float* gcn       = (const float*)d_in[8];
    const float* W_layers  = (const float*)d_in[10];
    const float* b_layers  = (const float*)d_in[11];
    const float* prelu_a   = (const float*)d_in[12];
    const float* W_dg      = (const float*)d_in[13];
    const float* b_dg      = (const float*)d_in[14];
    const float* W_mg      = (const float*)d_in[15];
    const float* b_mg      = (const float*)d_in[16];
    const float* W_out     = (const float*)d_in[17];
    const float* b_out     = (const float*)d_in[18];

    float *X, *delta, *FRBR, *pooled, *domout, *denom, *fbadj;
    unsigned char *dom8;
    fp16 *adjh, *relh, *relTh, *Xh16, *Xr16, *foboh, *P16, *Axh, *Axl,
         *outsh, *outsl, *frbrh, *wmg1, *wmg2, *wlh, *wll, *woh, *wol;
    cudaGetSymbolAddress((void**)&X, g_X);
    cudaGetSymbolAddress((void**)&delta, g_delta);
    cudaGetSymbolAddress((void**)&FRBR, g_FRBR);
    cudaGetSymbolAddress((void**)&pooled, g_pooled);
    cudaGetSymbolAddress((void**)&domout, g_domout);
    cudaGetSymbolAddress((void**)&denom, g_denom);
    cudaGetSymbolAddress((void**)&fbadj, g_fbadj);
    cudaGetSymbolAddress((void**)&dom8, g_dom8);
    cudaGetSymbolAddress((void**)&adjh, g_adjh);
    cudaGetSymbolAddress((void**)&relh, g_relh);
    cudaGetSymbolAddress((void**)&relTh, g_relTh);
    cudaGetSymbolAddress((void**)&Xh16, g_Xh16);   cudaGetSymbolAddress((void**)&Xr16, g_Xr16);
    cudaGetSymbolAddress((void**)&foboh, g_foboh);
    cudaGetSymbolAddress((void**)&P16, g_P16);
    cudaGetSymbolAddress((void**)&Axh, g_Axh);     cudaGetSymbolAddress((void**)&Axl, g_Axl);
    cudaGetSymbolAddress((void**)&outsh, g_outsh); cudaGetSymbolAddress((void**)&outsl, g_outsl);
    cudaGetSymbolAddress((void**)&frbrh, g_frbrh);
    cudaGetSymbolAddress((void**)&wmg1, g_wmg1);   cudaGetSymbolAddress((void**)&wmg2, g_wmg2);
    cudaGetSymbolAddress((void**)&wlh, g_wlh);     cudaGetSymbolAddress((void**)&wll, g_wll);
    cudaGetSymbolAddress((void**)&woh, g_woh);     cudaGetSymbolAddress((void**)&wol, g_wol);

    cudaFuncSetAttribute(hgemm<0, 1, false>, cudaFuncAttributeMaxDynamicSharedMemorySize, SM1);
    cudaFuncSetAttribute(hgemm<7, 1, true >, cudaFuncAttributeMaxDynamicSharedMemorySize, SM1);
    cudaFuncSetAttribute(hgemm<1, 1, false>, cudaFuncAttributeMaxDynamicSharedMemorySize, SM1);
    cudaFuncSetAttribute(hgemm<4, 1, true >, cudaFuncAttributeMaxDynamicSharedMemorySize, SM1);
    cudaFuncSetAttribute(hgemm<5, 1, true >, cudaFuncAttributeMaxDynamicSharedMemorySize, SM1);
    cudaFuncSetAttribute(hgemm<2, 3, false>, cudaFuncAttributeMaxDynamicSharedMemorySize, SM3);
    cudaFuncSetAttribute(hgemm<3, 3, false>, cudaFuncAttributeMaxDynamicSharedMemorySize, SM3);

    const dim3 tgA(4, 64);     // M=8192:  256 CTAs
    const dim3 tgB(4, 128);    // M=16384: 512 CTAs
    const int TB = 256;
    const int N2 = MTDD / 2;
    const int GB2 = (N2 + 255) / 256;
    const int W2 = (DD * DD / 2 + 255) / 256;
    const int W32 = (NLAY * DD * DD / 2 + 255) / 256;

    // launches 1-3 (deps of the profiled hgemm)
    split_single16<<<GB2, 256>>>(frontrel, frbrh, N2);
    split_single16<<<GB2, 256>>>(backrel, frbrh + MTDD, N2);
    split_single16<<<W2, 256>>>(W_mg + (size_t)DD * DD, wmg2, DD * DD / 2);
    // launch 4: PROFILED — merged FR/BR GEMM (single-pass)
    hgemm<0, 1, false><<<tgB, TB, SM1>>>(frbrh, nullptr, DD, wmg2, nullptr, DD, DD,
        FRBR, nullptr, nullptr, nullptr, nullptr, nullptr, nullptr, nullptr, nullptr,
        b_mg, nullptr, nullptr, nullptr, nullptr, nullptr, nullptr, nullptr, 0);

    detect_dom_fmt<<<1, 256>>>((const unsigned int*)domain);
    convert_dom<<<(MT * NDOM + 255) / 256, 256>>>(domain, dom8);
    rowstats_kernel<<<1024, 256>>>(adj, depmap, denom, fbadj);
    split_single16<<<GB2, 256>>>(adj, adjh, N2);
    split_single16<<<GB2, 256>>>(rel, relh, N2);
    transpose_single16<<<dim3(16, 16, 16), dim3(32, 8)>>>(rel, relTh);
    split_single16<<<W2, 256>>>(W_mg, wmg1, DD * DD / 2);
    split_pair16<<<W32, 256>>>(W_layers, wlh, wll, NLAY * DD * DD / 2);
    split_pair16<<<W32, 256>>>(W_out, woh, wol, NLAY * DD * DD / 2);
    copy_split0<<<GB2, 256>>>(gcn, rel, X, Xh16, Xr16, N2);

    for (int l = 0; l < NLAY; l++) {
        pool_kernel<<<dim3(BB, DD / 128), 128>>>(X, dom8, pooled);
        dgate_kernel<<<dim3(BB * NDOM, DD / 128), 128>>>(pooled, W_dg, b_dg, domout);
        // relX GEMM + fused fo/bo build (single-pass)
        hgemm<7, 1, true><<<tgA, TB, SM1>>>(relh, nullptr, DD, Xh16, nullptr, DD, DD,
            nullptr, foboh, nullptr, foboh + MTDD, nullptr,
            X, domout, domain_id, redom_id,
            nullptr, nullptr, nullptr, nullptr, nullptr, nullptr, nullptr, nullptr, 0);
        // merged gates: P16[0:MTDD)=Pf, [MTDD:)=Pb (single-pass)
        hgemm<1, 1, false><<<tgB, TB, SM1>>>(foboh, nullptr, DD, wmg1, nullptr, DD, DD,
            nullptr, P16, nullptr, nullptr, nullptr, nullptr, nullptr, nullptr, nullptr,
            nullptr, FRBR, nullptr, fbadj, foboh, nullptr, nullptr, nullptr, 0);
        // delta = relT @ Pf (single-pass)
        hgemm<4, 1, true><<<tgA, TB, SM1>>>(relTh, nullptr, DD, P16, nullptr, DD, DD,
            delta, nullptr, nullptr, nullptr, nullptr, nullptr, nullptr, nullptr, nullptr,
            nullptr, nullptr, nullptr, nullptr, nullptr, nullptr, nullptr, nullptr, 0);
        // AxpX = adj @ Xr + X -> pair (single-pass GEMM, pair output for 3-pass consumer)
        hgemm<5, 1, true><<<tgA, TB, SM1>>>(adjh, nullptr, DD, Xr16, nullptr, DD, DD,
            nullptr, Axh, Axl, nullptr, nullptr, nullptr, nullptr, nullptr, nullptr,
            nullptr, nullptr, nullptr, nullptr, nullptr, X, nullptr, nullptr, 0);
        // layer update (3-pass, weights split)
        hgemm<2, 3, false><<<tgA, TB, SM3>>>(Axh, Axl, DD,
            wlh + (size_t)l * DD * DD, wll + (size_t)l * DD * DD, DD, DD,
            X, Xh16, Xr16, outsh + (size_t)l * DD, outsl + (size_t)l * DD,
            nullptr, nullptr, nullptr, nullptr,
            b_layers + (size_t)l * DD, delta, P16 + MTDD, denom,
            nullptr, nullptr, rel, prelu_a, l);
    }
    // final projection (3-pass, weights split)
    hgemm<3, 3, false><<<tgA, TB, SM3>>>(outsh, outsl, NLAY * DD, woh, wol, DD, NLAY * DD,
        (float*)d_out, nullptr, nullptr, nullptr, nullptr, nullptr, nullptr, nullptr, nullptr,
        b_out, gcn, nullptr, nullptr, nullptr, nullptr, nullptr, nullptr, 0);
}

// round 10
// speedup vs baseline: 3.0554x; 1.1121x over previous
#include <cuda_runtime.h>
#include <cuda_fp16.h>
#include <math.h>
#include <stdint.h>

#define BB 16
#define SD 512
#define DD 512
#define MT (BB*SD)          // 8192
#define MTDD (MT*DD)        // 4194304
#define NLAY 3
#define NDOM 8

typedef __half fp16;

// ---------------- scratch (device globals; no allocation) ----------------
__device__ float g_X[MTDD];
__device__ float g_pooled[BB*NDOM*DD];
__device__ float g_domout[BB*NDOM*DD];
__device__ float g_denom[MT];
__device__ float g_fbadj[2*MT];
__device__ unsigned char g_dom8[MT*NDOM];
__device__ int g_domfmt;

// fp16 planes
__device__ fp16 g_adjh[MTDD];
__device__ fp16 g_relh[MTDD];
__device__ fp16 g_relTh[MTDD];
__device__ fp16 g_Xh16[MTDD];
__device__ fp16 g_Xr16[MTDD];
__device__ fp16 g_foboh[2*MTDD];
__device__ fp16 g_P16[2*MTDD];
__device__ fp16 g_delta16[MTDD];
__device__ fp16 g_FRBR16[2*MTDD];
__device__ fp16 g_Axh[MTDD],   g_Axl[MTDD];
__device__ fp16 g_outsh[MT*NLAY*DD], g_outsl[MT*NLAY*DD];
__device__ fp16 g_frbrh[2*MTDD];
__device__ fp16 g_wmg1[DD*DD];
__device__ fp16 g_wmg2[DD*DD];
__device__ fp16 g_wlh[NLAY*DD*DD];
__device__ fp16 g_woh[NLAY*DD*DD];

__device__ __forceinline__ float sigf(float x) { return 1.f / (1.f + expf(-x)); }

__device__ __forceinline__ void split2h(float x, float y, uint32_t& h, uint32_t& lo) {
    fp16 hx = __float2half_rn(x), hy = __float2half_rn(y);
    float rx = x - __half2float(hx), ry = y - __half2float(hy);
    fp16 lx = __float2half_rn(rx), ly = __float2half_rn(ry);
    h  = ((uint32_t)__half_as_ushort(hy) << 16) | (uint32_t)__half_as_ushort(hx);
    lo = ((uint32_t)__half_as_ushort(ly) << 16) | (uint32_t)__half_as_ushort(lx);
}
__device__ __forceinline__ uint32_t pack2h(float x, float y) {
    return ((uint32_t)__half_as_ushort(__float2half_rn(y)) << 16) |
           (uint32_t)__half_as_ushort(__float2half_rn(x));
}
__device__ __forceinline__ float h2lo(uint32_t w) { return __half2float(__ushort_as_half(w & 0xffff)); }
__device__ __forceinline__ float h2hi(uint32_t w) { return __half2float(__ushort_as_half(w >> 16)); }

__device__ __forceinline__ uint32_t smem_u32(const void* p) {
    uint32_t a;
    asm("{ .reg .u64 t; cvta.to.shared.u64 t, %1; cvt.u32.u64 %0, t; }" : "=r"(a) : "l"(p));
    return a;
}
__device__ __forceinline__ void cpa16(uint32_t dst, const void* src) {
    asm volatile("{ .reg .u64 g; cvta.to.global.u64 g, %1; cp.async.cg.shared.global [%0], [g], 16; }"
                 :: "r"(dst), "l"(src) : "memory");
}
#define CP_COMMIT() asm volatile("cp.async.commit_group;" ::: "memory")
#define CP_WAIT1()  asm volatile("cp.async.wait_group 1;" ::: "memory")
#define CP_WAIT0()  asm volatile("cp.async.wait_group 0;" ::: "memory")

#define LDSM4(r0, r1, r2, r3, a) \
    asm volatile("ldmatrix.sync.aligned.m8n8.x4.shared.b16 {%0,%1,%2,%3}, [%4];" \
        : "=r"(r0), "=r"(r1), "=r"(r2), "=r"(r3) : "r"(a))
#define LDSM4T(r0, r1, r2, r3, a) \
    asm volatile("ldmatrix.sync.aligned.m8n8.x4.trans.shared.b16 {%0,%1,%2,%3}, [%4];" \
        : "=r"(r0), "=r"(r1), "=r"(r2), "=r"(r3) : "r"(a))
#define MMAH(acc, a, b) \
    asm volatile("mma.sync.aligned.m16n8k16.row.col.f32.f16.f16.f32 " \
        "{%0,%1,%2,%3}, {%4,%5,%6,%7}, {%8,%9}, {%0,%1,%2,%3};" \
        : "+f"((acc)[0]), "+f"((acc)[1]), "+f"((acc)[2]), "+f"((acc)[3]) \
        : "r"((a)[0]), "r"((a)[1]), "r"((a)[2]), "r"((a)[3]), "r"((b)[0]), "r"((b)[1]))

__device__ __forceinline__ int oh_idx(const float* __restrict__ p) {
    float s = 0.f; int k = -1;
#pragma unroll
    for (int i = 0; i < 8; i++) { float t = p[i]; s += t; if (t == 1.f) k = i; }
    return (s == 1.f) ? k : -1;
}

// ================= fp16 GEMM, 128x128 CTA, 2 CTAs/SM =================
// 8 warps (2m x 4n), warp tile 64x32.
// PASSES=1: C = Ah*Bh          (BK=64, data GEMMs)
// PASSES=2: C = Ah*Bh + Al*Bh  (BK=32, weight GEMMs, A pair)
// EPI 0: FRBR16 = pack(acc + bias)
// EPI 7: relX epilogue: fo/bo build -> foboh fp16
// EPI 1: P16 = pack(rowv * sig(acc + frbr16) * mulh)
// EPI 8: delta16 = pack(acc)
// EPI 5: Ax pair = split(acc + Cadd)
// EPI 2: t = (acc + 2*bias + delta16(add16b) + Pb16(add16))/rowv; prelu
//        -> C(X fp32), Xh16, Xr16(=t*relf), outs pair
// EPI 3: C = acc + bias + add1(gcn)
template<int EPI, int PASSES, bool BATCHB>
__global__ void __launch_bounds__(256, 2) hgemm(
    const fp16* __restrict__ Ah, const fp16* __restrict__ Al, int lda,
    const fp16* __restrict__ Bh, int ldb, int K,
    float* __restrict__ C,
    fp16* __restrict__ O16a, fp16* __restrict__ O16b,
    fp16* __restrict__ O16c, fp16* __restrict__ O16d,
    const float* __restrict__ Xf, const float* __restrict__ domout,
    const float* __restrict__ did, const float* __restrict__ rid,
    const float* __restrict__ bias, const float* __restrict__ add1,
    const fp16* __restrict__ add16, const fp16* __restrict__ add16b,
    const float* __restrict__ rowv, const fp16* __restrict__ mulh,
    const float* __restrict__ Cadd, const float* __restrict__ relf,
    const float* __restrict__ pa, int l)
{
    constexpr int BK = (PASSES == 1) ? 64 : 32;
    constexpr int APITCH = 2 * BK + 16;        // 144 or 80
    constexpr int A_PL = 128 * APITCH;
    constexpr int BPITCH = 272;
    constexpr int B_PL = BK * BPITCH;
    constexpr int APLANES = (PASSES == 2) ? 2 : 1;
    constexpr int STG = APLANES * A_PL + B_PL;
    constexpr int KCH = BK / 8;                // A chunks per row
    constexpr int NIT = BK / 16;               // staging iters & k16 steps

    extern __shared__ __align__(128) char smp[];
    const uint32_t sb = smem_u32(smp);
    const int t = threadIdx.x;
    const int wid = t >> 5;
    const int lane = t & 31;
    const int m0 = blockIdx.y * 128;
    const int n0 = blockIdx.x * 128;
    const int KB = K / BK;
    const int wm = (wid & 1) * 64;
    const int wn = (wid >> 1) * 32;
    const size_t boff = BATCHB ? (size_t)(m0 >> 9) * 512 * ldb : 0;

    float acc[4][4][4];
#pragma unroll
    for (int im = 0; im < 4; im++)
#pragma unroll
        for (int in = 0; in < 4; in++)
#pragma unroll
            for (int c = 0; c < 4; c++) acc[im][in][c] = 0.f;

    const int q = lane >> 3, r = lane & 7;
    const int arow = (q & 1) * 8 + r;
    const int acol = (q >> 1) * 8;
    const int bkrow = (q & 1) * 8 + r;
    const int bq8 = (q >> 1) * 8;

    auto stage_cp = [&](int st, int kb) {
        const int k0 = kb * BK;
        const uint32_t sa = sb + (uint32_t)st * STG;
#pragma unroll
        for (int i = 0; i < NIT; i++) {
            int c = t + i * 256;
            int row = c / KCH, kc = c % KCH;
            size_t go = (size_t)(m0 + row) * lda + k0 + kc * 8;
            uint32_t so = (uint32_t)row * APITCH + kc * 16;
            cpa16(sa + so, Ah + go);
            if (PASSES == 2) cpa16(sa + A_PL + so, Al + go);
        }
#pragma unroll
        for (int i = 0; i < NIT; i++) {
            int c = t + i * 256;
            int row = c >> 4, nc = c & 15;
            size_t go = boff + (size_t)(k0 + row) * ldb + n0 + nc * 8;
            uint32_t so = (uint32_t)row * BPITCH + nc * 16;
            cpa16(sa + APLANES * A_PL + so, Bh + go);
        }
        CP_COMMIT();
    };

    auto compute = [&](int st) {
        const uint32_t aH = sb + (uint32_t)st * STG;
        const uint32_t aL = aH + A_PL;
        const uint32_t bHp = aH + APLANES * A_PL;
#pragma unroll
        for (int ks = 0; ks < NIT; ks++) {
            const int k16 = ks * 16;
            uint32_t ah[4][4], bb[4][2];
#pragma unroll
            for (int im = 0; im < 4; im++) {
                uint32_t off = (uint32_t)(wm + im * 16 + arow) * APITCH + (k16 + acol) * 2;
                LDSM4(ah[im][0], ah[im][1], ah[im][2], ah[im][3], aH + off);
            }
#pragma unroll
            for (int j2 = 0; j2 < 2; j2++) {
                uint32_t off = (uint32_t)(k16 + bkrow) * BPITCH + (wn + bq8 + j2 * 16) * 2;
                LDSM4T(bb[j2 * 2][0], bb[j2 * 2][1], bb[j2 * 2 + 1][0], bb[j2 * 2 + 1][1], bHp + off);
            }
#pragma unroll
            for (int im = 0; im < 4; im++)
#pragma unroll
                for (int in = 0; in < 4; in++)
                    MMAH(acc[im][in], ah[im], bb[in]);
            if (PASSES == 2) {
                uint32_t al[4][4];
#pragma unroll
                for (int im = 0; im < 4; im++) {
                    uint32_t off = (uint32_t)(wm + im * 16 + arow) * APITCH + (k16 + acol) * 2;
                    LDSM4(al[im][0], al[im][1], al[im][2], al[im][3], aL + off);
                }
#pragma unroll
                for (int im = 0; im < 4; im++)
#pragma unroll
                    for (int in = 0; in < 4; in++)
                        MMAH(acc[im][in], al[im], bb[in]);
            }
        }
    };

    stage_cp(0, 0);
    stage_cp(1, 1);
    for (int kb = 0; kb < KB; kb++) {
        if (kb + 2 < KB) { CP_WAIT1(); } else { CP_WAIT0(); }
        __syncthreads();
        if (kb + 2 < KB) stage_cp((kb + 2) % 3, kb + 2);
        compute(kb % 3);
    }

    // ---------------- epilogue ----------------
    const int lr = lane >> 2;
    const int lc = (lane & 3) * 2;
    float al_p = 0.f;
    if (EPI == 2) al_p = pa[l];
    const int bofs = (EPI == 7) ? (m0 >> 9) * NDOM * 512 : 0;

#pragma unroll
    for (int im = 0; im < 4; im++) {
        const int gm0 = m0 + wm + im * 16 + lr;
        const int gm1 = gm0 + 8;
        float rv0 = 1.f, rv1 = 1.f;
        if (EPI == 1) { rv0 = rowv[gm0]; rv1 = rowv[gm1]; }
        if (EPI == 2) { rv0 = 1.f / rowv[gm0]; rv1 = 1.f / rowv[gm1]; }
        int dk0 = 0, dk1 = 0, rk0 = 0, rk1 = 0;
        if (EPI == 7) {
            dk0 = oh_idx(did + (size_t)gm0 * 8);
            dk1 = oh_idx(did + (size_t)gm1 * 8);
            rk0 = oh_idx(rid + (size_t)gm0 * 8);
            rk1 = oh_idx(rid + (size_t)gm1 * 8);
        }
#pragma unroll
        for (int in = 0; in < 4; in++) {
            const int gc = n0 + wn + in * 8 + lc;
            float v[4] = {acc[im][in][0], acc[im][in][1], acc[im][in][2], acc[im][in][3]};
            const size_t i0 = (size_t)gm0 * 512 + gc;
            const size_t i1 = (size_t)gm1 * 512 + gc;
            if (EPI == 0) {
                *(uint32_t*)(O16a + i0) = pack2h(v[0] + bias[gc], v[1] + bias[gc + 1]);
                *(uint32_t*)(O16a + i1) = pack2h(v[2] + bias[gc], v[3] + bias[gc + 1]);
            } else if (EPI == 7) {
                float2 x0 = *(const float2*)(Xf + i0);
                float2 x1 = *(const float2*)(Xf + i1);
                float2 dd0 = (dk0 >= 0) ? *(const float2*)(domout + (size_t)(bofs + dk0 * 512) + gc) : make_float2(0.f, 0.f);
                float2 dd1 = (dk1 >= 0) ? *(const float2*)(domout + (size_t)(bofs + dk1 * 512) + gc) : make_float2(0.f, 0.f);
                float f00 = dk0 >= 0 ? dd0.x : x0.x, f01 = dk0 >= 0 ? dd0.y : x0.y;
                float f10 = dk1 >= 0 ? dd1.x : x1.x, f11 = dk1 >= 0 ? dd1.y : x1.y;
                *(uint32_t*)(O16a + i0) = pack2h(f00, f01);
                *(uint32_t*)(O16a + i1) = pack2h(f10, f11);
                float2 rr0 = (rk0 >= 0) ? *(const float2*)(domout + (size_t)(bofs + rk0 * 512) + gc) : make_float2(0.f, 0.f);
                float2 rr1 = (rk1 >= 0) ? *(const float2*)(domout + (size_t)(bofs + rk1 * 512) + gc) : make_float2(0.f, 0.f);
                float b00 = rk0 >= 0 ? rr0.x : v[0], b01 = rk0 >= 0 ? rr0.y : v[1];
                float b10 = rk1 >= 0 ? rr1.x : v[2], b11 = rk1 >= 0 ? rr1.y : v[3];
                *(uint32_t*)(O16c + i0) = pack2h(b00, b01);
                *(uint32_t*)(O16c + i1) = pack2h(b10, b11);
            } else if (EPI == 1) {
                uint32_t f0 = *(const uint32_t*)(add16 + i0);
                uint32_t f1 = *(const uint32_t*)(add16 + i1);
                uint32_t mh0 = *(const uint32_t*)(mulh + i0);
                uint32_t mh1 = *(const uint32_t*)(mulh + i1);
                v[0] = rv0 * sigf(v[0] + h2lo(f0)) * h2lo(mh0);
                v[1] = rv0 * sigf(v[1] + h2hi(f0)) * h2hi(mh0);
                v[2] = rv1 * sigf(v[2] + h2lo(f1)) * h2lo(mh1);
                v[3] = rv1 * sigf(v[3] + h2hi(f1)) * h2hi(mh1);
                *(uint32_t*)(O16a + i0) = pack2h(v[0], v[1]);
                *(uint32_t*)(O16a + i1) = pack2h(v[2], v[3]);
            } else if (EPI == 8) {
                *(uint32_t*)(O16a + i0) = pack2h(v[0], v[1]);
                *(uint32_t*)(O16a + i1) = pack2h(v[2], v[3]);
            } else if (EPI == 5) {
                float2 a0 = *(const float2*)(Cadd + i0);
                float2 a1 = *(const float2*)(Cadd + i1);
                v[0] += a0.x; v[1] += a0.y; v[2] += a1.x; v[3] += a1.y;
                uint32_t h, lo;
                split2h(v[0], v[1], h, lo);
                *(uint32_t*)(O16a + i0) = h; *(uint32_t*)(O16b + i0) = lo;
                split2h(v[2], v[3], h, lo);
                *(uint32_t*)(O16a + i1) = h; *(uint32_t*)(O16b + i1) = lo;
            } else if (EPI == 2) {
                float b0 = 2.f * bias[gc], b1 = 2.f * bias[gc + 1];
                uint32_t p0 = *(const uint32_t*)(add16 + i0);
                uint32_t p1 = *(const uint32_t*)(add16 + i1);
                uint32_t d0 = *(const uint32_t*)(add16b + i0);
                uint32_t d1 = *(const uint32_t*)(add16b + i1);
                float t0 = (v[0] + b0 + h2lo(d0) + h2lo(p0)) * rv0;
                float t1 = (v[1] + b1 + h2hi(d0) + h2hi(p0)) * rv0;
                float t2 = (v[2] + b0 + h2lo(d1) + h2lo(p1)) * rv1;
                float t3 = (v[3] + b1 + h2hi(d1) + h2hi(p1)) * rv1;
                v[0] = t0 >= 0.f ? t0 : al_p * t0;
                v[1] = t1 >= 0.f ? t1 : al_p * t1;
                v[2] = t2 >= 0.f ? t2 : al_p * t2;
                v[3] = t3 >= 0.f ? t3 : al_p * t3;
                *(float2*)(C + i0) = make_float2(v[0], v[1]);
                *(float2*)(C + i1) = make_float2(v[2], v[3]);
                *(uint32_t*)(O16a + i0) = pack2h(v[0], v[1]);
                *(uint32_t*)(O16a + i1) = pack2h(v[2], v[3]);
                float2 re0 = *(const float2*)(relf + i0);
                float2 re1 = *(const float2*)(relf + i1);
                *(uint32_t*)(O16b + i0) = pack2h(v[0] * re0.x, v[1] * re0.y);
                *(uint32_t*)(O16b + i1) = pack2h(v[2] * re1.x, v[3] * re1.y);
                uint32_t h, lo;
                split2h(v[0], v[1], h, lo);
                *(uint32_t*)(O16c + (size_t)gm0 * (NLAY * DD) + gc) = h;
                *(uint32_t*)(O16d + (size_t)gm0 * (NLAY * DD) + gc) = lo;
                split2h(v[2], v[3], h, lo);
                *(uint32_t*)(O16c + (size_t)gm1 * (NLAY * DD) + gc) = h;
                *(uint32_t*)(O16d + (size_t)gm1 * (NLAY * DD) + gc) = lo;
            } else if (EPI == 3) {
                float2 a0 = *(const float2*)(add1 + i0);
                float2 a1 = *(const float2*)(add1 + i1);
                v[0] += bias[gc] + a0.x;     v[1] += bias[gc + 1] + a0.y;
                v[2] += bias[gc] + a1.x;     v[3] += bias[gc + 1] + a1.y;
                *(float2*)(C + i0) = make_float2(v[0], v[1]);
                *(float2*)(C + i1) = make_float2(v[2], v[3]);
            }
        }
    }
}

// ================= small kernels =================
__global__ void detect_dom_fmt(const unsigned int* __restrict__ w) {
    __shared__ int sf, sbt;
    if (threadIdx.x == 0) { sf = 0; sbt = 0; }
    __syncthreads();
    for (int i = threadIdx.x; i < 1024; i += 256) {
        unsigned int v = w[i];
        if (v == 0x3F800000u) atomicOr(&sf, 1);
        else if (v > 1u) atomicOr(&sbt, 1);
    }
    __syncthreads();
    if (threadIdx.x == 0) g_domfmt = sf ? 2 : (sbt ? 0 : 1);
}

__global__ void convert_dom(const void* __restrict__ dom, unsigned char* __restrict__ out) {
    int i = blockIdx.x * 256 + threadIdx.x;
    if (i >= MT * NDOM) return;
    int fmt = g_domfmt;
    unsigned char v;
    if (fmt == 0)      v = ((const unsigned char*)dom)[i] != 0;
    else if (fmt == 1) v = ((const int*)dom)[i] != 0;
    else               v = ((const float*)dom)[i] != 0.f;
    out[i] = v;
}

__global__ void rowstats_kernel(const float* __restrict__ adj,
                                const float* __restrict__ depmap,
                                float* __restrict__ denom,
                                float* __restrict__ fbadj) {
    int warp = (blockIdx.x * blockDim.x + threadIdx.x) >> 5;
    int lane = threadIdx.x & 31;
    if (warp >= MT) return;
    int b = warp >> 9;
    int s = warp & 511;
    const float* arow = adj + (size_t)(b * SD + s) * SD;
    const float* drow = depmap + (size_t)(b * SD + s) * SD;
    const float* acol = adj + (size_t)b * SD * SD + s;
    float sa = 0.f, sf = 0.f, sb = 0.f;
    for (int j = lane; j < SD; j += 32) {
        float a = arow[j];
        float dp = drow[j];
        sa += a;
        sf += a * dp;
        sb += acol[(size_t)j * SD] * dp;
    }
#pragma unroll
    for (int off = 16; off > 0; off >>= 1) {
        sa += __shfl_down_sync(0xffffffffu, sa, off);
        sf += __shfl_down_sync(0xffffffffu, sf, off);
        sb += __shfl_down_sync(0xffffffffu, sb, off);
    }
    if (lane == 0) {
        denom[warp] = sa + 1.f;
        fbadj[warp] = sf;
        fbadj[MT + warp] = sb;
    }
}

__global__ void split_single16(const float* __restrict__ src, fp16* __restrict__ h, int n2) {
    int i = blockIdx.x * 256 + threadIdx.x;
    if (i >= n2) return;
    float2 v = ((const float2*)src)[i];
    ((uint32_t*)h)[i] = pack2h(v.x, v.y);
}

__global__ void copy_split0(const float* __restrict__ gcn, const float* __restrict__ rel,
                            float* __restrict__ X, fp16* __restrict__ Xh,
                            fp16* __restrict__ Xr, int n2) {
    int i = blockIdx.x * 256 + threadIdx.x;
    if (i >= n2) return;
    float2 v = ((const float2*)gcn)[i];
    float2 rv = ((const float2*)rel)[i];
    ((float2*)X)[i] = v;
    ((uint32_t*)Xh)[i] = pack2h(v.x, v.y);
    ((uint32_t*)Xr)[i] = pack2h(v.x * rv.x, v.y * rv.y);
}

__global__ void transpose_single16(const float* __restrict__ in, fp16* __restrict__ h) {
    __shared__ float ts[32][33];
    int b = blockIdx.z;
    int x0 = blockIdx.x * 32, y0 = blockIdx.y * 32;
    const float* ib = in + (size_t)b * 262144;
    int tx = threadIdx.x, ty = threadIdx.y;
#pragma unroll
    for (int i = 0; i < 32; i += 8)
        ts[ty + i][tx] = ib[(size_t)(y0 + ty + i) * 512 + x0 + tx];
    __syncthreads();
#pragma unroll
    for (int i = 0; i < 32; i += 8) {
        float v = ts[tx][ty + i];
        size_t o = (size_t)b * 262144 + (size_t)(x0 + ty + i) * 512 + y0 + tx;
        h[o] = __float2half_rn(v);
    }
}

__global__ void pool_kernel(const float* __restrict__ X,
                            const unsigned char* __restrict__ dom,
                            float* __restrict__ pooled) {
    int b = blockIdx.x;
    int d = blockIdx.y * 128 + threadIdx.x;
    float mv[NDOM];
#pragma unroll
    for (int k = 0; k < NDOM; k++) mv[k] = -3.402823466e38f;
    const float* Xb = X + (size_t)b * SD * DD;
    const unsigned long long* db = (const unsigned long long*)(dom + (size_t)b * SD * NDOM);
    for (int s = 0; s < SD; s++) {
        float x = Xb[(size_t)s * DD + d];
        unsigned long long mk = db[s];
#pragma unroll
        for (int k = 0; k < NDOM; k++) {
            float v = ((mk >> (8 * k)) & 0xffull) ? -10000.f : x;
            mv[k] = fmaxf(mv[k], v);
        }
    }
#pragma unroll
    for (int k = 0; k < NDOM; k++) pooled[((size_t)b * NDOM + k) * DD + d] = mv[k];
}

__global__ void dgate_kernel(const float* __restrict__ pooled,
                             const float* __restrict__ Wdg,
                             const float* __restrict__ bdg,
                             float* __restrict__ out) {
    int bk = blockIdx.x;
    int d = blockIdx.y * 128 + threadIdx.x;
    __shared__ float sp[DD];
    for (int e = threadIdx.x; e < DD; e += 128) sp[e] = pooled[(size_t)bk * DD + e];
    __syncthreads();
    float acc = bdg[d];
#pragma unroll 8
    for (int e = 0; e < DD; e++) acc += sp[e] * Wdg[(size_t)e * DD + d];
    out[(size_t)bk * DD + d] = sigf(acc);
}

// ================= host launcher =================
#define SM1 (3 * (128 * 144 + 64 * 272))       // 107520 (BK=64, 1 A plane)
#define SM2 (3 * (2 * 128 * 80 + 32 * 272))    // 87552  (BK=32, 2 A planes)

extern "C" void kernel_launch(void* const* d_in, const int* in_sizes, int n_in,
                              void* d_out, int out_size) {
    const float* adj       = (const float*)d_in[0];
    const void*  domain    = d_in[1];
    const float* domain_id = (const float*)d_in[2];
    const float* redom_id  = (const float*)d_in[3];
    const float* frontrel  = (const float*)d_in[4];
    const float* backrel   = (const float*)d_in[5];
    const float* depmap    = (const float*)d_in[6];
    const float* rel       = (const float*)d_in[7];
    const float* gcn       = (const float*)d_in[8];
    const float* W_layers  = (const float*)d_in[10];
    const float* b_layers  = (const float*)d_in[11];
    const float* prelu_a   = (const float*)d_in[12];
    const float* W_dg      = (const float*)d_in[13];
    const float* b_dg      = (const float*)d_in[14];
    const float* W_mg      = (const float*)d_in[15];
    const float* b_mg      = (const float*)d_in[16];
    const float* W_out     = (const float*)d_in[17];
    const float* b_out     = (const float*)d_in[18];

    float *X, *pooled, *domout, *denom, *fbadj;
    unsigned char *dom8;
    fp16 *adjh, *relh, *relTh, *Xh16, *Xr16, *foboh, *P16, *delta16, *FRBR16,
         *Axh, *Axl, *outsh, *outsl, *frbrh, *wmg1, *wmg2, *wlh, *woh;
    cudaGetSymbolAddress((void**)&X, g_X);
    cudaGetSymbolAddress((void**)&pooled, g_pooled);
    cudaGetSymbolAddress((void**)&domout, g_domout);
    cudaGetSymbolAddress((void**)&denom, g_denom);
    cudaGetSymbolAddress((void**)&fbadj, g_fbadj);
    cudaGetSymbolAddress((void**)&dom8, g_dom8);
    cudaGetSymbolAddress((void**)&adjh, g_adjh);
    cudaGetSymbolAddress((void**)&relh, g_relh);
    cudaGetSymbolAddress((void**)&relTh, g_relTh);
    cudaGetSymbolAddress((void**)&Xh16, g_Xh16);   cudaGetSymbolAddress((void**)&Xr16, g_Xr16);
    cudaGetSymbolAddress((void**)&foboh, g_foboh);
    cudaGetSymbolAddress((void**)&P16, g_P16);
    cudaGetSymbolAddress((void**)&delta16, g_delta16);
    cudaGetSymbolAddress((void**)&FRBR16, g_FRBR16);
    cudaGetSymbolAddress((void**)&Axh, g_Axh);     cudaGetSymbolAddress((void**)&Axl, g_Axl);
    cudaGetSymbolAddress((void**)&outsh, g_outsh); cudaGetSymbolAddress((void**)&outsl, g_outsl);
    cudaGetSymbolAddress((void**)&frbrh, g_frbrh);
    cudaGetSymbolAddress((void**)&wmg1, g_wmg1);   cudaGetSymbolAddress((void**)&wmg2, g_wmg2);
    cudaGetSymbolAddress((void**)&wlh, g_wlh);
    cudaGetSymbolAddress((void**)&woh, g_woh);

    cudaFuncSetAttribute(hgemm<0, 1, false>, cudaFuncAttributeMaxDynamicSharedMemorySize, SM1);
    cudaFuncSetAttribute(hgemm<7, 1, true >, cudaFuncAttributeMaxDynamicSharedMemorySize, SM1);
    cudaFuncSetAttribute(hgemm<1, 1, false>, cudaFuncAttributeMaxDynamicSharedMemorySize, SM1);
    cudaFuncSetAttribute(hgemm<8, 1, true >, cudaFuncAttributeMaxDynamicSharedMemorySize, SM1);
    cudaFuncSetAttribute(hgemm<5, 1, true >, cudaFuncAttributeMaxDynamicSharedMemorySize, SM1);
    cudaFuncSetAttribute(hgemm<2, 2, false>, cudaFuncAttributeMaxDynamicSharedMemorySize, SM2);
    cudaFuncSetAttribute(hgemm<3, 2, false>, cudaFuncAttributeMaxDynamicSharedMemorySize, SM2);

    const dim3 tgA(4, 64);     // M=8192:  256 CTAs
    const dim3 tgB(4, 128);    // M=16384: 512 CTAs
    const int TB = 256;
    const int N2 = MTDD / 2;
    const int GB2 = (N2 + 255) / 256;
    const int W2 = (DD * DD / 2 + 255) / 256;
    const int W32 = (NLAY * DD * DD / 2 + 255) / 256;

    // launches 1-3 (deps of the profiled hgemm)
    split_single16<<<GB2, 256>>>(frontrel, frbrh, N2);
    split_single16<<<GB2, 256>>>(backrel, frbrh + MTDD, N2);
    split_single16<<<W2, 256>>>(W_mg + (size_t)DD * DD, wmg2, DD * DD / 2);
    // launch 4: PROFILED — merged FR/BR GEMM (single-pass BK=64, fp16 out)
    hgemm<0, 1, false><<<tgB, TB, SM1>>>(frbrh, nullptr, DD, wmg2, DD, DD,
        nullptr, FRBR16, nullptr, nullptr, nullptr,
        nullptr, nullptr, nullptr, nullptr,
        b_mg, nullptr, nullptr, nullptr, nullptr, nullptr, nullptr, nullptr, nullptr, 0);

    detect_dom_fmt<<<1, 256>>>((const unsigned int*)domain);
    convert_dom<<<(MT * NDOM + 255) / 256, 256>>>(domain, dom8);
    rowstats_kernel<<<1024, 256>>>(adj, depmap, denom, fbadj);
    split_single16<<<GB2, 256>>>(adj, adjh, N2);
    split_single16<<<GB2, 256>>>(rel, relh, N2);
    transpose_single16<<<dim3(16, 16, 16), dim3(32, 8)>>>(rel, relTh);
    split_single16<<<W2, 256>>>(W_mg, wmg1, DD * DD / 2);
    split_single16<<<W32, 256>>>(W_layers, wlh, NLAY * DD * DD / 2);
    split_single16<<<W32, 256>>>(W_out, woh, NLAY * DD * DD / 2);
    copy_split0<<<GB2, 256>>>(gcn, rel, X, Xh16, Xr16, N2);

    for (int l = 0; l < NLAY; l++) {
        pool_kernel<<<dim3(BB, DD / 128), 128>>>(X, dom8, pooled);
        dgate_kernel<<<dim3(BB * NDOM, DD / 128), 128>>>(pooled, W_dg, b_dg, domout);
        // relX GEMM + fused fo/bo build
        hgemm<7, 1, true><<<tgA, TB, SM1>>>(relh, nullptr, DD, Xh16, DD, DD,
            nullptr, foboh, nullptr, foboh + MTDD, nullptr,
            X, domout, domain_id, redom_id,
            nullptr, nullptr, nullptr, nullptr, nullptr, nullptr, nullptr, nullptr, nullptr, 0);
        // merged gates: P16[0:MTDD)=Pf, [MTDD:)=Pb
        hgemm<1, 1, false><<<tgB, TB, SM1>>>(foboh, nullptr, DD, wmg1, DD, DD,
            nullptr, P16, nullptr, nullptr, nullptr,
            nullptr, nullptr, nullptr, nullptr,
            nullptr, nullptr, FRBR16, nullptr, fbadj, foboh, nullptr, nullptr, nullptr, 0);
        // delta16 = relT @ Pf
        hgemm<8, 1, true><<<tgA, TB, SM1>>>(relTh, nullptr, DD, P16, DD, DD,
            nullptr, delta16, nullptr, nullptr, nullptr,
            nullptr, nullptr, nullptr, nullptr,
            nullptr, nullptr, nullptr, nullptr, nullptr, nullptr, nullptr, nullptr, nullptr, 0);
        // AxpX = adj @ Xr + X -> pair
        hgemm<5, 1, true><<<tgA, TB, SM1>>>(adjh, nullptr, DD, Xr16, DD, DD,
            nullptr, Axh, Axl, nullptr, nullptr,
            nullptr, nullptr, nullptr, nullptr,
            nullptr, nullptr, nullptr, nullptr, nullptr, nullptr, X, nullptr, nullptr, 0);
        // layer update (2-pass: A pair x W hi)
        hgemm<2, 2, false><<<tgA, TB, SM2>>>(Axh, Axl, DD,
            wlh + (size_t)l * DD * DD, DD, DD,
            X, Xh16, Xr16, outsh + (size_t)l * DD, outsl + (size_t)l * DD,
            nullptr, nullptr, nullptr, nullptr,
            b_layers + (size_t)l * DD, nullptr, P16 + MTDD, delta16, denom,
            nullptr, nullptr, rel, prelu_a, l);
    }
    // final projection (2-pass: outs pair x W hi)
    hgemm<3, 2, false><<<tgA, TB, SM2>>>(outsh, outsl, NLAY * DD, woh, DD, NLAY * DD,
        (float*)d_out, nullptr, nullptr, nullptr, nullptr,
        nullptr, nullptr, nullptr, nullptr,
        b_out, gcn, nullptr, nullptr, nullptr, nullptr, nullptr, nullptr, nullptr, 0);
}

// round 11
// speedup vs baseline: 3.3563x; 1.0985x over previous
#include <cuda_runtime.h>
#include <cuda_fp16.h>
#include <math.h>
#include <stdint.h>

#define BB 16
#define SD 512
#define DD 512
#define MT (BB*SD)          // 8192
#define MTDD (MT*DD)        // 4194304
#define NLAY 3
#define NDOM 8

typedef __half fp16;

// ---------------- scratch (device globals; no allocation) ----------------
__device__ float g_X[MTDD];
__device__ float g_pooled[BB*NDOM*DD];
__device__ float g_domout[BB*NDOM*DD];
__device__ float g_denom[MT];
__device__ float g_fbadj[2*MT];
__device__ unsigned char g_dom8[MT*NDOM];
__device__ int g_domfmt;

// fp16 planes
__device__ fp16 g_adjh[MTDD];
__device__ fp16 g_relh[MTDD];
__device__ fp16 g_relTh[MTDD];
__device__ fp16 g_Xh16[MTDD];
__device__ fp16 g_Xr16[MTDD];
__device__ fp16 g_foboh[2*MTDD];
__device__ fp16 g_P16[2*MTDD];
__device__ fp16 g_delta16[MTDD];
__device__ fp16 g_FRBR16[2*MTDD];
__device__ fp16 g_Axh[MTDD];
__device__ fp16 g_outsh[MT*NLAY*DD];
__device__ fp16 g_frbrh[2*MTDD];
__device__ fp16 g_wmg1[DD*DD];
__device__ fp16 g_wmg2[DD*DD];
__device__ fp16 g_wlh[NLAY*DD*DD];
__device__ fp16 g_woh[NLAY*DD*DD];

__device__ __forceinline__ float sigf(float x) { return 1.f / (1.f + expf(-x)); }

__device__ __forceinline__ uint32_t pack2h(float x, float y) {
    return ((uint32_t)__half_as_ushort(__float2half_rn(y)) << 16) |
           (uint32_t)__half_as_ushort(__float2half_rn(x));
}
__device__ __forceinline__ float h2lo(uint32_t w) { return __half2float(__ushort_as_half(w & 0xffff)); }
__device__ __forceinline__ float h2hi(uint32_t w) { return __half2float(__ushort_as_half(w >> 16)); }

__device__ __forceinline__ uint32_t smem_u32(const void* p) {
    uint32_t a;
    asm("{ .reg .u64 t; cvta.to.shared.u64 t, %1; cvt.u32.u64 %0, t; }" : "=r"(a) : "l"(p));
    return a;
}
__device__ __forceinline__ void cpa16(uint32_t dst, const void* src) {
    asm volatile("{ .reg .u64 g; cvta.to.global.u64 g, %1; cp.async.cg.shared.global [%0], [g], 16; }"
                 :: "r"(dst), "l"(src) : "memory");
}
#define CP_COMMIT() asm volatile("cp.async.commit_group;" ::: "memory")
#define CP_WAIT2()  asm volatile("cp.async.wait_group 2;" ::: "memory")
#define CP_WAIT1()  asm volatile("cp.async.wait_group 1;" ::: "memory")
#define CP_WAIT0()  asm volatile("cp.async.wait_group 0;" ::: "memory")

#define LDSM4(r0, r1, r2, r3, a) \
    asm volatile("ldmatrix.sync.aligned.m8n8.x4.shared.b16 {%0,%1,%2,%3}, [%4];" \
        : "=r"(r0), "=r"(r1), "=r"(r2), "=r"(r3) : "r"(a))
#define LDSM4T(r0, r1, r2, r3, a) \
    asm volatile("ldmatrix.sync.aligned.m8n8.x4.trans.shared.b16 {%0,%1,%2,%3}, [%4];" \
        : "=r"(r0), "=r"(r1), "=r"(r2), "=r"(r3) : "r"(a))
#define MMAH(acc, a, b) \
    asm volatile("mma.sync.aligned.m16n8k16.row.col.f32.f16.f16.f32 " \
        "{%0,%1,%2,%3}, {%4,%5,%6,%7}, {%8,%9}, {%0,%1,%2,%3};" \
        : "+f"((acc)[0]), "+f"((acc)[1]), "+f"((acc)[2]), "+f"((acc)[3]) \
        : "r"((a)[0]), "r"((a)[1]), "r"((a)[2]), "r"((a)[3]), "r"((b)[0]), "r"((b)[1]))

__device__ __forceinline__ int oh_idx(const float* __restrict__ p) {
    float s = 0.f; int k = -1;
#pragma unroll
    for (int i = 0; i < 8; i++) { float t = p[i]; s += t; if (t == 1.f) k = i; }
    return (s == 1.f) ? k : -1;
}

// ================= fp16 GEMM, 128x128 CTA, BK=32, 4-stage, 2 CTAs/SM ========
// 8 warps (2m x 4n), warp tile 64x32. Single-pass: C = Ah*Bh.
// EPI 0: FRBR16 = pack(acc + bias)
// EPI 7: relX epilogue: fo/bo build -> foboh fp16
// EPI 1: P16 = pack(rowv * sig(acc + frbr16) * mulh)
// EPI 8: delta16 = pack(acc)
// EPI 5: Axh = pack(acc + Cadd)
// EPI 2: t = (acc + 2*bias + delta16 + Pb16)/rowv; prelu
//        -> C(X fp32), Xh16, Xr16(=t*relf), outsh
// EPI 3: C = acc + bias + add1(gcn)
#define APITCH 80
#define BPITCH 272
#define A_PL (128*APITCH)            // 10240
#define B_PL (32*BPITCH)             // 8704
#define STG (A_PL + B_PL)            // 18944
#define SM1 (4 * STG)                // 75776

template<int EPI, bool BATCHB>
__global__ void __launch_bounds__(256, 2) hgemm(
    const fp16* __restrict__ Ah, int lda,
    const fp16* __restrict__ Bh, int ldb, int K,
    float* __restrict__ C,
    fp16* __restrict__ O16a, fp16* __restrict__ O16b,
    fp16* __restrict__ O16c,
    const float* __restrict__ Xf, const float* __restrict__ domout,
    const float* __restrict__ did, const float* __restrict__ rid,
    const float* __restrict__ bias, const float* __restrict__ add1,
    const fp16* __restrict__ add16, const fp16* __restrict__ add16b,
    const float* __restrict__ rowv, const fp16* __restrict__ mulh,
    const float* __restrict__ Cadd, const float* __restrict__ relf,
    const float* __restrict__ pa, int l)
{
    extern __shared__ __align__(128) char smp[];
    const uint32_t sb = smem_u32(smp);
    const int t = threadIdx.x;
    const int wid = t >> 5;
    const int lane = t & 31;
    const int m0 = blockIdx.y * 128;
    const int n0 = blockIdx.x * 128;
    const int KB = K >> 5;
    const int wm = (wid & 1) * 64;
    const int wn = (wid >> 1) * 32;
    const size_t boff = BATCHB ? (size_t)(m0 >> 9) * 512 * ldb : 0;

    float acc[4][4][4];
#pragma unroll
    for (int im = 0; im < 4; im++)
#pragma unroll
        for (int in = 0; in < 4; in++)
#pragma unroll
            for (int c = 0; c < 4; c++) acc[im][in][c] = 0.f;

    const int q = lane >> 3, r = lane & 7;
    const int arow = (q & 1) * 8 + r;
    const int acol = (q >> 1) * 8;
    const int bkrow = (q & 1) * 8 + r;
    const int bq8 = (q >> 1) * 8;

    auto stage_cp = [&](int st, int kb) {
        const int k0 = kb * 32;
        const uint32_t sa = sb + (uint32_t)st * STG;
#pragma unroll
        for (int i = 0; i < 2; i++) {
            int c = t + i * 256;
            int row = c >> 2, kc = c & 3;
            size_t go = (size_t)(m0 + row) * lda + k0 + kc * 8;
            cpa16(sa + (uint32_t)row * APITCH + kc * 16, Ah + go);
        }
#pragma unroll
        for (int i = 0; i < 2; i++) {
            int c = t + i * 256;
            int row = c >> 4, nc = c & 15;
            size_t go = boff + (size_t)(k0 + row) * ldb + n0 + nc * 8;
            cpa16(sa + A_PL + (uint32_t)row * BPITCH + nc * 16, Bh + go);
        }
        CP_COMMIT();
    };

    auto compute = [&](int st) {
        const uint32_t aH = sb + (uint32_t)st * STG;
        const uint32_t bHp = aH + A_PL;
#pragma unroll
        for (int ks = 0; ks < 2; ks++) {
            const int k16 = ks * 16;
            uint32_t ah[4][4], bb[4][2];
#pragma unroll
            for (int im = 0; im < 4; im++) {
                uint32_t off = (uint32_t)(wm + im * 16 + arow) * APITCH + (k16 + acol) * 2;
                LDSM4(ah[im][0], ah[im][1], ah[im][2], ah[im][3], aH + off);
            }
#pragma unroll
            for (int j2 = 0; j2 < 2; j2++) {
                uint32_t off = (uint32_t)(k16 + bkrow) * BPITCH + (wn + bq8 + j2 * 16) * 2;
                LDSM4T(bb[j2 * 2][0], bb[j2 * 2][1], bb[j2 * 2 + 1][0], bb[j2 * 2 + 1][1], bHp + off);
            }
#pragma unroll
            for (int im = 0; im < 4; im++)
#pragma unroll
                for (int in = 0; in < 4; in++)
                    MMAH(acc[im][in], ah[im], bb[in]);
        }
    };

    stage_cp(0, 0);
    stage_cp(1, 1);
    stage_cp(2, 2);
    for (int kb = 0; kb < KB; kb++) {
        const int rem = KB - 1 - kb;
        if (rem >= 2) { CP_WAIT2(); } else if (rem == 1) { CP_WAIT1(); } else { CP_WAIT0(); }
        __syncthreads();
        if (kb + 3 < KB) stage_cp((kb + 3) & 3, kb + 3);
        compute(kb & 3);
    }

    // ---------------- epilogue ----------------
    const int lr = lane >> 2;
    const int lc = (lane & 3) * 2;
    float al_p = 0.f;
    if (EPI == 2) al_p = pa[l];
    const int bofs = (EPI == 7) ? (m0 >> 9) * NDOM * 512 : 0;

#pragma unroll
    for (int im = 0; im < 4; im++) {
        const int gm0 = m0 + wm + im * 16 + lr;
        const int gm1 = gm0 + 8;
        float rv0 = 1.f, rv1 = 1.f;
        if (EPI == 1) { rv0 = rowv[gm0]; rv1 = rowv[gm1]; }
        if (EPI == 2) { rv0 = 1.f / rowv[gm0]; rv1 = 1.f / rowv[gm1]; }
        int dk0 = 0, dk1 = 0, rk0 = 0, rk1 = 0;
        if (EPI == 7) {
            dk0 = oh_idx(did + (size_t)gm0 * 8);
            dk1 = oh_idx(did + (size_t)gm1 * 8);
            rk0 = oh_idx(rid + (size_t)gm0 * 8);
            rk1 = oh_idx(rid + (size_t)gm1 * 8);
        }
#pragma unroll
        for (int in = 0; in < 4; in++) {
            const int gc = n0 + wn + in * 8 + lc;
            float v[4] = {acc[im][in][0], acc[im][in][1], acc[im][in][2], acc[im][in][3]};
            const size_t i0 = (size_t)gm0 * 512 + gc;
            const size_t i1 = (size_t)gm1 * 512 + gc;
            if (EPI == 0) {
                *(uint32_t*)(O16a + i0) = pack2h(v[0] + bias[gc], v[1] + bias[gc + 1]);
                *(uint32_t*)(O16a + i1) = pack2h(v[2] + bias[gc], v[3] + bias[gc + 1]);
            } else if (EPI == 7) {
                float2 x0 = *(const float2*)(Xf + i0);
                float2 x1 = *(const float2*)(Xf + i1);
                float2 dd0 = (dk0 >= 0) ? *(const float2*)(domout + (size_t)(bofs + dk0 * 512) + gc) : make_float2(0.f, 0.f);
                float2 dd1 = (dk1 >= 0) ? *(const float2*)(domout + (size_t)(bofs + dk1 * 512) + gc) : make_float2(0.f, 0.f);
                float f00 = dk0 >= 0 ? dd0.x : x0.x, f01 = dk0 >= 0 ? dd0.y : x0.y;
                float f10 = dk1 >= 0 ? dd1.x : x1.x, f11 = dk1 >= 0 ? dd1.y : x1.y;
                *(uint32_t*)(O16a + i0) = pack2h(f00, f01);
                *(uint32_t*)(O16a + i1) = pack2h(f10, f11);
                float2 rr0 = (rk0 >= 0) ? *(const float2*)(domout + (size_t)(bofs + rk0 * 512) + gc) : make_float2(0.f, 0.f);
                float2 rr1 = (rk1 >= 0) ? *(const float2*)(domout + (size_t)(bofs + rk1 * 512) + gc) : make_float2(0.f, 0.f);
                float b00 = rk0 >= 0 ? rr0.x : v[0], b01 = rk0 >= 0 ? rr0.y : v[1];
                float b10 = rk1 >= 0 ? rr1.x : v[2], b11 = rk1 >= 0 ? rr1.y : v[3];
                *(uint32_t*)(O16c + i0) = pack2h(b00, b01);
                *(uint32_t*)(O16c + i1) = pack2h(b10, b11);
            } else if (EPI == 1) {
                uint32_t f0 = *(const uint32_t*)(add16 + i0);
                uint32_t f1 = *(const uint32_t*)(add16 + i1);
                uint32_t mh0 = *(const uint32_t*)(mulh + i0);
                uint32_t mh1 = *(const uint32_t*)(mulh + i1);
                v[0] = rv0 * sigf(v[0] + h2lo(f0)) * h2lo(mh0);
                v[1] = rv0 * sigf(v[1] + h2hi(f0)) * h2hi(mh0);
                v[2] = rv1 * sigf(v[2] + h2lo(f1)) * h2lo(mh1);
                v[3] = rv1 * sigf(v[3] + h2hi(f1)) * h2hi(mh1);
                *(uint32_t*)(O16a + i0) = pack2h(v[0], v[1]);
                *(uint32_t*)(O16a + i1) = pack2h(v[2], v[3]);
            } else if (EPI == 8) {
                *(uint32_t*)(O16a + i0) = pack2h(v[0], v[1]);
                *(uint32_t*)(O16a + i1) = pack2h(v[2], v[3]);
            } else if (EPI == 5) {
                float2 a0 = *(const float2*)(Cadd + i0);
                float2 a1 = *(const float2*)(Cadd + i1);
                *(uint32_t*)(O16a + i0) = pack2h(v[0] + a0.x, v[1] + a0.y);
                *(uint32_t*)(O16a + i1) = pack2h(v[2] + a1.x, v[3] + a1.y);
            } else if (EPI == 2) {
                float b0 = 2.f * bias[gc], b1 = 2.f * bias[gc + 1];
                uint32_t p0 = *(const uint32_t*)(add16 + i0);
                uint32_t p1 = *(const uint32_t*)(add16 + i1);
                uint32_t d0 = *(const uint32_t*)(add16b + i0);
                uint32_t d1 = *(const uint32_t*)(add16b + i1);
                float t0 = (v[0] + b0 + h2lo(d0) + h2lo(p0)) * rv0;
                float t1 = (v[1] + b1 + h2hi(d0) + h2hi(p0)) * rv0;
                float t2 = (v[2] + b0 + h2lo(d1) + h2lo(p1)) * rv1;
                float t3 = (v[3] + b1 + h2hi(d1) + h2hi(p1)) * rv1;
                v[0] = t0 >= 0.f ? t0 : al_p * t0;
                v[1] = t1 >= 0.f ? t1 : al_p * t1;
                v[2] = t2 >= 0.f ? t2 : al_p * t2;
                v[3] = t3 >= 0.f ? t3 : al_p * t3;
                *(float2*)(C + i0) = make_float2(v[0], v[1]);
                *(float2*)(C + i1) = make_float2(v[2], v[3]);
                *(uint32_t*)(O16a + i0) = pack2h(v[0], v[1]);
                *(uint32_t*)(O16a + i1) = pack2h(v[2], v[3]);
                float2 re0 = *(const float2*)(relf + i0);
                float2 re1 = *(const float2*)(relf + i1);
                *(uint32_t*)(O16b + i0) = pack2h(v[0] * re0.x, v[1] * re0.y);
                *(uint32_t*)(O16b + i1) = pack2h(v[2] * re1.x, v[3] * re1.y);
                *(uint32_t*)(O16c + (size_t)gm0 * (NLAY * DD) + gc) = pack2h(v[0], v[1]);
                *(uint32_t*)(O16c + (size_t)gm1 * (NLAY * DD) + gc) = pack2h(v[2], v[3]);
            } else if (EPI == 3) {
                float2 a0 = *(const float2*)(add1 + i0);
                float2 a1 = *(const float2*)(add1 + i1);
                v[0] += bias[gc] + a0.x;     v[1] += bias[gc + 1] + a0.y;
                v[2] += bias[gc] + a1.x;     v[3] += bias[gc + 1] + a1.y;
                *(float2*)(C + i0) = make_float2(v[0], v[1]);
                *(float2*)(C + i1) = make_float2(v[2], v[3]);
            }
        }
    }
}

// ================= small kernels =================
__global__ void detect_dom_fmt(const unsigned int* __restrict__ w) {
    __shared__ int sf, sbt;
    if (threadIdx.x == 0) { sf = 0; sbt = 0; }
    __syncthreads();
    for (int i = threadIdx.x; i < 1024; i += 256) {
        unsigned int v = w[i];
        if (v == 0x3F800000u) atomicOr(&sf, 1);
        else if (v > 1u) atomicOr(&sbt, 1);
    }
    __syncthreads();
    if (threadIdx.x == 0) g_domfmt = sf ? 2 : (sbt ? 0 : 1);
}

__global__ void convert_dom(const void* __restrict__ dom, unsigned char* __restrict__ out) {
    int i = blockIdx.x * 256 + threadIdx.x;
    if (i >= MT * NDOM) return;
    int fmt = g_domfmt;
    unsigned char v;
    if (fmt == 0)      v = ((const unsigned char*)dom)[i] != 0;
    else if (fmt == 1) v = ((const int*)dom)[i] != 0;
    else               v = ((const float*)dom)[i] != 0.f;
    out[i] = v;
}

__global__ void rowstats_kernel(const float* __restrict__ adj,
                                const float* __restrict__ depmap,
                                float* __restrict__ denom,
                                float* __restrict__ fbadj) {
    int warp = (blockIdx.x * blockDim.x + threadIdx.x) >> 5;
    int lane = threadIdx.x & 31;
    if (warp >= MT) return;
    int b = warp >> 9;
    int s = warp & 511;
    const float* arow = adj + (size_t)(b * SD + s) * SD;
    const float* drow = depmap + (size_t)(b * SD + s) * SD;
    const float* acol = adj + (size_t)b * SD * SD + s;
    float sa = 0.f, sf = 0.f, sb = 0.f;
    for (int j = lane; j < SD; j += 32) {
        float a = arow[j];
        float dp = drow[j];
        sa += a;
        sf += a * dp;
        sb += acol[(size_t)j * SD] * dp;
    }
#pragma unroll
    for (int off = 16; off > 0; off >>= 1) {
        sa += __shfl_down_sync(0xffffffffu, sa, off);
        sf += __shfl_down_sync(0xffffffffu, sf, off);
        sb += __shfl_down_sync(0xffffffffu, sb, off);
    }
    if (lane == 0) {
        denom[warp] = sa + 1.f;
        fbadj[warp] = sf;
        fbadj[MT + warp] = sb;
    }
}

__global__ void split_single16(const float* __restrict__ src, fp16* __restrict__ h, int n2) {
    int i = blockIdx.x * 256 + threadIdx.x;
    if (i >= n2) return;
    float2 v = ((const float2*)src)[i];
    ((uint32_t*)h)[i] = pack2h(v.x, v.y);
}

__global__ void copy_split0(const float* __restrict__ gcn, const float* __restrict__ rel,
                            float* __restrict__ X, fp16* __restrict__ Xh,
                            fp16* __restrict__ Xr, int n2) {
    int i = blockIdx.x * 256 + threadIdx.x;
    if (i >= n2) return;
    float2 v = ((const float2*)gcn)[i];
    float2 rv = ((const float2*)rel)[i];
    ((float2*)X)[i] = v;
    ((uint32_t*)Xh)[i] = pack2h(v.x, v.y);
    ((uint32_t*)Xr)[i] = pack2h(v.x * rv.x, v.y * rv.y);
}

__global__ void transpose_single16(const float* __restrict__ in, fp16* __restrict__ h) {
    __shared__ float ts[32][33];
    int b = blockIdx.z;
    int x0 = blockIdx.x * 32, y0 = blockIdx.y * 32;
    const float* ib = in + (size_t)b * 262144;
    int tx = threadIdx.x, ty = threadIdx.y;
#pragma unroll
    for (int i = 0; i < 32; i += 8)
        ts[ty + i][tx] = ib[(size_t)(y0 + ty + i) * 512 + x0 + tx];
    __syncthreads();
#pragma unroll
    for (int i = 0; i < 32; i += 8) {
        float v = ts[tx][ty + i];
        size_t o = (size_t)b * 262144 + (size_t)(x0 + ty + i) * 512 + y0 + tx;
        h[o] = __float2half_rn(v);
    }
}

__global__ void pool_kernel(const float* __restrict__ X,
                            const unsigned char* __restrict__ dom,
                            float* __restrict__ pooled) {
    int b = blockIdx.x;
    int d = blockIdx.y * 128 + threadIdx.x;
    float mv[NDOM];
#pragma unroll
    for (int k = 0; k < NDOM; k++) mv[k] = -3.402823466e38f;
    const float* Xb = X + (size_t)b * SD * DD;
    const unsigned long long* db = (const unsigned long long*)(dom + (size_t)b * SD * NDOM);
    for (int s = 0; s < SD; s++) {
        float x = Xb[(size_t)s * DD + d];
        unsigned long long mk = db[s];
#pragma unroll
        for (int k = 0; k < NDOM; k++) {
            float v = ((mk >> (8 * k)) & 0xffull) ? -10000.f : x;
            mv[k] = fmaxf(mv[k], v);
        }
    }
#pragma unroll
    for (int k = 0; k < NDOM; k++) pooled[((size_t)b * NDOM + k) * DD + d] = mv[k];
}

__global__ void dgate_kernel(const float* __restrict__ pooled,
                             const float* __restrict__ Wdg,
                             const float* __restrict__ bdg,
                             float* __restrict__ out) {
    int bk = blockIdx.x;
    int d = blockIdx.y * 128 + threadIdx.x;
    __shared__ float sp[DD];
    for (int e = threadIdx.x; e < DD; e += 128) sp[e] = pooled[(size_t)bk * DD + e];
    __syncthreads();
    float acc = bdg[d];
#pragma unroll 8
    for (int e = 0; e < DD; e++) acc += sp[e] * Wdg[(size_t)e * DD + d];
    out[(size_t)bk * DD + d] = sigf(acc);
}

// ================= host launcher =================
extern "C" void kernel_launch(void* const* d_in, const int* in_sizes, int n_in,
                              void* d_out, int out_size) {
    const float* adj       = (const float*)d_in[0];
    const void*  domain    = d_in[1];
    const float* domain_id = (const float*)d_in[2];
    const float* redom_id  = (const float*)d_in[3];
    const float* frontrel  = (const float*)d_in[4];
    const float* backrel   = (const float*)d_in[5];
    const float* depmap    = (const float*)d_in[6];
    const float* rel       = (const float*)d_in[7];
    const float* gcn       = (const float*)d_in[8];
    const float* W_layers  = (const float*)d_in[10];
    const float* b_layers  = (const float*)d_in[11];
    const float* prelu_a   = (const float*)d_in[12];
    const float* W_dg      = (const float*)d_in[13];
    const float* b_dg      = (const float*)d_in[14];
    const float* W_mg      = (const float*)d_in[15];
    const float* b_mg      = (const float*)d_in[16];
    const float* W_out     = (const float*)d_in[17];
    const float* b_out     = (const float*)d_in[18];

    float *X, *pooled, *domout, *denom, *fbadj;
    unsigned char *dom8;
    fp16 *adjh, *relh, *relTh, *Xh16, *Xr16, *foboh, *P16, *delta16, *FRBR16,
         *Axh, *outsh, *frbrh, *wmg1, *wmg2, *wlh, *woh;
    cudaGetSymbolAddress((void**)&X, g_X);
    cudaGetSymbolAddress((void**)&pooled, g_pooled);
    cudaGetSymbolAddress((void**)&domout, g_domout);
    cudaGetSymbolAddress((void**)&denom, g_denom);
    cudaGetSymbolAddress((void**)&fbadj, g_fbadj);
    cudaGetSymbolAddress((void**)&dom8, g_dom8);
    cudaGetSymbolAddress((void**)&adjh, g_adjh);
    cudaGetSymbolAddress((void**)&relh, g_relh);
    cudaGetSymbolAddress((void**)&relTh, g_relTh);
    cudaGetSymbolAddress((void**)&Xh16, g_Xh16);   cudaGetSymbolAddress((void**)&Xr16, g_Xr16);
    cudaGetSymbolAddress((void**)&foboh, g_foboh);
    cudaGetSymbolAddress((void**)&P16, g_P16);
    cudaGetSymbolAddress((void**)&delta16, g_delta16);
    cudaGetSymbolAddress((void**)&FRBR16, g_FRBR16);
    cudaGetSymbolAddress((void**)&Axh, g_Axh);
    cudaGetSymbolAddress((void**)&outsh, g_outsh);
    cudaGetSymbolAddress((void**)&frbrh, g_frbrh);
    cudaGetSymbolAddress((void**)&wmg1, g_wmg1);   cudaGetSymbolAddress((void**)&wmg2, g_wmg2);
    cudaGetSymbolAddress((void**)&wlh, g_wlh);
    cudaGetSymbolAddress((void**)&woh, g_woh);

    cudaFuncSetAttribute(hgemm<0, false>, cudaFuncAttributeMaxDynamicSharedMemorySize, SM1);
    cudaFuncSetAttribute(hgemm<7, true >, cudaFuncAttributeMaxDynamicSharedMemorySize, SM1);
    cudaFuncSetAttribute(hgemm<1, false>, cudaFuncAttributeMaxDynamicSharedMemorySize, SM1);
    cudaFuncSetAttribute(hgemm<8, true >, cudaFuncAttributeMaxDynamicSharedMemorySize, SM1);
    cudaFuncSetAttribute(hgemm<5, true >, cudaFuncAttributeMaxDynamicSharedMemorySize, SM1);
    cudaFuncSetAttribute(hgemm<2, false>, cudaFuncAttributeMaxDynamicSharedMemorySize, SM1);
    cudaFuncSetAttribute(hgemm<3, false>, cudaFuncAttributeMaxDynamicSharedMemorySize, SM1);

    const dim3 tgA(4, 64);     // M=8192:  256 CTAs
    const dim3 tgB(4, 128);    // M=16384: 512 CTAs
    const int TB = 256;
    const int N2 = MTDD / 2;
    const int GB2 = (N2 + 255) / 256;
    const int W2 = (DD * DD / 2 + 255) / 256;
    const int W32 = (NLAY * DD * DD / 2 + 255) / 256;

    // launches 1-3 (deps of the profiled hgemm)
    split_single16<<<GB2, 256>>>(frontrel, frbrh, N2);
    split_single16<<<GB2, 256>>>(backrel, frbrh + MTDD, N2);
    split_single16<<<W2, 256>>>(W_mg + (size_t)DD * DD, wmg2, DD * DD / 2);
    // launch 4: PROFILED — merged FR/BR GEMM
    hgemm<0, false><<<tgB, TB, SM1>>>(frbrh, DD, wmg2, DD, DD,
        nullptr, FRBR16, nullptr, nullptr,
        nullptr, nullptr, nullptr, nullptr,
        b_mg, nullptr, nullptr, nullptr, nullptr, nullptr, nullptr, nullptr, nullptr, 0);

    detect_dom_fmt<<<1, 256>>>((const unsigned int*)domain);
    convert_dom<<<(MT * NDOM + 255) / 256, 256>>>(domain, dom8);
    rowstats_kernel<<<1024, 256>>>(adj, depmap, denom, fbadj);
    split_single16<<<GB2, 256>>>(adj, adjh, N2);
    split_single16<<<GB2, 256>>>(rel, relh, N2);
    transpose_single16<<<dim3(16, 16, 16), dim3(32, 8)>>>(rel, relTh);
    split_single16<<<W2, 256>>>(W_mg, wmg1, DD * DD / 2);
    split_single16<<<W32, 256>>>(W_layers, wlh, NLAY * DD * DD / 2);
    split_single16<<<W32, 256>>>(W_out, woh, NLAY * DD * DD / 2);
    copy_split0<<<GB2, 256>>>(gcn, rel, X, Xh16, Xr16, N2);

    for (int l = 0; l < NLAY; l++) {
        pool_kernel<<<dim3(BB, DD / 128), 128>>>(X, dom8, pooled);
        dgate_kernel<<<dim3(BB * NDOM, DD / 128), 128>>>(pooled, W_dg, b_dg, domout);
        // relX GEMM + fused fo/bo build
        hgemm<7, true><<<tgA, TB, SM1>>>(relh, DD, Xh16, DD, DD,
            nullptr, foboh, nullptr, foboh + MTDD,
            X, domout, domain_id, redom_id,
            nullptr, nullptr, nullptr, nullptr, nullptr, nullptr, nullptr, nullptr, nullptr, 0);
        // merged gates: P16[0:MTDD)=Pf, [MTDD:)=Pb
        hgemm<1, false><<<tgB, TB, SM1>>>(foboh, DD, wmg1, DD, DD,
            nullptr, P16, nullptr, nullptr,
            nullptr, nullptr, nullptr, nullptr,
            nullptr, nullptr, FRBR16, nullptr, fbadj, foboh, nullptr, nullptr, nullptr, 0);
        // delta16 = relT @ Pf
        hgemm<8, true><<<tgA, TB, SM1>>>(relTh, DD, P16, DD, DD,
            nullptr, delta16, nullptr, nullptr,
            nullptr, nullptr, nullptr, nullptr,
            nullptr, nullptr, nullptr, nullptr, nullptr, nullptr, nullptr, nullptr, nullptr, 0);
        // Axh = adj @ Xr + X
        hgemm<5, true><<<tgA, TB, SM1>>>(adjh, DD, Xr16, DD, DD,
            nullptr, Axh, nullptr, nullptr,
            nullptr, nullptr, nullptr, nullptr,
            nullptr, nullptr, nullptr, nullptr, nullptr, nullptr, X, nullptr, nullptr, 0);
        // layer update (single-pass)
        hgemm<2, false><<<tgA, TB, SM1>>>(Axh, DD,
            wlh + (size_t)l * DD * DD, DD, DD,
            X, Xh16, Xr16, outsh + (size_t)l * DD,
            nullptr, nullptr, nullptr, nullptr,
            b_layers + (size_t)l * DD, nullptr, P16 + MTDD, delta16, denom,
            nullptr, nullptr, rel, prelu_a, l);
    }
    // final projection (single-pass)
    hgemm<3, false><<<tgA, TB, SM1>>>(outsh, NLAY * DD, woh, DD, NLAY * DD,
        (float*)d_out, nullptr, nullptr, nullptr,
        nullptr, nullptr, nullptr, nullptr,
        b_out, gcn, nullptr, nullptr, nullptr, nullptr, nullptr, nullptr, nullptr, 0);
}